// round 1
// baseline (speedup 1.0000x reference)
#include <cuda_runtime.h>
#include <math.h>

// Problem dims
#define T_DIM   4096
#define B_DIM   8
#define EMB_DIM 1024
#define CONV_DIM 1024
#define H_DIM   16
#define R_DIM   64
#define FFN_DIM 4096
#define M_TOK   (T_DIM * B_DIM)       // 32768 tokens
#define BH_DIM  (B_DIM * H_DIM)       // 128
#define CHAN    (B_DIM * CONV_DIM)    // 8192 cumsum channels

// Scratch (device globals; no runtime allocation allowed)
__device__ float g_xn [M_TOK * EMB_DIM];    // 128 MB: ln1 out, then TaLK out (reused)
__device__ float g_glu[M_TOK * CONV_DIM];   // 128 MB: GLU out, then ln2 out (reused)
__device__ float g_S  [M_TOK * CONV_DIM];   // 128 MB: cumsum
__device__ float g_y  [M_TOK * EMB_DIM];    // 128 MB: conv-block output (residual 2)
__device__ float g_big[M_TOK * FFN_DIM];    // 512 MB: pre-GLU h2 (2048 cols), then FFN mid (4096 cols)
__device__ float g_alpha[T_DIM * BH_DIM];   // 2 MB

__device__ __forceinline__ float sigmoidf_(float v) {
    return 1.f / (1.f + __expf(-v));
}

// ---------------------------------------------------------------------------
// Block-wide sum (blockDim.x == 256)
// ---------------------------------------------------------------------------
__device__ __forceinline__ float block_sum256(float v, float* sh) {
    #pragma unroll
    for (int o = 16; o > 0; o >>= 1) v += __shfl_xor_sync(0xffffffffu, v, o);
    if ((threadIdx.x & 31) == 0) sh[threadIdx.x >> 5] = v;
    __syncthreads();
    float tot = 0.f;
    #pragma unroll
    for (int i = 0; i < 8; i++) tot += sh[i];
    __syncthreads();
    return tot;
}

// ---------------------------------------------------------------------------
// LayerNorm over last dim (1024). One block (256 thr) per row, float4/thread.
// ---------------------------------------------------------------------------
__global__ __launch_bounds__(256) void ln_kernel(
    const float* __restrict__ in, float* __restrict__ out,
    const float* __restrict__ gw, const float* __restrict__ bw)
{
    __shared__ float sh[8];
    const size_t row = blockIdx.x;
    const float4 v = ((const float4*)(in + row * 1024))[threadIdx.x];

    float s = v.x + v.y + v.z + v.w;
    s = block_sum256(s, sh);
    const float mean = s * (1.f / 1024.f);

    const float dx = v.x - mean, dy = v.y - mean, dz = v.z - mean, dw = v.w - mean;
    float q = dx * dx + dy * dy + dz * dz + dw * dw;
    q = block_sum256(q, sh);
    const float rstd = rsqrtf(q * (1.f / 1024.f) + 1e-5f);

    const float4 g4 = ((const float4*)gw)[threadIdx.x];
    const float4 b4 = ((const float4*)bw)[threadIdx.x];
    float4 o;
    o.x = dx * rstd * g4.x + b4.x;
    o.y = dy * rstd * g4.y + b4.y;
    o.z = dz * rstd * g4.z + b4.z;
    o.w = dw * rstd * g4.w + b4.w;
    ((float4*)(out + row * 1024))[threadIdx.x] = o;
}

// ---------------------------------------------------------------------------
// SGEMM: C[M,N] = A[M,K] @ B[K,N] (+bias / +epilogue)
// 128x128 block tile, 256 threads, 8x8 per thread, KC=16, reg prefetch.
// EPI: 0 = +bias, 1 = +bias then swish, 2 = +bias + residual
// M,N multiples of 128; K multiple of 16 (always true here).
// ---------------------------------------------------------------------------
template<int EPI>
__global__ __launch_bounds__(256, 2) void sgemm_kernel(
    const float* __restrict__ A, const float* __restrict__ B,
    const float* __restrict__ bias, const float* __restrict__ res,
    float* __restrict__ C, int M, int N, int K)
{
    __shared__ float As[16][128];
    __shared__ float Bs[16][128];

    const int tid = threadIdx.x;
    const int m0 = blockIdx.y << 7;
    const int n0 = blockIdx.x << 7;
    const int tm = (tid >> 4) << 3;
    const int tn = (tid & 15) << 3;

    // per-thread global load positions (8 contiguous floats each for A and B)
    const int a_sr = tid >> 1;           // As row (m within tile)
    const int a_sk = (tid & 1) << 3;     // As starting k
    const int b_sr = tid >> 4;           // Bs row (k within chunk)
    const int b_sc = (tid & 15) << 3;    // Bs col

    const float* Aptr = A + (size_t)(m0 + a_sr) * K + a_sk;
    const float* Bptr = B + (size_t)b_sr * N + n0 + b_sc;

    float4 ra0 = *(const float4*)(Aptr);
    float4 ra1 = *(const float4*)(Aptr + 4);
    float4 rb0 = *(const float4*)(Bptr);
    float4 rb1 = *(const float4*)(Bptr + 4);

    float acc[8][8];
    #pragma unroll
    for (int i = 0; i < 8; i++)
        #pragma unroll
        for (int j = 0; j < 8; j++) acc[i][j] = 0.f;

    for (int k0 = 0; k0 < K; k0 += 16) {
        // commit prefetched tile to smem (A stored transposed: As[k][m])
        As[a_sk + 0][a_sr] = ra0.x; As[a_sk + 1][a_sr] = ra0.y;
        As[a_sk + 2][a_sr] = ra0.z; As[a_sk + 3][a_sr] = ra0.w;
        As[a_sk + 4][a_sr] = ra1.x; As[a_sk + 5][a_sr] = ra1.y;
        As[a_sk + 6][a_sr] = ra1.z; As[a_sk + 7][a_sr] = ra1.w;
        *(float4*)&Bs[b_sr][b_sc]     = rb0;
        *(float4*)&Bs[b_sr][b_sc + 4] = rb1;
        __syncthreads();

        if (k0 + 16 < K) {
            ra0 = *(const float4*)(Aptr + k0 + 16);
            ra1 = *(const float4*)(Aptr + k0 + 20);
            const float* bp = Bptr + (size_t)(k0 + 16) * N;
            rb0 = *(const float4*)(bp);
            rb1 = *(const float4*)(bp + 4);
        }

        #pragma unroll
        for (int kk = 0; kk < 16; kk++) {
            const float4 a0 = *(const float4*)&As[kk][tm];
            const float4 a1 = *(const float4*)&As[kk][tm + 4];
            const float4 b0 = *(const float4*)&Bs[kk][tn];
            const float4 b1 = *(const float4*)&Bs[kk][tn + 4];
            const float av[8] = {a0.x, a0.y, a0.z, a0.w, a1.x, a1.y, a1.z, a1.w};
            const float bv[8] = {b0.x, b0.y, b0.z, b0.w, b1.x, b1.y, b1.z, b1.w};
            #pragma unroll
            for (int i = 0; i < 8; i++)
                #pragma unroll
                for (int j = 0; j < 8; j++)
                    acc[i][j] = fmaf(av[i], bv[j], acc[i][j]);
        }
        __syncthreads();
    }

    // epilogue
    #pragma unroll
    for (int i = 0; i < 8; i++) {
        const size_t m = (size_t)(m0 + tm + i);
        float* crow = C + m * N + n0 + tn;
        const float* rrow = (EPI == 2) ? (res + m * N + n0 + tn) : nullptr;
        #pragma unroll
        for (int j = 0; j < 8; j++) {
            float v = acc[i][j] + bias[n0 + tn + j];
            if (EPI == 1) v = v * sigmoidf_(v);
            if (EPI == 2) v += rrow[j];
            crow[j] = v;
        }
    }
}

// ---------------------------------------------------------------------------
// GLU: out[m, c] = h2[m, c] * sigmoid(h2[m, 1024 + c]); h2 is [M, 2048]
// ---------------------------------------------------------------------------
__global__ __launch_bounds__(256) void glu_kernel(
    const float* __restrict__ h2, float* __restrict__ out)
{
    const size_t e = ((size_t)blockIdx.x * blockDim.x + threadIdx.x) << 2;
    const size_t m = e >> 10;
    const int c = (int)(e & 1023);
    const float4 a = *(const float4*)(h2 + m * 2048 + c);
    const float4 g = *(const float4*)(h2 + m * 2048 + 1024 + c);
    float4 o;
    o.x = a.x * sigmoidf_(g.x);
    o.y = a.y * sigmoidf_(g.y);
    o.z = a.z * sigmoidf_(g.z);
    o.w = a.w * sigmoidf_(g.w);
    *(float4*)(out + e) = o;
}

// ---------------------------------------------------------------------------
// alpha = sigmoid(glu @ W_off + b_off)  — N=16, warp per token row.
// Layout: alpha[t * 128 + b * 16 + h], token row m = t*8 + b.
// ---------------------------------------------------------------------------
__global__ __launch_bounds__(256) void alpha_kernel(
    const float* __restrict__ g, const float* __restrict__ Woff,
    const float* __restrict__ boff, float* __restrict__ alpha)
{
    const int warp = (blockIdx.x * blockDim.x + threadIdx.x) >> 5;
    const int lane = threadIdx.x & 31;
    if (warp >= M_TOK) return;

    const float* row = g + (size_t)warp * 1024;
    float acc[16];
    #pragma unroll
    for (int n = 0; n < 16; n++) acc[n] = 0.f;

    for (int k = lane; k < 1024; k += 32) {
        const float v = __ldg(row + k);
        const float4* w = (const float4*)(Woff + (size_t)k * 16);
        const float4 w0 = __ldg(w + 0), w1 = __ldg(w + 1);
        const float4 w2 = __ldg(w + 2), w3 = __ldg(w + 3);
        acc[0]  = fmaf(v, w0.x, acc[0]);  acc[1]  = fmaf(v, w0.y, acc[1]);
        acc[2]  = fmaf(v, w0.z, acc[2]);  acc[3]  = fmaf(v, w0.w, acc[3]);
        acc[4]  = fmaf(v, w1.x, acc[4]);  acc[5]  = fmaf(v, w1.y, acc[5]);
        acc[6]  = fmaf(v, w1.z, acc[6]);  acc[7]  = fmaf(v, w1.w, acc[7]);
        acc[8]  = fmaf(v, w2.x, acc[8]);  acc[9]  = fmaf(v, w2.y, acc[9]);
        acc[10] = fmaf(v, w2.z, acc[10]); acc[11] = fmaf(v, w2.w, acc[11]);
        acc[12] = fmaf(v, w3.x, acc[12]); acc[13] = fmaf(v, w3.y, acc[13]);
        acc[14] = fmaf(v, w3.z, acc[14]); acc[15] = fmaf(v, w3.w, acc[15]);
    }
    #pragma unroll
    for (int o = 16; o > 0; o >>= 1)
        #pragma unroll
        for (int n = 0; n < 16; n++)
            acc[n] += __shfl_xor_sync(0xffffffffu, acc[n], o);

    if (lane < 16) {
        const int t = warp / B_DIM, b = warp % B_DIM;
        alpha[(size_t)t * BH_DIM + b * H_DIM + lane] = sigmoidf_(acc[lane] + boff[lane]);
    }
}

// ---------------------------------------------------------------------------
// Time cumsum of glu/32 per channel: S[t, c] = sum_{u<=t} glu[u, c] / 32.
// 8192 channels, one thread each; batch-8 load prefetch for MLP.
// ---------------------------------------------------------------------------
__global__ __launch_bounds__(256) void cumsum_kernel(
    const float* __restrict__ in, float* __restrict__ out)
{
    const int c = blockIdx.x * blockDim.x + threadIdx.x;   // 0..8191
    float acc = 0.f;
    const float scale = 1.f / 32.f;
    for (int t0 = 0; t0 < T_DIM; t0 += 8) {
        float v[8];
        #pragma unroll
        for (int i = 0; i < 8; i++)
            v[i] = in[(size_t)(t0 + i) * CHAN + c];
        #pragma unroll
        for (int i = 0; i < 8; i++) {
            acc = fmaf(v[i], scale, acc);
            out[(size_t)(t0 + i) * CHAN + c] = acc;
        }
    }
}

// ---------------------------------------------------------------------------
// TaLK: out[t, col] = S[t, col] - lerp(S at fractional left boundary).
// col = b*1024 + c, bh = col >> 6. float4 per thread.
// ---------------------------------------------------------------------------
__global__ __launch_bounds__(256) void talk_kernel(
    const float* __restrict__ S, const float* __restrict__ alpha,
    float* __restrict__ out)
{
    const size_t e = ((size_t)blockIdx.x * blockDim.x + threadIdx.x) << 2;
    const int t = (int)(e >> 13);          // / 8192
    const int col = (int)(e & 8191);
    const int bh = col >> 6;

    const float al = alpha[(size_t)t * BH_DIM + bh];
    const float eff = fminf(31.f, (float)t);
    const float pos = (float)t - 1.f - al * eff;
    const float i0f = floorf(pos);
    const float frac = pos - i0f;
    const int i0 = (int)i0f;               // >= -1 always
    const int c0 = max(i0, 0);
    const int c1 = i0 + 1;                 // in [0, t], always valid

    const float4 s  = *(const float4*)(S + (size_t)t  * CHAN + col);
    float4 v0       = *(const float4*)(S + (size_t)c0 * CHAN + col);
    const float4 v1 = *(const float4*)(S + (size_t)c1 * CHAN + col);
    if (i0 < 0) { v0.x = 0.f; v0.y = 0.f; v0.z = 0.f; v0.w = 0.f; }

    float4 o;
    o.x = s.x - (v0.x + frac * (v1.x - v0.x));
    o.y = s.y - (v0.y + frac * (v1.y - v0.y));
    o.z = s.z - (v0.z + frac * (v1.z - v0.z));
    o.w = s.w - (v0.w + frac * (v1.w - v0.w));
    *(float4*)(out + e) = o;
}

// ---------------------------------------------------------------------------
// Launch
// ---------------------------------------------------------------------------
extern "C" void kernel_launch(void* const* d_in, const int* in_sizes, int n_in,
                              void* d_out, int out_size)
{
    const float* x    = (const float*)d_in[0];
    const float* W1   = (const float*)d_in[4];
    const float* b1   = (const float*)d_in[5];
    const float* Woff = (const float*)d_in[6];
    const float* boff = (const float*)d_in[7];
    const float* W2   = (const float*)d_in[8];
    const float* b2   = (const float*)d_in[9];
    const float* Wf1  = (const float*)d_in[10];
    const float* bf1  = (const float*)d_in[11];
    const float* Wf2  = (const float*)d_in[12];
    const float* bf2  = (const float*)d_in[13];
    const float* gcv  = (const float*)d_in[14];
    const float* bcv  = (const float*)d_in[15];
    const float* gfn  = (const float*)d_in[16];
    const float* bfn  = (const float*)d_in[17];

    float *xn, *glu, *S, *y, *big, *alpha;
    cudaGetSymbolAddress((void**)&xn,    g_xn);
    cudaGetSymbolAddress((void**)&glu,   g_glu);
    cudaGetSymbolAddress((void**)&S,     g_S);
    cudaGetSymbolAddress((void**)&y,     g_y);
    cudaGetSymbolAddress((void**)&big,   g_big);
    cudaGetSymbolAddress((void**)&alpha, g_alpha);

    const int ew_blocks = (M_TOK * 1024 / 4) / 256;   // 32768

    // conv block
    ln_kernel<<<M_TOK, 256>>>(x, xn, gcv, bcv);
    sgemm_kernel<0><<<dim3(2048 / 128, M_TOK / 128), 256>>>(
        xn, W1, b1, nullptr, big, M_TOK, 2048, 1024);
    glu_kernel<<<ew_blocks, 256>>>(big, glu);
    alpha_kernel<<<M_TOK / 8, 256>>>(glu, Woff, boff, alpha);
    cumsum_kernel<<<CHAN / 256, 256>>>(glu, S);
    talk_kernel<<<ew_blocks, 256>>>(S, alpha, xn);
    sgemm_kernel<2><<<dim3(1024 / 128, M_TOK / 128), 256>>>(
        xn, W2, b2, x, y, M_TOK, 1024, 1024);

    // FFN block
    ln_kernel<<<M_TOK, 256>>>(y, glu, gfn, bfn);
    sgemm_kernel<1><<<dim3(4096 / 128, M_TOK / 128), 256>>>(
        glu, Wf1, bf1, nullptr, big, M_TOK, 4096, 1024);
    sgemm_kernel<2><<<dim3(1024 / 128, M_TOK / 128), 256>>>(
        big, Wf2, bf2, y, (float*)d_out, M_TOK, 1024, 4096);
}

// round 3
// speedup vs baseline: 1.6223x; 1.6223x over previous
#include <cuda_runtime.h>
#include <cuda_bf16.h>
#include <stdint.h>
#include <math.h>

#define T_DIM   4096
#define B_DIM   8
#define M_TOK   32768
#define CHAN    8192
#define BH_DIM  128

// ---------------------------------------------------------------------------
// Device-global scratch
// ---------------------------------------------------------------------------
__device__ __nv_bfloat16 g_Ah [M_TOK * 1024];
__device__ __nv_bfloat16 g_Al [M_TOK * 1024];
__device__ __nv_bfloat16 g_Mh [M_TOK * 4096];
__device__ __nv_bfloat16 g_Ml [M_TOK * 4096];
__device__ __nv_bfloat16 g_W1h[2048 * 1024], g_W1l[2048 * 1024];
__device__ __nv_bfloat16 g_W2h[1024 * 1024], g_W2l[1024 * 1024];
__device__ __nv_bfloat16 g_Wf1h[4096 * 1024], g_Wf1l[4096 * 1024];
__device__ __nv_bfloat16 g_Wf2h[1024 * 4096], g_Wf2l[1024 * 4096];
__device__ float g_big [M_TOK * 2048];
__device__ float g_glu [M_TOK * 1024];
__device__ float g_S   [M_TOK * 1024];
__device__ float g_y   [M_TOK * 1024];
__device__ float g_alpha[T_DIM * BH_DIM];
__device__ float g_part[8 * CHAN];

__device__ __forceinline__ float sigmoidf_(float v) { return 1.f / (1.f + __expf(-v)); }

__device__ __forceinline__ uint32_t smem_addr_of(const void* p) {
    uint32_t a;
    asm("{ .reg .u64 t; cvta.to.shared.u64 t, %1; cvt.u32.u64 %0, t; }" : "=r"(a) : "l"(p));
    return a;
}
__device__ __forceinline__ void ldsm4(uint32_t* r, uint32_t addr) {
    asm volatile("ldmatrix.sync.aligned.m8n8.x4.shared.b16 {%0,%1,%2,%3}, [%4];"
                 : "=r"(r[0]), "=r"(r[1]), "=r"(r[2]), "=r"(r[3]) : "r"(addr));
}
__device__ __forceinline__ void mma16816(float* d, const uint32_t* a, const uint32_t* b) {
    asm volatile("mma.sync.aligned.m16n8k16.row.col.f32.bf16.bf16.f32 "
                 "{%0,%1,%2,%3}, {%4,%5,%6,%7}, {%8,%9}, {%0,%1,%2,%3};"
                 : "+f"(d[0]), "+f"(d[1]), "+f"(d[2]), "+f"(d[3])
                 : "r"(a[0]), "r"(a[1]), "r"(a[2]), "r"(a[3]), "r"(b[0]), "r"(b[1]));
}
__device__ __forceinline__ void cpa16(uint32_t s, const void* g) {
    asm volatile("cp.async.cg.shared.global [%0], [%1], 16;" :: "r"(s), "l"(g));
}
__device__ __forceinline__ void cpa_commit() {
    asm volatile("cp.async.commit_group;" ::: "memory");
}
__device__ __forceinline__ void cpa_wait1() {
    asm volatile("cp.async.wait_group 1;" ::: "memory");
}
__device__ __forceinline__ void cpa_wait0() {
    asm volatile("cp.async.wait_group 0;" ::: "memory");
}

// ---------------------------------------------------------------------------
// bf16 hi/lo emulated fp32 GEMM on mma.sync (HMMA).
// C[M,N] = A[M,K] @ Bt[N,K]^T, A/B given as hi+lo bf16 pairs.
// CTA 128x128, 8 warps (64x32 each), BK=64, 2-stage cp.async pipeline.
// EPI: 0 = +bias -> fp32 ; 1 = +bias, swish -> bf16 hi/lo ; 2 = +bias+res -> fp32
// ---------------------------------------------------------------------------
#define ROWB    144                 // smem row stride bytes (128B data + 16B pad)
#define TILE_B  (128 * ROWB)        // 18432
#define STAGE_B (4 * TILE_B)        // 73728
#define GEMM_SMEM (2 * STAGE_B)     // 147456

template<int EPI>
__global__ __launch_bounds__(256) void gemm_mma(
    const __nv_bfloat16* __restrict__ Ah, const __nv_bfloat16* __restrict__ Al,
    const __nv_bfloat16* __restrict__ Bh, const __nv_bfloat16* __restrict__ Bl,
    const float* __restrict__ bias, const float* __restrict__ res,
    float* __restrict__ C, __nv_bfloat16* __restrict__ Ch, __nv_bfloat16* __restrict__ Cl,
    int M, int N, int K)
{
    extern __shared__ __align__(1024) char smem[];
    const uint32_t sb = smem_addr_of(smem);
    const int tid = threadIdx.x, wid = tid >> 5, lane = tid & 31;
    const int wm = wid & 1, wn = wid >> 1;
    const int m0 = blockIdx.y << 7, n0 = blockIdx.x << 7;

    const __nv_bfloat16* gt[4] = {
        Ah + (size_t)m0 * K, Al + (size_t)m0 * K,
        Bh + (size_t)n0 * K, Bl + (size_t)n0 * K };

    const int ldr = tid >> 3;          // 0..31 row group
    const int ldc = tid & 7;           // 16B chunk in row

    // ---- stage loader: 4 tiles x 128 rows x 128B via cp.async ----
    auto load_stage = [&](int s, int kc) {
        const uint32_t sbase = sb + s * STAGE_B;
        const int k0 = kc << 6;
        #pragma unroll
        for (int t = 0; t < 4; t++) {
            const __nv_bfloat16* g = gt[t] + k0;
            const uint32_t tb = sbase + t * TILE_B;
            #pragma unroll
            for (int i = 0; i < 4; i++) {
                const int r = ldr + (i << 5);
                cpa16(tb + r * ROWB + (ldc << 4), g + (size_t)r * K + (ldc << 3));
            }
        }
    };

    float acc[4][4][4];
    #pragma unroll
    for (int a = 0; a < 4; a++)
        #pragma unroll
        for (int b = 0; b < 4; b++)
            #pragma unroll
            for (int k = 0; k < 4; k++) acc[a][b][k] = 0.f;

    const int NC = K >> 6;
    load_stage(0, 0);
    cpa_commit();

    const uint32_t aOff = ((wm << 6) + (lane & 15)) * ROWB + ((lane >> 4) << 4);
    const int nrow = (lane & 7) | ((lane & 16) >> 1);
    const uint32_t bOff = ((wn << 5) + nrow) * ROWB + ((lane & 8) << 1);

    #pragma unroll 1
    for (int c = 0; c < NC; c++) {
        if (c + 1 < NC) { load_stage((c + 1) & 1, c + 1); cpa_commit(); cpa_wait1(); }
        else           { cpa_wait0(); }
        __syncthreads();

        const uint32_t st = sb + (c & 1) * STAGE_B;
        const uint32_t aB = st + aOff;
        const uint32_t bB = st + 2 * TILE_B + bOff;

        #pragma unroll
        for (int kk = 0; kk < 4; kk++) {
            const uint32_t ko = kk << 5;
            uint32_t ah[4][4], al[4][4], bh[2][4], bl[2][4];
            #pragma unroll
            for (int fm = 0; fm < 4; fm++) {
                ldsm4(ah[fm], aB + fm * (16 * ROWB) + ko);
                ldsm4(al[fm], aB + TILE_B + fm * (16 * ROWB) + ko);
            }
            #pragma unroll
            for (int f2 = 0; f2 < 2; f2++) {
                ldsm4(bh[f2], bB + f2 * (16 * ROWB) + ko);
                ldsm4(bl[f2], bB + TILE_B + f2 * (16 * ROWB) + ko);
            }
            #pragma unroll
            for (int fm = 0; fm < 4; fm++) {
                #pragma unroll
                for (int fn = 0; fn < 4; fn++) {
                    const uint32_t* bhf = &bh[fn >> 1][(fn & 1) << 1];
                    const uint32_t* blf = &bl[fn >> 1][(fn & 1) << 1];
                    mma16816(acc[fm][fn], ah[fm], bhf);
                    mma16816(acc[fm][fn], ah[fm], blf);
                    mma16816(acc[fm][fn], al[fm], bhf);
                }
            }
        }
        __syncthreads();
    }

    // ---- epilogue ----
    const int mB = m0 + (wm << 6) + (lane >> 2);
    const int nB = n0 + (wn << 5) + ((lane & 3) << 1);
    #pragma unroll
    for (int fm = 0; fm < 4; fm++) {
        const int r0 = mB + (fm << 4);
        #pragma unroll
        for (int fn = 0; fn < 4; fn++) {
            const int cc = nB + (fn << 3);
            const float2 bv = __ldg((const float2*)(bias + cc));
            float v0 = acc[fm][fn][0] + bv.x;
            float v1 = acc[fm][fn][1] + bv.y;
            float v2 = acc[fm][fn][2] + bv.x;
            float v3 = acc[fm][fn][3] + bv.y;
            const size_t o0 = (size_t)r0 * N + cc;
            const size_t o1 = (size_t)(r0 + 8) * N + cc;
            if (EPI == 1) {
                v0 = v0 * sigmoidf_(v0); v1 = v1 * sigmoidf_(v1);
                v2 = v2 * sigmoidf_(v2); v3 = v3 * sigmoidf_(v3);
                __nv_bfloat16 h0 = __float2bfloat16(v0), h1 = __float2bfloat16(v1);
                __nv_bfloat16 h2 = __float2bfloat16(v2), h3 = __float2bfloat16(v3);
                __nv_bfloat162 p;
                p.x = h0; p.y = h1; *(__nv_bfloat162*)(Ch + o0) = p;
                p.x = h2; p.y = h3; *(__nv_bfloat162*)(Ch + o1) = p;
                p.x = __float2bfloat16(v0 - __bfloat162float(h0));
                p.y = __float2bfloat16(v1 - __bfloat162float(h1));
                *(__nv_bfloat162*)(Cl + o0) = p;
                p.x = __float2bfloat16(v2 - __bfloat162float(h2));
                p.y = __float2bfloat16(v3 - __bfloat162float(h3));
                *(__nv_bfloat162*)(Cl + o1) = p;
            } else {
                if (EPI == 2) {
                    const float2 ra = __ldg((const float2*)(res + o0));
                    const float2 rb = __ldg((const float2*)(res + o1));
                    v0 += ra.x; v1 += ra.y; v2 += rb.x; v3 += rb.y;
                }
                float2 q;
                q.x = v0; q.y = v1; *(float2*)(C + o0) = q;
                q.x = v2; q.y = v3; *(float2*)(C + o1) = q;
            }
        }
    }
}

// ---------------------------------------------------------------------------
// Weight split + transpose: W[K,N] fp32 -> Wh,Wl [N,K] bf16
// ---------------------------------------------------------------------------
__global__ __launch_bounds__(256) void wsplit_kernel(
    const float* __restrict__ W, __nv_bfloat16* __restrict__ Wh,
    __nv_bfloat16* __restrict__ Wl, int K, int N)
{
    __shared__ float tile[32][33];
    const int n0 = blockIdx.x << 5;
    const int k0 = blockIdx.y << 5;
    for (int i = threadIdx.y; i < 32; i += 8)
        tile[i][threadIdx.x] = W[(size_t)(k0 + i) * N + n0 + threadIdx.x];
    __syncthreads();
    for (int i = threadIdx.y; i < 32; i += 8) {
        const float v = tile[threadIdx.x][i];
        const __nv_bfloat16 h = __float2bfloat16(v);
        const size_t o = (size_t)(n0 + i) * K + k0 + threadIdx.x;
        Wh[o] = h;
        Wl[o] = __float2bfloat16(v - __bfloat162float(h));
    }
}

// ---------------------------------------------------------------------------
// LayerNorm -> bf16 hi/lo split
// ---------------------------------------------------------------------------
__device__ __forceinline__ float block_sum256(float v, float* sh) {
    #pragma unroll
    for (int o = 16; o > 0; o >>= 1) v += __shfl_xor_sync(0xffffffffu, v, o);
    if ((threadIdx.x & 31) == 0) sh[threadIdx.x >> 5] = v;
    __syncthreads();
    float tot = 0.f;
    #pragma unroll
    for (int i = 0; i < 8; i++) tot += sh[i];
    __syncthreads();
    return tot;
}

__global__ __launch_bounds__(256) void ln_split_kernel(
    const float* __restrict__ in, __nv_bfloat16* __restrict__ oh,
    __nv_bfloat16* __restrict__ ol,
    const float* __restrict__ gw, const float* __restrict__ bw)
{
    __shared__ float sh[8];
    const size_t row = blockIdx.x;
    const float4 v = ((const float4*)(in + row * 1024))[threadIdx.x];

    float s = v.x + v.y + v.z + v.w;
    s = block_sum256(s, sh);
    const float mean = s * (1.f / 1024.f);
    const float dx = v.x - mean, dy = v.y - mean, dz = v.z - mean, dw = v.w - mean;
    float q = dx * dx + dy * dy + dz * dz + dw * dw;
    q = block_sum256(q, sh);
    const float rstd = rsqrtf(q * (1.f / 1024.f) + 1e-5f);

    const float4 g4 = ((const float4*)gw)[threadIdx.x];
    const float4 b4 = ((const float4*)bw)[threadIdx.x];
    float o[4];
    o[0] = dx * rstd * g4.x + b4.x;
    o[1] = dy * rstd * g4.y + b4.y;
    o[2] = dz * rstd * g4.z + b4.z;
    o[3] = dw * rstd * g4.w + b4.w;

    const size_t base = row * 1024 + (size_t)threadIdx.x * 4;
    __nv_bfloat16 h0 = __float2bfloat16(o[0]), h1 = __float2bfloat16(o[1]);
    __nv_bfloat16 h2 = __float2bfloat16(o[2]), h3 = __float2bfloat16(o[3]);
    __nv_bfloat162 p;
    p.x = h0; p.y = h1; *(__nv_bfloat162*)(oh + base) = p;
    p.x = h2; p.y = h3; *(__nv_bfloat162*)(oh + base + 2) = p;
    p.x = __float2bfloat16(o[0] - __bfloat162float(h0));
    p.y = __float2bfloat16(o[1] - __bfloat162float(h1));
    *(__nv_bfloat162*)(ol + base) = p;
    p.x = __float2bfloat16(o[2] - __bfloat162float(h2));
    p.y = __float2bfloat16(o[3] - __bfloat162float(h3));
    *(__nv_bfloat162*)(ol + base + 2) = p;
}

// ---------------------------------------------------------------------------
// GLU
// ---------------------------------------------------------------------------
__global__ __launch_bounds__(256) void glu_kernel(
    const float* __restrict__ h2, float* __restrict__ out)
{
    const size_t e = ((size_t)blockIdx.x * blockDim.x + threadIdx.x) << 2;
    const size_t m = e >> 10;
    const int c = (int)(e & 1023);
    const float4 a = *(const float4*)(h2 + m * 2048 + c);
    const float4 g = *(const float4*)(h2 + m * 2048 + 1024 + c);
    float4 o;
    o.x = a.x * sigmoidf_(g.x);
    o.y = a.y * sigmoidf_(g.y);
    o.z = a.z * sigmoidf_(g.z);
    o.w = a.w * sigmoidf_(g.w);
    *(float4*)(out + e) = o;
}

// ---------------------------------------------------------------------------
// alpha = sigmoid(glu @ W_off + b_off). W_off cached in smem (64KB),
// one thread per token row, 128 rows per block.
// ---------------------------------------------------------------------------
__global__ __launch_bounds__(128) void alpha_kernel(
    const float* __restrict__ g, const float* __restrict__ Woff,
    const float* __restrict__ boff, float* __restrict__ alpha)
{
    extern __shared__ float Ws[];   // 1024*16 floats
    for (int i = threadIdx.x; i < 4096; i += 128)
        ((float4*)Ws)[i] = ((const float4*)Woff)[i];
    __syncthreads();

    const int row = blockIdx.x * 128 + threadIdx.x;
    const float* gr = g + (size_t)row * 1024;
    float acc[16];
    #pragma unroll
    for (int n = 0; n < 16; n++) acc[n] = 0.f;

    #pragma unroll 4
    for (int k4 = 0; k4 < 256; k4++) {
        const float4 v = ((const float4*)gr)[k4];
        const float vv[4] = {v.x, v.y, v.z, v.w};
        #pragma unroll
        for (int j = 0; j < 4; j++) {
            const float4* w = (const float4*)(Ws + (k4 * 4 + j) * 16);
            const float4 w0 = w[0], w1 = w[1], w2 = w[2], w3 = w[3];
            const float s = vv[j];
            acc[0]  = fmaf(s, w0.x, acc[0]);  acc[1]  = fmaf(s, w0.y, acc[1]);
            acc[2]  = fmaf(s, w0.z, acc[2]);  acc[3]  = fmaf(s, w0.w, acc[3]);
            acc[4]  = fmaf(s, w1.x, acc[4]);  acc[5]  = fmaf(s, w1.y, acc[5]);
            acc[6]  = fmaf(s, w1.z, acc[6]);  acc[7]  = fmaf(s, w1.w, acc[7]);
            acc[8]  = fmaf(s, w2.x, acc[8]);  acc[9]  = fmaf(s, w2.y, acc[9]);
            acc[10] = fmaf(s, w2.z, acc[10]); acc[11] = fmaf(s, w2.w, acc[11]);
            acc[12] = fmaf(s, w3.x, acc[12]); acc[13] = fmaf(s, w3.y, acc[13]);
            acc[14] = fmaf(s, w3.z, acc[14]); acc[15] = fmaf(s, w3.w, acc[15]);
        }
    }
    const int t = row >> 3, b = row & 7;
    float* ap = alpha + (size_t)t * BH_DIM + b * 16;
    #pragma unroll
    for (int n = 0; n < 16; n++)
        ap[n] = sigmoidf_(acc[n] + __ldg(boff + n));
}

// ---------------------------------------------------------------------------
// Segmented cumsum over time (scale 1/32)
// ---------------------------------------------------------------------------
__global__ __launch_bounds__(256) void cumsum_part(
    const float* __restrict__ in, float* __restrict__ part)
{
    const int c = blockIdx.x * 256 + threadIdx.x;
    const int s = blockIdx.y;
    float acc = 0.f;
    for (int t0 = s * 512; t0 < (s + 1) * 512; t0 += 8) {
        float v[8];
        #pragma unroll
        for (int i = 0; i < 8; i++) v[i] = in[(size_t)(t0 + i) * CHAN + c];
        #pragma unroll
        for (int i = 0; i < 8; i++) acc += v[i];
    }
    part[s * CHAN + c] = acc;
}

__global__ __launch_bounds__(256) void cumsum_scan(
    const float* __restrict__ in, const float* __restrict__ part,
    float* __restrict__ out)
{
    const int c = blockIdx.x * 256 + threadIdx.x;
    const int s = blockIdx.y;
    const float scale = 1.f / 32.f;
    float acc = 0.f;
    for (int p = 0; p < s; p++) acc += part[p * CHAN + c];
    acc *= scale;
    for (int t0 = s * 512; t0 < (s + 1) * 512; t0 += 8) {
        float v[8];
        #pragma unroll
        for (int i = 0; i < 8; i++) v[i] = in[(size_t)(t0 + i) * CHAN + c];
        #pragma unroll
        for (int i = 0; i < 8; i++) {
            acc = fmaf(v[i], scale, acc);
            out[(size_t)(t0 + i) * CHAN + c] = acc;
        }
    }
}

// ---------------------------------------------------------------------------
// TaLK gather/lerp -> bf16 hi/lo split
// ---------------------------------------------------------------------------
__global__ __launch_bounds__(256) void talk_split_kernel(
    const float* __restrict__ S, const float* __restrict__ alpha,
    __nv_bfloat16* __restrict__ oh, __nv_bfloat16* __restrict__ ol)
{
    const size_t e = ((size_t)blockIdx.x * blockDim.x + threadIdx.x) << 2;
    const int t = (int)(e >> 13);
    const int col = (int)(e & 8191);
    const int bh = col >> 6;

    const float al = alpha[(size_t)t * BH_DIM + bh];
    const float eff = fminf(31.f, (float)t);
    const float pos = (float)t - 1.f - al * eff;
    const float i0f = floorf(pos);
    const float frac = pos - i0f;
    const int i0 = (int)i0f;
    const int c0 = max(i0, 0);
    const int c1 = i0 + 1;

    const float4 s  = *(const float4*)(S + (size_t)t  * CHAN + col);
    float4 v0       = *(const float4*)(S + (size_t)c0 * CHAN + col);
    const float4 v1 = *(const float4*)(S + (size_t)c1 * CHAN + col);
    if (i0 < 0) { v0.x = 0.f; v0.y = 0.f; v0.z = 0.f; v0.w = 0.f; }

    float o[4];
    o[0] = s.x - (v0.x + frac * (v1.x - v0.x));
    o[1] = s.y - (v0.y + frac * (v1.y - v0.y));
    o[2] = s.z - (v0.z + frac * (v1.z - v0.z));
    o[3] = s.w - (v0.w + frac * (v1.w - v0.w));

    __nv_bfloat16 h0 = __float2bfloat16(o[0]), h1 = __float2bfloat16(o[1]);
    __nv_bfloat16 h2 = __float2bfloat16(o[2]), h3 = __float2bfloat16(o[3]);
    __nv_bfloat162 p;
    p.x = h0; p.y = h1; *(__nv_bfloat162*)(oh + e) = p;
    p.x = h2; p.y = h3; *(__nv_bfloat162*)(oh + e + 2) = p;
    p.x = __float2bfloat16(o[0] - __bfloat162float(h0));
    p.y = __float2bfloat16(o[1] - __bfloat162float(h1));
    *(__nv_bfloat162*)(ol + e) = p;
    p.x = __float2bfloat16(o[2] - __bfloat162float(h2));
    p.y = __float2bfloat16(o[3] - __bfloat162float(h3));
    *(__nv_bfloat162*)(ol + e + 2) = p;
}

// ---------------------------------------------------------------------------
// Launch
// ---------------------------------------------------------------------------
extern "C" void kernel_launch(void* const* d_in, const int* in_sizes, int n_in,
                              void* d_out, int out_size)
{
    const float* x    = (const float*)d_in[0];
    const float* W1   = (const float*)d_in[4];
    const float* b1   = (const float*)d_in[5];
    const float* Woff = (const float*)d_in[6];
    const float* boff = (const float*)d_in[7];
    const float* W2   = (const float*)d_in[8];
    const float* b2   = (const float*)d_in[9];
    const float* Wf1  = (const float*)d_in[10];
    const float* bf1  = (const float*)d_in[11];
    const float* Wf2  = (const float*)d_in[12];
    const float* bf2  = (const float*)d_in[13];
    const float* gcv  = (const float*)d_in[14];
    const float* bcv  = (const float*)d_in[15];
    const float* gfn  = (const float*)d_in[16];
    const float* bfn  = (const float*)d_in[17];

    __nv_bfloat16 *Ahp, *Alp, *Mhp, *Mlp;
    __nv_bfloat16 *W1h, *W1l, *W2h, *W2l, *Wf1h, *Wf1l, *Wf2h, *Wf2l;
    float *big, *glu, *S, *y, *alpha, *part;
    cudaGetSymbolAddress((void**)&Ahp, g_Ah);   cudaGetSymbolAddress((void**)&Alp, g_Al);
    cudaGetSymbolAddress((void**)&Mhp, g_Mh);   cudaGetSymbolAddress((void**)&Mlp, g_Ml);
    cudaGetSymbolAddress((void**)&W1h, g_W1h);  cudaGetSymbolAddress((void**)&W1l, g_W1l);
    cudaGetSymbolAddress((void**)&W2h, g_W2h);  cudaGetSymbolAddress((void**)&W2l, g_W2l);
    cudaGetSymbolAddress((void**)&Wf1h, g_Wf1h); cudaGetSymbolAddress((void**)&Wf1l, g_Wf1l);
    cudaGetSymbolAddress((void**)&Wf2h, g_Wf2h); cudaGetSymbolAddress((void**)&Wf2l, g_Wf2l);
    cudaGetSymbolAddress((void**)&big, g_big);  cudaGetSymbolAddress((void**)&glu, g_glu);
    cudaGetSymbolAddress((void**)&S, g_S);      cudaGetSymbolAddress((void**)&y, g_y);
    cudaGetSymbolAddress((void**)&alpha, g_alpha);
    cudaGetSymbolAddress((void**)&part, g_part);

    cudaFuncSetAttribute(gemm_mma<0>, cudaFuncAttributeMaxDynamicSharedMemorySize, GEMM_SMEM);
    cudaFuncSetAttribute(gemm_mma<1>, cudaFuncAttributeMaxDynamicSharedMemorySize, GEMM_SMEM);
    cudaFuncSetAttribute(gemm_mma<2>, cudaFuncAttributeMaxDynamicSharedMemorySize, GEMM_SMEM);
    cudaFuncSetAttribute(alpha_kernel, cudaFuncAttributeMaxDynamicSharedMemorySize, 65536);

    const dim3 tb(32, 8);
    wsplit_kernel<<<dim3(2048 / 32, 1024 / 32), tb>>>(W1,  W1h,  W1l,  1024, 2048);
    wsplit_kernel<<<dim3(1024 / 32, 1024 / 32), tb>>>(W2,  W2h,  W2l,  1024, 1024);
    wsplit_kernel<<<dim3(4096 / 32, 1024 / 32), tb>>>(Wf1, Wf1h, Wf1l, 1024, 4096);
    wsplit_kernel<<<dim3(1024 / 32, 4096 / 32), tb>>>(Wf2, Wf2h, Wf2l, 4096, 1024);

    const int ew_blocks = (M_TOK * 1024 / 4) / 256;   // 32768

    // conv block
    ln_split_kernel<<<M_TOK, 256>>>(x, Ahp, Alp, gcv, bcv);
    gemm_mma<0><<<dim3(16, 256), 256, GEMM_SMEM>>>(
        Ahp, Alp, W1h, W1l, b1, nullptr, big, nullptr, nullptr, M_TOK, 2048, 1024);
    glu_kernel<<<ew_blocks, 256>>>(big, glu);
    alpha_kernel<<<M_TOK / 128, 128, 65536>>>(glu, Woff, boff, alpha);
    cumsum_part<<<dim3(CHAN / 256, 8), 256>>>(glu, part);
    cumsum_scan<<<dim3(CHAN / 256, 8), 256>>>(glu, part, S);
    talk_split_kernel<<<ew_blocks, 256>>>(S, alpha, Ahp, Alp);
    gemm_mma<2><<<dim3(8, 256), 256, GEMM_SMEM>>>(
        Ahp, Alp, W2h, W2l, b2, x, y, nullptr, nullptr, M_TOK, 1024, 1024);

    // FFN block
    ln_split_kernel<<<M_TOK, 256>>>(y, Ahp, Alp, gfn, bfn);
    gemm_mma<1><<<dim3(32, 256), 256, GEMM_SMEM>>>(
        Ahp, Alp, Wf1h, Wf1l, bf1, nullptr, nullptr, Mhp, Mlp, M_TOK, 4096, 1024);
    gemm_mma<2><<<dim3(8, 256), 256, GEMM_SMEM>>>(
        Mhp, Mlp, Wf2h, Wf2l, bf2, y, (float*)d_out, nullptr, nullptr, M_TOK, 1024, 4096);
}

// round 4
// speedup vs baseline: 3.0765x; 1.8963x over previous
#include <cuda_runtime.h>
#include <cuda_bf16.h>
#include <stdint.h>
#include <math.h>

#define T_DIM   4096
#define B_DIM   8
#define M_TOK   32768
#define CHAN    8192
#define BH_DIM  128

// ---------------------------------------------------------------------------
// Device-global scratch
// ---------------------------------------------------------------------------
__device__ __nv_bfloat16 g_Ah [M_TOK * 1024];
__device__ __nv_bfloat16 g_Al [M_TOK * 1024];
__device__ __nv_bfloat16 g_Mh [M_TOK * 4096];
__device__ __nv_bfloat16 g_Ml [M_TOK * 4096];
__device__ __nv_bfloat16 g_W1h[2048 * 1024], g_W1l[2048 * 1024];
__device__ __nv_bfloat16 g_W2h[1024 * 1024], g_W2l[1024 * 1024];
__device__ __nv_bfloat16 g_Wf1h[4096 * 1024], g_Wf1l[4096 * 1024];
__device__ __nv_bfloat16 g_Wf2h[1024 * 4096], g_Wf2l[1024 * 4096];
__device__ float g_big [M_TOK * 2048];
__device__ float g_glu [M_TOK * 1024];
__device__ float g_S   [M_TOK * 1024];
__device__ float g_y   [M_TOK * 1024];
__device__ float g_alpha[T_DIM * BH_DIM];
__device__ float g_part[8 * CHAN];

__device__ __forceinline__ float sigmoidf_(float v) { return 1.f / (1.f + __expf(-v)); }

__device__ __forceinline__ uint32_t smem_addr_of(const void* p) {
    uint32_t a;
    asm("{ .reg .u64 t; cvta.to.shared.u64 t, %1; cvt.u32.u64 %0, t; }" : "=r"(a) : "l"(p));
    return a;
}
__device__ __forceinline__ void ldsm4(uint32_t* r, uint32_t addr) {
    asm volatile("ldmatrix.sync.aligned.m8n8.x4.shared.b16 {%0,%1,%2,%3}, [%4];"
                 : "=r"(r[0]), "=r"(r[1]), "=r"(r[2]), "=r"(r[3]) : "r"(addr));
}
__device__ __forceinline__ void mma16816(float* d, const uint32_t* a, const uint32_t* b) {
    asm volatile("mma.sync.aligned.m16n8k16.row.col.f32.bf16.bf16.f32 "
                 "{%0,%1,%2,%3}, {%4,%5,%6,%7}, {%8,%9}, {%0,%1,%2,%3};"
                 : "+f"(d[0]), "+f"(d[1]), "+f"(d[2]), "+f"(d[3])
                 : "r"(a[0]), "r"(a[1]), "r"(a[2]), "r"(a[3]), "r"(b[0]), "r"(b[1]));
}
__device__ __forceinline__ void cpa16(uint32_t s, const void* g) {
    asm volatile("cp.async.cg.shared.global [%0], [%1], 16;" :: "r"(s), "l"(g));
}
__device__ __forceinline__ void cpa_commit() {
    asm volatile("cp.async.commit_group;" ::: "memory");
}
__device__ __forceinline__ void cpa_wait1() {
    asm volatile("cp.async.wait_group 1;" ::: "memory");
}

// ---------------------------------------------------------------------------
// bf16 hi/lo emulated fp32 GEMM on mma.sync.
// CTA 128x128, 8 warps (64x32), BK=32, 3-stage cp.async ring, swizzled 64B
// rows (no pad) -> 96KB smem -> 2 CTAs/SM.
// EPI: 0 = +bias -> fp32 ; 1 = +bias, swish -> bf16 hi/lo ; 2 = +bias+res -> fp32
// ---------------------------------------------------------------------------
#define TILE_B  8192                // 128 rows * 64B
#define STAGE_B 32768               // Ah, Al, Bh, Bl tiles
#define GEMM_SMEM (3 * STAGE_B)     // 98304

template<int EPI>
__global__ __launch_bounds__(256, 2) void gemm_mma(
    const __nv_bfloat16* __restrict__ Ah, const __nv_bfloat16* __restrict__ Al,
    const __nv_bfloat16* __restrict__ Bh, const __nv_bfloat16* __restrict__ Bl,
    const float* __restrict__ bias, const float* __restrict__ res,
    float* __restrict__ C, __nv_bfloat16* __restrict__ Ch, __nv_bfloat16* __restrict__ Cl,
    int M, int N, int K)
{
    extern __shared__ __align__(1024) char smem[];
    const uint32_t sb = smem_addr_of(smem);
    const int tid = threadIdx.x, wid = tid >> 5, lane = tid & 31;
    const int wm = wid & 1, wn = wid >> 1;
    const int m0 = blockIdx.y << 7, n0 = blockIdx.x << 7;

    const __nv_bfloat16* gt[4] = {
        Ah + (size_t)m0 * K, Al + (size_t)m0 * K,
        Bh + (size_t)n0 * K, Bl + (size_t)n0 * K };

    // loader mapping: thread t -> row r = t>>2, 16B chunk c = t&3 (+128 rows on i=1)
    const int ldr = tid >> 2;
    const int ldc = tid & 3;

    auto load_stage = [&](int s, int chunk) {
        const uint32_t sbase = sb + s * STAGE_B;
        const int k0 = chunk << 5;
        #pragma unroll
        for (int t = 0; t < 4; t++) {
            #pragma unroll
            for (int i = 0; i < 2; i++) {
                const int r = ldr + (i << 6);
                const uint32_t dst = sbase + t * TILE_B + r * 64 +
                                     ((ldc ^ ((r >> 1) & 3)) << 4);
                cpa16(dst, gt[t] + (size_t)r * K + k0 + (ldc << 3));
            }
        }
    };

    float acc[4][4][4];
    #pragma unroll
    for (int a = 0; a < 4; a++)
        #pragma unroll
        for (int b = 0; b < 4; b++)
            #pragma unroll
            for (int k = 0; k < 4; k++) acc[a][b][k] = 0.f;

    const int NC = K >> 5;
    load_stage(0, 0); cpa_commit();
    load_stage(1, 1); cpa_commit();

    // per-lane fragment addressing (swizzled)
    const int ar = (wm << 6) + (lane & 15);
    const uint32_t aRow = (uint32_t)ar * 64;
    const int ax = (ar >> 1) & 3;
    const int ahalf = lane >> 4;
    const int br = (wn << 5) + ((lane & 7) | ((lane & 16) >> 1));
    const uint32_t bRow = (uint32_t)br * 64;
    const int bx = (br >> 1) & 3;
    const int bhalf = (lane >> 3) & 1;

    #pragma unroll 1
    for (int c = 0; c < NC; c++) {
        cpa_wait1();
        __syncthreads();
        if (c + 2 < NC) load_stage((c + 2) % 3, c + 2);
        cpa_commit();

        const uint32_t st = sb + (c % 3) * STAGE_B;
        const uint32_t aH = st + aRow;
        const uint32_t bH = st + 2 * TILE_B + bRow;

        #pragma unroll
        for (int kk = 0; kk < 2; kk++) {
            const uint32_t acol = (uint32_t)(((kk << 1) + ahalf) ^ ax) << 4;
            const uint32_t bcol = (uint32_t)(((kk << 1) + bhalf) ^ bx) << 4;
            uint32_t bh[2][4], bl[2][4];
            #pragma unroll
            for (int f2 = 0; f2 < 2; f2++) {
                ldsm4(bh[f2], bH + f2 * 1024 + bcol);
                ldsm4(bl[f2], bH + TILE_B + f2 * 1024 + bcol);
            }
            #pragma unroll
            for (int fm = 0; fm < 4; fm++) {
                uint32_t a_h[4], a_l[4];
                ldsm4(a_h, aH + fm * 1024 + acol);
                ldsm4(a_l, aH + TILE_B + fm * 1024 + acol);
                #pragma unroll
                for (int fn = 0; fn < 4; fn++) {
                    const uint32_t* bhf = &bh[fn >> 1][(fn & 1) << 1];
                    const uint32_t* blf = &bl[fn >> 1][(fn & 1) << 1];
                    mma16816(acc[fm][fn], a_h, bhf);
                    mma16816(acc[fm][fn], a_h, blf);
                    mma16816(acc[fm][fn], a_l, bhf);
                }
            }
        }
        __syncthreads();
    }

    // ---- epilogue ----
    const int mB = m0 + (wm << 6) + (lane >> 2);
    const int nB = n0 + (wn << 5) + ((lane & 3) << 1);
    #pragma unroll
    for (int fm = 0; fm < 4; fm++) {
        const int r0 = mB + (fm << 4);
        #pragma unroll
        for (int fn = 0; fn < 4; fn++) {
            const int cc = nB + (fn << 3);
            const float2 bv = __ldg((const float2*)(bias + cc));
            float v0 = acc[fm][fn][0] + bv.x;
            float v1 = acc[fm][fn][1] + bv.y;
            float v2 = acc[fm][fn][2] + bv.x;
            float v3 = acc[fm][fn][3] + bv.y;
            const size_t o0 = (size_t)r0 * N + cc;
            const size_t o1 = (size_t)(r0 + 8) * N + cc;
            if (EPI == 1) {
                v0 = v0 * sigmoidf_(v0); v1 = v1 * sigmoidf_(v1);
                v2 = v2 * sigmoidf_(v2); v3 = v3 * sigmoidf_(v3);
                __nv_bfloat16 h0 = __float2bfloat16(v0), h1 = __float2bfloat16(v1);
                __nv_bfloat16 h2 = __float2bfloat16(v2), h3 = __float2bfloat16(v3);
                __nv_bfloat162 p;
                p.x = h0; p.y = h1; *(__nv_bfloat162*)(Ch + o0) = p;
                p.x = h2; p.y = h3; *(__nv_bfloat162*)(Ch + o1) = p;
                p.x = __float2bfloat16(v0 - __bfloat162float(h0));
                p.y = __float2bfloat16(v1 - __bfloat162float(h1));
                *(__nv_bfloat162*)(Cl + o0) = p;
                p.x = __float2bfloat16(v2 - __bfloat162float(h2));
                p.y = __float2bfloat16(v3 - __bfloat162float(h3));
                *(__nv_bfloat162*)(Cl + o1) = p;
            } else {
                if (EPI == 2) {
                    const float2 ra = __ldg((const float2*)(res + o0));
                    const float2 rb = __ldg((const float2*)(res + o1));
                    v0 += ra.x; v1 += ra.y; v2 += rb.x; v3 += rb.y;
                }
                float2 q;
                q.x = v0; q.y = v1; *(float2*)(C + o0) = q;
                q.x = v2; q.y = v3; *(float2*)(C + o1) = q;
            }
        }
    }
}

// ---------------------------------------------------------------------------
// Weight split + transpose: W[K,N] fp32 -> Wh,Wl [N,K] bf16
// ---------------------------------------------------------------------------
__global__ __launch_bounds__(256) void wsplit_kernel(
    const float* __restrict__ W, __nv_bfloat16* __restrict__ Wh,
    __nv_bfloat16* __restrict__ Wl, int K, int N)
{
    __shared__ float tile[32][33];
    const int n0 = blockIdx.x << 5;
    const int k0 = blockIdx.y << 5;
    for (int i = threadIdx.y; i < 32; i += 8)
        tile[i][threadIdx.x] = W[(size_t)(k0 + i) * N + n0 + threadIdx.x];
    __syncthreads();
    for (int i = threadIdx.y; i < 32; i += 8) {
        const float v = tile[threadIdx.x][i];
        const __nv_bfloat16 h = __float2bfloat16(v);
        const size_t o = (size_t)(n0 + i) * K + k0 + threadIdx.x;
        Wh[o] = h;
        Wl[o] = __float2bfloat16(v - __bfloat162float(h));
    }
}

// ---------------------------------------------------------------------------
// LayerNorm -> bf16 hi/lo split
// ---------------------------------------------------------------------------
__device__ __forceinline__ float block_sum256(float v, float* sh) {
    #pragma unroll
    for (int o = 16; o > 0; o >>= 1) v += __shfl_xor_sync(0xffffffffu, v, o);
    if ((threadIdx.x & 31) == 0) sh[threadIdx.x >> 5] = v;
    __syncthreads();
    float tot = 0.f;
    #pragma unroll
    for (int i = 0; i < 8; i++) tot += sh[i];
    __syncthreads();
    return tot;
}

__global__ __launch_bounds__(256) void ln_split_kernel(
    const float* __restrict__ in, __nv_bfloat16* __restrict__ oh,
    __nv_bfloat16* __restrict__ ol,
    const float* __restrict__ gw, const float* __restrict__ bw)
{
    __shared__ float sh[8];
    const size_t row = blockIdx.x;
    const float4 v = ((const float4*)(in + row * 1024))[threadIdx.x];

    float s = v.x + v.y + v.z + v.w;
    s = block_sum256(s, sh);
    const float mean = s * (1.f / 1024.f);
    const float dx = v.x - mean, dy = v.y - mean, dz = v.z - mean, dw = v.w - mean;
    float q = dx * dx + dy * dy + dz * dz + dw * dw;
    q = block_sum256(q, sh);
    const float rstd = rsqrtf(q * (1.f / 1024.f) + 1e-5f);

    const float4 g4 = ((const float4*)gw)[threadIdx.x];
    const float4 b4 = ((const float4*)bw)[threadIdx.x];
    float o[4];
    o[0] = dx * rstd * g4.x + b4.x;
    o[1] = dy * rstd * g4.y + b4.y;
    o[2] = dz * rstd * g4.z + b4.z;
    o[3] = dw * rstd * g4.w + b4.w;

    const size_t base = row * 1024 + (size_t)threadIdx.x * 4;
    __nv_bfloat16 h0 = __float2bfloat16(o[0]), h1 = __float2bfloat16(o[1]);
    __nv_bfloat16 h2 = __float2bfloat16(o[2]), h3 = __float2bfloat16(o[3]);
    __nv_bfloat162 p;
    p.x = h0; p.y = h1; *(__nv_bfloat162*)(oh + base) = p;
    p.x = h2; p.y = h3; *(__nv_bfloat162*)(oh + base + 2) = p;
    p.x = __float2bfloat16(o[0] - __bfloat162float(h0));
    p.y = __float2bfloat16(o[1] - __bfloat162float(h1));
    *(__nv_bfloat162*)(ol + base) = p;
    p.x = __float2bfloat16(o[2] - __bfloat162float(h2));
    p.y = __float2bfloat16(o[3] - __bfloat162float(h3));
    *(__nv_bfloat162*)(ol + base + 2) = p;
}

// ---------------------------------------------------------------------------
// GLU
// ---------------------------------------------------------------------------
__global__ __launch_bounds__(256) void glu_kernel(
    const float* __restrict__ h2, float* __restrict__ out)
{
    const size_t e = ((size_t)blockIdx.x * blockDim.x + threadIdx.x) << 2;
    const size_t m = e >> 10;
    const int c = (int)(e & 1023);
    const float4 a = *(const float4*)(h2 + m * 2048 + c);
    const float4 g = *(const float4*)(h2 + m * 2048 + 1024 + c);
    float4 o;
    o.x = a.x * sigmoidf_(g.x);
    o.y = a.y * sigmoidf_(g.y);
    o.z = a.z * sigmoidf_(g.z);
    o.w = a.w * sigmoidf_(g.w);
    *(float4*)(out + e) = o;
}

// ---------------------------------------------------------------------------
// alpha = sigmoid(glu @ W_off + b_off). W_off cached in smem (64KB),
// one thread per token row, 128 rows per block.
// ---------------------------------------------------------------------------
__global__ __launch_bounds__(128) void alpha_kernel(
    const float* __restrict__ g, const float* __restrict__ Woff,
    const float* __restrict__ boff, float* __restrict__ alpha)
{
    extern __shared__ float Ws[];
    for (int i = threadIdx.x; i < 4096; i += 128)
        ((float4*)Ws)[i] = ((const float4*)Woff)[i];
    __syncthreads();

    const int row = blockIdx.x * 128 + threadIdx.x;
    const float* gr = g + (size_t)row * 1024;
    float acc[16];
    #pragma unroll
    for (int n = 0; n < 16; n++) acc[n] = 0.f;

    #pragma unroll 4
    for (int k4 = 0; k4 < 256; k4++) {
        const float4 v = ((const float4*)gr)[k4];
        const float vv[4] = {v.x, v.y, v.z, v.w};
        #pragma unroll
        for (int j = 0; j < 4; j++) {
            const float4* w = (const float4*)(Ws + (k4 * 4 + j) * 16);
            const float4 w0 = w[0], w1 = w[1], w2 = w[2], w3 = w[3];
            const float s = vv[j];
            acc[0]  = fmaf(s, w0.x, acc[0]);  acc[1]  = fmaf(s, w0.y, acc[1]);
            acc[2]  = fmaf(s, w0.z, acc[2]);  acc[3]  = fmaf(s, w0.w, acc[3]);
            acc[4]  = fmaf(s, w1.x, acc[4]);  acc[5]  = fmaf(s, w1.y, acc[5]);
            acc[6]  = fmaf(s, w1.z, acc[6]);  acc[7]  = fmaf(s, w1.w, acc[7]);
            acc[8]  = fmaf(s, w2.x, acc[8]);  acc[9]  = fmaf(s, w2.y, acc[9]);
            acc[10] = fmaf(s, w2.z, acc[10]); acc[11] = fmaf(s, w2.w, acc[11]);
            acc[12] = fmaf(s, w3.x, acc[12]); acc[13] = fmaf(s, w3.y, acc[13]);
            acc[14] = fmaf(s, w3.z, acc[14]); acc[15] = fmaf(s, w3.w, acc[15]);
        }
    }
    const int t = row >> 3, b = row & 7;
    float* ap = alpha + (size_t)t * BH_DIM + b * 16;
    #pragma unroll
    for (int n = 0; n < 16; n++)
        ap[n] = sigmoidf_(acc[n] + __ldg(boff + n));
}

// ---------------------------------------------------------------------------
// Segmented cumsum over time (scale 1/32)
// ---------------------------------------------------------------------------
__global__ __launch_bounds__(256) void cumsum_part(
    const float* __restrict__ in, float* __restrict__ part)
{
    const int c = blockIdx.x * 256 + threadIdx.x;
    const int s = blockIdx.y;
    float acc = 0.f;
    for (int t0 = s * 512; t0 < (s + 1) * 512; t0 += 8) {
        float v[8];
        #pragma unroll
        for (int i = 0; i < 8; i++) v[i] = in[(size_t)(t0 + i) * CHAN + c];
        #pragma unroll
        for (int i = 0; i < 8; i++) acc += v[i];
    }
    part[s * CHAN + c] = acc;
}

__global__ __launch_bounds__(256) void cumsum_scan(
    const float* __restrict__ in, const float* __restrict__ part,
    float* __restrict__ out)
{
    const int c = blockIdx.x * 256 + threadIdx.x;
    const int s = blockIdx.y;
    const float scale = 1.f / 32.f;
    float acc = 0.f;
    for (int p = 0; p < s; p++) acc += part[p * CHAN + c];
    acc *= scale;
    for (int t0 = s * 512; t0 < (s + 1) * 512; t0 += 8) {
        float v[8];
        #pragma unroll
        for (int i = 0; i < 8; i++) v[i] = in[(size_t)(t0 + i) * CHAN + c];
        #pragma unroll
        for (int i = 0; i < 8; i++) {
            acc = fmaf(v[i], scale, acc);
            out[(size_t)(t0 + i) * CHAN + c] = acc;
        }
    }
}

// ---------------------------------------------------------------------------
// TaLK gather/lerp -> bf16 hi/lo split
// ---------------------------------------------------------------------------
__global__ __launch_bounds__(256) void talk_split_kernel(
    const float* __restrict__ S, const float* __restrict__ alpha,
    __nv_bfloat16* __restrict__ oh, __nv_bfloat16* __restrict__ ol)
{
    const size_t e = ((size_t)blockIdx.x * blockDim.x + threadIdx.x) << 2;
    const int t = (int)(e >> 13);
    const int col = (int)(e & 8191);
    const int bh = col >> 6;

    const float al = alpha[(size_t)t * BH_DIM + bh];
    const float eff = fminf(31.f, (float)t);
    const float pos = (float)t - 1.f - al * eff;
    const float i0f = floorf(pos);
    const float frac = pos - i0f;
    const int i0 = (int)i0f;
    const int c0 = max(i0, 0);
    const int c1 = i0 + 1;

    const float4 s  = *(const float4*)(S + (size_t)t  * CHAN + col);
    float4 v0       = *(const float4*)(S + (size_t)c0 * CHAN + col);
    const float4 v1 = *(const float4*)(S + (size_t)c1 * CHAN + col);
    if (i0 < 0) { v0.x = 0.f; v0.y = 0.f; v0.z = 0.f; v0.w = 0.f; }

    float o[4];
    o[0] = s.x - (v0.x + frac * (v1.x - v0.x));
    o[1] = s.y - (v0.y + frac * (v1.y - v0.y));
    o[2] = s.z - (v0.z + frac * (v1.z - v0.z));
    o[3] = s.w - (v0.w + frac * (v1.w - v0.w));

    __nv_bfloat16 h0 = __float2bfloat16(o[0]), h1 = __float2bfloat16(o[1]);
    __nv_bfloat16 h2 = __float2bfloat16(o[2]), h3 = __float2bfloat16(o[3]);
    __nv_bfloat162 p;
    p.x = h0; p.y = h1; *(__nv_bfloat162*)(oh + e) = p;
    p.x = h2; p.y = h3; *(__nv_bfloat162*)(oh + e + 2) = p;
    p.x = __float2bfloat16(o[0] - __bfloat162float(h0));
    p.y = __float2bfloat16(o[1] - __bfloat162float(h1));
    *(__nv_bfloat162*)(ol + e) = p;
    p.x = __float2bfloat16(o[2] - __bfloat162float(h2));
    p.y = __float2bfloat16(o[3] - __bfloat162float(h3));
    *(__nv_bfloat162*)(ol + e + 2) = p;
}

// ---------------------------------------------------------------------------
// Launch
// ---------------------------------------------------------------------------
extern "C" void kernel_launch(void* const* d_in, const int* in_sizes, int n_in,
                              void* d_out, int out_size)
{
    const float* x    = (const float*)d_in[0];
    const float* W1   = (const float*)d_in[4];
    const float* b1   = (const float*)d_in[5];
    const float* Woff = (const float*)d_in[6];
    const float* boff = (const float*)d_in[7];
    const float* W2   = (const float*)d_in[8];
    const float* b2   = (const float*)d_in[9];
    const float* Wf1  = (const float*)d_in[10];
    const float* bf1  = (const float*)d_in[11];
    const float* Wf2  = (const float*)d_in[12];
    const float* bf2  = (const float*)d_in[13];
    const float* gcv  = (const float*)d_in[14];
    const float* bcv  = (const float*)d_in[15];
    const float* gfn  = (const float*)d_in[16];
    const float* bfn  = (const float*)d_in[17];

    __nv_bfloat16 *Ahp, *Alp, *Mhp, *Mlp;
    __nv_bfloat16 *W1h, *W1l, *W2h, *W2l, *Wf1h, *Wf1l, *Wf2h, *Wf2l;
    float *big, *glu, *S, *y, *alpha, *part;
    cudaGetSymbolAddress((void**)&Ahp, g_Ah);   cudaGetSymbolAddress((void**)&Alp, g_Al);
    cudaGetSymbolAddress((void**)&Mhp, g_Mh);   cudaGetSymbolAddress((void**)&Mlp, g_Ml);
    cudaGetSymbolAddress((void**)&W1h, g_W1h);  cudaGetSymbolAddress((void**)&W1l, g_W1l);
    cudaGetSymbolAddress((void**)&W2h, g_W2h);  cudaGetSymbolAddress((void**)&W2l, g_W2l);
    cudaGetSymbolAddress((void**)&Wf1h, g_Wf1h); cudaGetSymbolAddress((void**)&Wf1l, g_Wf1l);
    cudaGetSymbolAddress((void**)&Wf2h, g_Wf2h); cudaGetSymbolAddress((void**)&Wf2l, g_Wf2l);
    cudaGetSymbolAddress((void**)&big, g_big);  cudaGetSymbolAddress((void**)&glu, g_glu);
    cudaGetSymbolAddress((void**)&S, g_S);      cudaGetSymbolAddress((void**)&y, g_y);
    cudaGetSymbolAddress((void**)&alpha, g_alpha);
    cudaGetSymbolAddress((void**)&part, g_part);

    cudaFuncSetAttribute(gemm_mma<0>, cudaFuncAttributeMaxDynamicSharedMemorySize, GEMM_SMEM);
    cudaFuncSetAttribute(gemm_mma<1>, cudaFuncAttributeMaxDynamicSharedMemorySize, GEMM_SMEM);
    cudaFuncSetAttribute(gemm_mma<2>, cudaFuncAttributeMaxDynamicSharedMemorySize, GEMM_SMEM);
    cudaFuncSetAttribute(alpha_kernel, cudaFuncAttributeMaxDynamicSharedMemorySize, 65536);

    const dim3 tb(32, 8);
    wsplit_kernel<<<dim3(2048 / 32, 1024 / 32), tb>>>(W1,  W1h,  W1l,  1024, 2048);
    wsplit_kernel<<<dim3(1024 / 32, 1024 / 32), tb>>>(W2,  W2h,  W2l,  1024, 1024);
    wsplit_kernel<<<dim3(4096 / 32, 1024 / 32), tb>>>(Wf1, Wf1h, Wf1l, 1024, 4096);
    wsplit_kernel<<<dim3(1024 / 32, 4096 / 32), tb>>>(Wf2, Wf2h, Wf2l, 4096, 1024);

    const int ew_blocks = (M_TOK * 1024 / 4) / 256;

    // conv block
    ln_split_kernel<<<M_TOK, 256>>>(x, Ahp, Alp, gcv, bcv);
    gemm_mma<0><<<dim3(16, 256), 256, GEMM_SMEM>>>(
        Ahp, Alp, W1h, W1l, b1, nullptr, big, nullptr, nullptr, M_TOK, 2048, 1024);
    glu_kernel<<<ew_blocks, 256>>>(big, glu);
    alpha_kernel<<<M_TOK / 128, 128, 65536>>>(glu, Woff, boff, alpha);
    cumsum_part<<<dim3(CHAN / 256, 8), 256>>>(glu, part);
    cumsum_scan<<<dim3(CHAN / 256, 8), 256>>>(glu, part, S);
    talk_split_kernel<<<ew_blocks, 256>>>(S, alpha, Ahp, Alp);
    gemm_mma<2><<<dim3(8, 256), 256, GEMM_SMEM>>>(
        Ahp, Alp, W2h, W2l, b2, x, y, nullptr, nullptr, M_TOK, 1024, 1024);

    // FFN block
    ln_split_kernel<<<M_TOK, 256>>>(y, Ahp, Alp, gfn, bfn);
    gemm_mma<1><<<dim3(32, 256), 256, GEMM_SMEM>>>(
        Ahp, Alp, Wf1h, Wf1l, bf1, nullptr, nullptr, Mhp, Mlp, M_TOK, 4096, 1024);
    gemm_mma<2><<<dim3(8, 256), 256, GEMM_SMEM>>>(
        Mhp, Mlp, Wf2h, Wf2l, bf2, y, (float*)d_out, nullptr, nullptr, M_TOK, 1024, 4096);
}

// round 5
// speedup vs baseline: 3.0964x; 1.0065x over previous
#include <cuda_runtime.h>
#include <cuda_bf16.h>
#include <stdint.h>
#include <math.h>

#define T_DIM   4096
#define B_DIM   8
#define M_TOK   32768
#define CHAN    8192
#define BH_DIM  128

// ---------------------------------------------------------------------------
// Device-global scratch
// ---------------------------------------------------------------------------
__device__ __nv_bfloat16 g_Ah [M_TOK * 1024];
__device__ __nv_bfloat16 g_Al [M_TOK * 1024];
__device__ __nv_bfloat16 g_Mh [M_TOK * 4096];
__device__ __nv_bfloat16 g_Ml [M_TOK * 4096];
__device__ __nv_bfloat16 g_W1h[2048 * 1024], g_W1l[2048 * 1024];   // permuted (a/gate interleaved)
__device__ __nv_bfloat16 g_W2h[1024 * 1024], g_W2l[1024 * 1024];
__device__ __nv_bfloat16 g_Wf1h[4096 * 1024], g_Wf1l[4096 * 1024];
__device__ __nv_bfloat16 g_Wf2h[1024 * 4096], g_Wf2l[1024 * 4096];
__device__ float g_glu [M_TOK * 1024];
__device__ float g_S   [M_TOK * 1024];
__device__ float g_y   [M_TOK * 1024];
__device__ float g_alpha[T_DIM * BH_DIM];
__device__ float g_part[8 * CHAN];

__device__ __forceinline__ float sigmoidf_(float v) { return 1.f / (1.f + __expf(-v)); }

__device__ __forceinline__ uint32_t smem_addr_of(const void* p) {
    uint32_t a;
    asm("{ .reg .u64 t; cvta.to.shared.u64 t, %1; cvt.u32.u64 %0, t; }" : "=r"(a) : "l"(p));
    return a;
}
__device__ __forceinline__ void ldsm4(uint32_t* r, uint32_t addr) {
    asm volatile("ldmatrix.sync.aligned.m8n8.x4.shared.b16 {%0,%1,%2,%3}, [%4];"
                 : "=r"(r[0]), "=r"(r[1]), "=r"(r[2]), "=r"(r[3]) : "r"(addr));
}
__device__ __forceinline__ void mma16816(float* d, const uint32_t* a, const uint32_t* b) {
    asm volatile("mma.sync.aligned.m16n8k16.row.col.f32.bf16.bf16.f32 "
                 "{%0,%1,%2,%3}, {%4,%5,%6,%7}, {%8,%9}, {%0,%1,%2,%3};"
                 : "+f"(d[0]), "+f"(d[1]), "+f"(d[2]), "+f"(d[3])
                 : "r"(a[0]), "r"(a[1]), "r"(a[2]), "r"(a[3]), "r"(b[0]), "r"(b[1]));
}
__device__ __forceinline__ void cpa16(uint32_t s, const void* g) {
    asm volatile("cp.async.cg.shared.global [%0], [%1], 16;" :: "r"(s), "l"(g));
}
__device__ __forceinline__ void cpa_commit() {
    asm volatile("cp.async.commit_group;" ::: "memory");
}
__device__ __forceinline__ void cpa_wait1() {
    asm volatile("cp.async.wait_group 1;" ::: "memory");
}

// ---------------------------------------------------------------------------
// bf16 hi/lo emulated fp32 GEMM on mma.sync.
// CTA 128x128, 8 warps (64x32), BK=32, 3-stage cp.async ring, swizzled 64B
// rows -> 96KB smem -> 2 CTAs/SM.
// EPI: 1 = +bias, swish -> bf16 hi/lo ; 2 = +bias + residual -> fp32 ;
//      3 = GLU (paired cols a/gate) +bias -> fp32 glu [M, N/2]
// ---------------------------------------------------------------------------
#define TILE_B  8192
#define STAGE_B 32768
#define GEMM_SMEM (3 * STAGE_B)

template<int EPI>
__global__ __launch_bounds__(256, 2) void gemm_mma(
    const __nv_bfloat16* __restrict__ Ah, const __nv_bfloat16* __restrict__ Al,
    const __nv_bfloat16* __restrict__ Bh, const __nv_bfloat16* __restrict__ Bl,
    const float* __restrict__ bias, const float* __restrict__ res,
    float* __restrict__ C, __nv_bfloat16* __restrict__ Ch, __nv_bfloat16* __restrict__ Cl,
    int M, int N, int K)
{
    extern __shared__ __align__(1024) char smem[];
    const uint32_t sb = smem_addr_of(smem);
    const int tid = threadIdx.x, wid = tid >> 5, lane = tid & 31;
    const int wm = wid & 1, wn = wid >> 1;
    const int m0 = blockIdx.y << 7, n0 = blockIdx.x << 7;

    const __nv_bfloat16* gt[4] = {
        Ah + (size_t)m0 * K, Al + (size_t)m0 * K,
        Bh + (size_t)n0 * K, Bl + (size_t)n0 * K };

    const int ldr = tid >> 2;
    const int ldc = tid & 3;

    auto load_stage = [&](int s, int chunk) {
        const uint32_t sbase = sb + s * STAGE_B;
        const int k0 = chunk << 5;
        #pragma unroll
        for (int t = 0; t < 4; t++) {
            #pragma unroll
            for (int i = 0; i < 2; i++) {
                const int r = ldr + (i << 6);
                const uint32_t dst = sbase + t * TILE_B + r * 64 +
                                     ((ldc ^ ((r >> 1) & 3)) << 4);
                cpa16(dst, gt[t] + (size_t)r * K + k0 + (ldc << 3));
            }
        }
    };

    float acc[4][4][4];
    #pragma unroll
    for (int a = 0; a < 4; a++)
        #pragma unroll
        for (int b = 0; b < 4; b++)
            #pragma unroll
            for (int k = 0; k < 4; k++) acc[a][b][k] = 0.f;

    const int NC = K >> 5;
    load_stage(0, 0); cpa_commit();
    load_stage(1, 1); cpa_commit();

    const int ar = (wm << 6) + (lane & 15);
    const uint32_t aRow = (uint32_t)ar * 64;
    const int ax = (ar >> 1) & 3;
    const int ahalf = lane >> 4;
    const int br = (wn << 5) + ((lane & 7) | ((lane & 16) >> 1));
    const uint32_t bRow = (uint32_t)br * 64;
    const int bx = (br >> 1) & 3;
    const int bhalf = (lane >> 3) & 1;

    #pragma unroll 1
    for (int c = 0; c < NC; c++) {
        cpa_wait1();
        __syncthreads();
        if (c + 2 < NC) load_stage((c + 2) % 3, c + 2);
        cpa_commit();

        const uint32_t st = sb + (c % 3) * STAGE_B;
        const uint32_t aH = st + aRow;
        const uint32_t bH = st + 2 * TILE_B + bRow;

        #pragma unroll
        for (int kk = 0; kk < 2; kk++) {
            const uint32_t acol = (uint32_t)(((kk << 1) + ahalf) ^ ax) << 4;
            const uint32_t bcol = (uint32_t)(((kk << 1) + bhalf) ^ bx) << 4;
            uint32_t bh[2][4], bl[2][4];
            #pragma unroll
            for (int f2 = 0; f2 < 2; f2++) {
                ldsm4(bh[f2], bH + f2 * 1024 + bcol);
                ldsm4(bl[f2], bH + TILE_B + f2 * 1024 + bcol);
            }
            #pragma unroll
            for (int fm = 0; fm < 4; fm++) {
                uint32_t a_h[4], a_l[4];
                ldsm4(a_h, aH + fm * 1024 + acol);
                ldsm4(a_l, aH + TILE_B + fm * 1024 + acol);
                #pragma unroll
                for (int fn = 0; fn < 4; fn++) {
                    const uint32_t* bhf = &bh[fn >> 1][(fn & 1) << 1];
                    const uint32_t* blf = &bl[fn >> 1][(fn & 1) << 1];
                    mma16816(acc[fm][fn], a_h, bhf);
                    mma16816(acc[fm][fn], a_h, blf);
                    mma16816(acc[fm][fn], a_l, bhf);
                }
            }
        }
        __syncthreads();
    }

    // ---- epilogue ----
    const int mB = m0 + (wm << 6) + (lane >> 2);
    const int nB = n0 + (wn << 5) + ((lane & 3) << 1);
    #pragma unroll
    for (int fm = 0; fm < 4; fm++) {
        const int r0 = mB + (fm << 4);
        #pragma unroll
        for (int fn = 0; fn < 4; fn++) {
            const int cc = nB + (fn << 3);
            if (EPI == 3) {
                // paired columns: even = a, odd = gate. Output col j = cc/2.
                const int j = cc >> 1;
                const float ba = __ldg(bias + j);
                const float bg = __ldg(bias + 1024 + j);
                const float a0 = acc[fm][fn][0] + ba, gg0 = acc[fm][fn][1] + bg;
                const float a1 = acc[fm][fn][2] + ba, gg1 = acc[fm][fn][3] + bg;
                C[(size_t)r0 * (N >> 1) + j]       = a0 * sigmoidf_(gg0);
                C[(size_t)(r0 + 8) * (N >> 1) + j] = a1 * sigmoidf_(gg1);
            } else {
                const float2 bv = __ldg((const float2*)(bias + cc));
                float v0 = acc[fm][fn][0] + bv.x;
                float v1 = acc[fm][fn][1] + bv.y;
                float v2 = acc[fm][fn][2] + bv.x;
                float v3 = acc[fm][fn][3] + bv.y;
                const size_t o0 = (size_t)r0 * N + cc;
                const size_t o1 = (size_t)(r0 + 8) * N + cc;
                if (EPI == 1) {
                    v0 = v0 * sigmoidf_(v0); v1 = v1 * sigmoidf_(v1);
                    v2 = v2 * sigmoidf_(v2); v3 = v3 * sigmoidf_(v3);
                    __nv_bfloat16 h0 = __float2bfloat16(v0), h1 = __float2bfloat16(v1);
                    __nv_bfloat16 h2 = __float2bfloat16(v2), h3 = __float2bfloat16(v3);
                    __nv_bfloat162 p;
                    p.x = h0; p.y = h1; *(__nv_bfloat162*)(Ch + o0) = p;
                    p.x = h2; p.y = h3; *(__nv_bfloat162*)(Ch + o1) = p;
                    p.x = __float2bfloat16(v0 - __bfloat162float(h0));
                    p.y = __float2bfloat16(v1 - __bfloat162float(h1));
                    *(__nv_bfloat162*)(Cl + o0) = p;
                    p.x = __float2bfloat16(v2 - __bfloat162float(h2));
                    p.y = __float2bfloat16(v3 - __bfloat162float(h3));
                    *(__nv_bfloat162*)(Cl + o1) = p;
                } else {
                    const float2 ra = __ldg((const float2*)(res + o0));
                    const float2 rb = __ldg((const float2*)(res + o1));
                    v0 += ra.x; v1 += ra.y; v2 += rb.x; v3 += rb.y;
                    float2 q;
                    q.x = v0; q.y = v1; *(float2*)(C + o0) = q;
                    q.x = v2; q.y = v3; *(float2*)(C + o1) = q;
                }
            }
        }
    }
}

// ---------------------------------------------------------------------------
// Weight split + transpose: W[K,N] fp32 -> Wh,Wl [N,K] bf16
// ---------------------------------------------------------------------------
__global__ __launch_bounds__(256) void wsplit_kernel(
    const float* __restrict__ W, __nv_bfloat16* __restrict__ Wh,
    __nv_bfloat16* __restrict__ Wl, int K, int N)
{
    __shared__ float tile[32][33];
    const int n0 = blockIdx.x << 5;
    const int k0 = blockIdx.y << 5;
    for (int i = threadIdx.y; i < 32; i += 8)
        tile[i][threadIdx.x] = W[(size_t)(k0 + i) * N + n0 + threadIdx.x];
    __syncthreads();
    for (int i = threadIdx.y; i < 32; i += 8) {
        const float v = tile[threadIdx.x][i];
        const __nv_bfloat16 h = __float2bfloat16(v);
        const size_t o = (size_t)(n0 + i) * K + k0 + threadIdx.x;
        Wh[o] = h;
        Wl[o] = __float2bfloat16(v - __bfloat162float(h));
    }
}

// W1 permuted: out row 2j = src col j (a), out row 2j+1 = src col 1024+j (gate)
__global__ __launch_bounds__(256) void wsplit_perm_kernel(
    const float* __restrict__ W, __nv_bfloat16* __restrict__ Wh,
    __nv_bfloat16* __restrict__ Wl)
{
    __shared__ float tile[32][33];
    const int n0 = blockIdx.x << 5;   // output row block (0..2047)
    const int k0 = blockIdx.y << 5;
    const int tx = threadIdx.x;
    const int orow = n0 + tx;
    const int scol = (orow & 1) ? (1024 + (orow >> 1)) : (orow >> 1);
    for (int i = threadIdx.y; i < 32; i += 8)
        tile[i][tx] = W[(size_t)(k0 + i) * 2048 + scol];
    __syncthreads();
    for (int i = threadIdx.y; i < 32; i += 8) {
        const float v = tile[tx][i];
        const __nv_bfloat16 h = __float2bfloat16(v);
        const size_t o = (size_t)(n0 + i) * 1024 + k0 + tx;
        Wh[o] = h;
        Wl[o] = __float2bfloat16(v - __bfloat162float(h));
    }
}

// ---------------------------------------------------------------------------
// LayerNorm -> bf16 hi/lo split
// ---------------------------------------------------------------------------
__device__ __forceinline__ float block_sum256(float v, float* sh) {
    #pragma unroll
    for (int o = 16; o > 0; o >>= 1) v += __shfl_xor_sync(0xffffffffu, v, o);
    if ((threadIdx.x & 31) == 0) sh[threadIdx.x >> 5] = v;
    __syncthreads();
    float tot = 0.f;
    #pragma unroll
    for (int i = 0; i < 8; i++) tot += sh[i];
    __syncthreads();
    return tot;
}

__global__ __launch_bounds__(256) void ln_split_kernel(
    const float* __restrict__ in, __nv_bfloat16* __restrict__ oh,
    __nv_bfloat16* __restrict__ ol,
    const float* __restrict__ gw, const float* __restrict__ bw)
{
    __shared__ float sh[8];
    const size_t row = blockIdx.x;
    const float4 v = ((const float4*)(in + row * 1024))[threadIdx.x];

    float s = v.x + v.y + v.z + v.w;
    s = block_sum256(s, sh);
    const float mean = s * (1.f / 1024.f);
    const float dx = v.x - mean, dy = v.y - mean, dz = v.z - mean, dw = v.w - mean;
    float q = dx * dx + dy * dy + dz * dz + dw * dw;
    q = block_sum256(q, sh);
    const float rstd = rsqrtf(q * (1.f / 1024.f) + 1e-5f);

    const float4 g4 = ((const float4*)gw)[threadIdx.x];
    const float4 b4 = ((const float4*)bw)[threadIdx.x];
    float o[4];
    o[0] = dx * rstd * g4.x + b4.x;
    o[1] = dy * rstd * g4.y + b4.y;
    o[2] = dz * rstd * g4.z + b4.z;
    o[3] = dw * rstd * g4.w + b4.w;

    const size_t base = row * 1024 + (size_t)threadIdx.x * 4;
    __nv_bfloat16 h0 = __float2bfloat16(o[0]), h1 = __float2bfloat16(o[1]);
    __nv_bfloat16 h2 = __float2bfloat16(o[2]), h3 = __float2bfloat16(o[3]);
    __nv_bfloat162 p;
    p.x = h0; p.y = h1; *(__nv_bfloat162*)(oh + base) = p;
    p.x = h2; p.y = h3; *(__nv_bfloat162*)(oh + base + 2) = p;
    p.x = __float2bfloat16(o[0] - __bfloat162float(h0));
    p.y = __float2bfloat16(o[1] - __bfloat162float(h1));
    *(__nv_bfloat162*)(ol + base) = p;
    p.x = __float2bfloat16(o[2] - __bfloat162float(h2));
    p.y = __float2bfloat16(o[3] - __bfloat162float(h3));
    *(__nv_bfloat162*)(ol + base + 2) = p;
}

// ---------------------------------------------------------------------------
// alpha = sigmoid(glu @ W_off + b_off). Warp per row, W_off transposed in
// smem Ws[n][k] (16 x 1024 floats = 64KB). 8 rows per block.
// ---------------------------------------------------------------------------
__global__ __launch_bounds__(256) void alpha_kernel(
    const float* __restrict__ g, const float* __restrict__ Woff,
    const float* __restrict__ boff, float* __restrict__ alpha)
{
    extern __shared__ float Ws[];   // [16][1024]
    // load transposed: thread handles k = tid, tid+256, ...
    for (int k = threadIdx.x; k < 1024; k += 256) {
        const float4 w0 = __ldg((const float4*)(Woff + (size_t)k * 16));
        const float4 w1 = __ldg((const float4*)(Woff + (size_t)k * 16 + 4));
        const float4 w2 = __ldg((const float4*)(Woff + (size_t)k * 16 + 8));
        const float4 w3 = __ldg((const float4*)(Woff + (size_t)k * 16 + 12));
        Ws[0 * 1024 + k] = w0.x; Ws[1 * 1024 + k] = w0.y;
        Ws[2 * 1024 + k] = w0.z; Ws[3 * 1024 + k] = w0.w;
        Ws[4 * 1024 + k] = w1.x; Ws[5 * 1024 + k] = w1.y;
        Ws[6 * 1024 + k] = w1.z; Ws[7 * 1024 + k] = w1.w;
        Ws[8 * 1024 + k] = w2.x; Ws[9 * 1024 + k] = w2.y;
        Ws[10 * 1024 + k] = w2.z; Ws[11 * 1024 + k] = w2.w;
        Ws[12 * 1024 + k] = w3.x; Ws[13 * 1024 + k] = w3.y;
        Ws[14 * 1024 + k] = w3.z; Ws[15 * 1024 + k] = w3.w;
    }
    __syncthreads();

    const int wid = threadIdx.x >> 5, lane = threadIdx.x & 31;
    const int row = blockIdx.x * 8 + wid;
    const float* gr = g + (size_t)row * 1024;

    float acc[16];
    #pragma unroll
    for (int n = 0; n < 16; n++) acc[n] = 0.f;

    #pragma unroll
    for (int j = 0; j < 8; j++) {
        const int k = (lane << 2) + (j << 7);
        const float4 v = *(const float4*)(gr + k);
        #pragma unroll
        for (int n = 0; n < 16; n++) {
            const float4 w = *(const float4*)(Ws + n * 1024 + k);
            acc[n] += v.x * w.x + v.y * w.y + v.z * w.z + v.w * w.w;
        }
    }
    #pragma unroll
    for (int o = 16; o > 0; o >>= 1)
        #pragma unroll
        for (int n = 0; n < 16; n++)
            acc[n] += __shfl_xor_sync(0xffffffffu, acc[n], o);

    if (lane < 16) {
        const int t = row >> 3, b = row & 7;
        alpha[(size_t)t * BH_DIM + b * 16 + lane] =
            sigmoidf_(acc[lane] + __ldg(boff + lane));
    }
}

// ---------------------------------------------------------------------------
// Segmented cumsum over time (scale 1/32)
// ---------------------------------------------------------------------------
__global__ __launch_bounds__(256) void cumsum_part(
    const float* __restrict__ in, float* __restrict__ part)
{
    const int c = blockIdx.x * 256 + threadIdx.x;
    const int s = blockIdx.y;
    float acc = 0.f;
    for (int t0 = s * 512; t0 < (s + 1) * 512; t0 += 8) {
        float v[8];
        #pragma unroll
        for (int i = 0; i < 8; i++) v[i] = in[(size_t)(t0 + i) * CHAN + c];
        #pragma unroll
        for (int i = 0; i < 8; i++) acc += v[i];
    }
    part[s * CHAN + c] = acc;
}

__global__ __launch_bounds__(256) void cumsum_scan(
    const float* __restrict__ in, const float* __restrict__ part,
    float* __restrict__ out)
{
    const int c = blockIdx.x * 256 + threadIdx.x;
    const int s = blockIdx.y;
    const float scale = 1.f / 32.f;
    float acc = 0.f;
    for (int p = 0; p < s; p++) acc += part[p * CHAN + c];
    acc *= scale;
    for (int t0 = s * 512; t0 < (s + 1) * 512; t0 += 8) {
        float v[8];
        #pragma unroll
        for (int i = 0; i < 8; i++) v[i] = in[(size_t)(t0 + i) * CHAN + c];
        #pragma unroll
        for (int i = 0; i < 8; i++) {
            acc = fmaf(v[i], scale, acc);
            out[(size_t)(t0 + i) * CHAN + c] = acc;
        }
    }
}

// ---------------------------------------------------------------------------
// TaLK gather/lerp -> bf16 hi/lo split
// ---------------------------------------------------------------------------
__global__ __launch_bounds__(256) void talk_split_kernel(
    const float* __restrict__ S, const float* __restrict__ alpha,
    __nv_bfloat16* __restrict__ oh, __nv_bfloat16* __restrict__ ol)
{
    const size_t e = ((size_t)blockIdx.x * blockDim.x + threadIdx.x) << 2;
    const int t = (int)(e >> 13);
    const int col = (int)(e & 8191);
    const int bh = col >> 6;

    const float al = alpha[(size_t)t * BH_DIM + bh];
    const float eff = fminf(31.f, (float)t);
    const float pos = (float)t - 1.f - al * eff;
    const float i0f = floorf(pos);
    const float frac = pos - i0f;
    const int i0 = (int)i0f;
    const int c0 = max(i0, 0);
    const int c1 = i0 + 1;

    const float4 s  = *(const float4*)(S + (size_t)t  * CHAN + col);
    float4 v0       = *(const float4*)(S + (size_t)c0 * CHAN + col);
    const float4 v1 = *(const float4*)(S + (size_t)c1 * CHAN + col);
    if (i0 < 0) { v0.x = 0.f; v0.y = 0.f; v0.z = 0.f; v0.w = 0.f; }

    float o[4];
    o[0] = s.x - (v0.x + frac * (v1.x - v0.x));
    o[1] = s.y - (v0.y + frac * (v1.y - v0.y));
    o[2] = s.z - (v0.z + frac * (v1.z - v0.z));
    o[3] = s.w - (v0.w + frac * (v1.w - v0.w));

    __nv_bfloat16 h0 = __float2bfloat16(o[0]), h1 = __float2bfloat16(o[1]);
    __nv_bfloat16 h2 = __float2bfloat16(o[2]), h3 = __float2bfloat16(o[3]);
    __nv_bfloat162 p;
    p.x = h0; p.y = h1; *(__nv_bfloat162*)(oh + e) = p;
    p.x = h2; p.y = h3; *(__nv_bfloat162*)(oh + e + 2) = p;
    p.x = __float2bfloat16(o[0] - __bfloat162float(h0));
    p.y = __float2bfloat16(o[1] - __bfloat162float(h1));
    *(__nv_bfloat162*)(ol + e) = p;
    p.x = __float2bfloat16(o[2] - __bfloat162float(h2));
    p.y = __float2bfloat16(o[3] - __bfloat162float(h3));
    *(__nv_bfloat162*)(ol + e + 2) = p;
}

// ---------------------------------------------------------------------------
// Launch
// ---------------------------------------------------------------------------
extern "C" void kernel_launch(void* const* d_in, const int* in_sizes, int n_in,
                              void* d_out, int out_size)
{
    const float* x    = (const float*)d_in[0];
    const float* W1   = (const float*)d_in[4];
    const float* b1   = (const float*)d_in[5];
    const float* Woff = (const float*)d_in[6];
    const float* boff = (const float*)d_in[7];
    const float* W2   = (const float*)d_in[8];
    const float* b2   = (const float*)d_in[9];
    const float* Wf1  = (const float*)d_in[10];
    const float* bf1  = (const float*)d_in[11];
    const float* Wf2  = (const float*)d_in[12];
    const float* bf2  = (const float*)d_in[13];
    const float* gcv  = (const float*)d_in[14];
    const float* bcv  = (const float*)d_in[15];
    const float* gfn  = (const float*)d_in[16];
    const float* bfn  = (const float*)d_in[17];

    __nv_bfloat16 *Ahp, *Alp, *Mhp, *Mlp;
    __nv_bfloat16 *W1h, *W1l, *W2h, *W2l, *Wf1h, *Wf1l, *Wf2h, *Wf2l;
    float *glu, *S, *y, *alpha, *part;
    cudaGetSymbolAddress((void**)&Ahp, g_Ah);   cudaGetSymbolAddress((void**)&Alp, g_Al);
    cudaGetSymbolAddress((void**)&Mhp, g_Mh);   cudaGetSymbolAddress((void**)&Mlp, g_Ml);
    cudaGetSymbolAddress((void**)&W1h, g_W1h);  cudaGetSymbolAddress((void**)&W1l, g_W1l);
    cudaGetSymbolAddress((void**)&W2h, g_W2h);  cudaGetSymbolAddress((void**)&W2l, g_W2l);
    cudaGetSymbolAddress((void**)&Wf1h, g_Wf1h); cudaGetSymbolAddress((void**)&Wf1l, g_Wf1l);
    cudaGetSymbolAddress((void**)&Wf2h, g_Wf2h); cudaGetSymbolAddress((void**)&Wf2l, g_Wf2l);
    cudaGetSymbolAddress((void**)&glu, g_glu);
    cudaGetSymbolAddress((void**)&S, g_S);      cudaGetSymbolAddress((void**)&y, g_y);
    cudaGetSymbolAddress((void**)&alpha, g_alpha);
    cudaGetSymbolAddress((void**)&part, g_part);

    cudaFuncSetAttribute(gemm_mma<1>, cudaFuncAttributeMaxDynamicSharedMemorySize, GEMM_SMEM);
    cudaFuncSetAttribute(gemm_mma<2>, cudaFuncAttributeMaxDynamicSharedMemorySize, GEMM_SMEM);
    cudaFuncSetAttribute(gemm_mma<3>, cudaFuncAttributeMaxDynamicSharedMemorySize, GEMM_SMEM);
    cudaFuncSetAttribute(alpha_kernel, cudaFuncAttributeMaxDynamicSharedMemorySize, 65536);

    const dim3 tb(32, 8);
    wsplit_perm_kernel<<<dim3(2048 / 32, 1024 / 32), tb>>>(W1, W1h, W1l);
    wsplit_kernel<<<dim3(1024 / 32, 1024 / 32), tb>>>(W2,  W2h,  W2l,  1024, 1024);
    wsplit_kernel<<<dim3(4096 / 32, 1024 / 32), tb>>>(Wf1, Wf1h, Wf1l, 1024, 4096);
    wsplit_kernel<<<dim3(1024 / 32, 4096 / 32), tb>>>(Wf2, Wf2h, Wf2l, 4096, 1024);

    const int ew_blocks = (M_TOK * 1024 / 4) / 256;

    // conv block
    ln_split_kernel<<<M_TOK, 256>>>(x, Ahp, Alp, gcv, bcv);
    gemm_mma<3><<<dim3(16, 256), 256, GEMM_SMEM>>>(
        Ahp, Alp, W1h, W1l, b1, nullptr, glu, nullptr, nullptr, M_TOK, 2048, 1024);
    alpha_kernel<<<M_TOK / 8, 256, 65536>>>(glu, Woff, boff, alpha);
    cumsum_part<<<dim3(CHAN / 256, 8), 256>>>(glu, part);
    cumsum_scan<<<dim3(CHAN / 256, 8), 256>>>(glu, part, S);
    talk_split_kernel<<<ew_blocks, 256>>>(S, alpha, Ahp, Alp);
    gemm_mma<2><<<dim3(8, 256), 256, GEMM_SMEM>>>(
        Ahp, Alp, W2h, W2l, b2, x, y, nullptr, nullptr, M_TOK, 1024, 1024);

    // FFN block
    ln_split_kernel<<<M_TOK, 256>>>(y, Ahp, Alp, gfn, bfn);
    gemm_mma<1><<<dim3(32, 256), 256, GEMM_SMEM>>>(
        Ahp, Alp, Wf1h, Wf1l, bf1, nullptr, nullptr, Mhp, Mlp, M_TOK, 4096, 1024);
    gemm_mma<2><<<dim3(8, 256), 256, GEMM_SMEM>>>(
        Mhp, Mlp, Wf2h, Wf2l, bf2, y, (float*)d_out, nullptr, nullptr, M_TOK, 1024, 4096);
}

// round 6
// speedup vs baseline: 3.1340x; 1.0121x over previous
#include <cuda_runtime.h>
#include <cuda_bf16.h>
#include <stdint.h>
#include <math.h>

#define T_DIM   4096
#define B_DIM   8
#define M_TOK   32768
#define CHAN    8192
#define BH_DIM  128

// ---------------------------------------------------------------------------
// Device-global scratch
// ---------------------------------------------------------------------------
__device__ __nv_bfloat16 g_Ah [M_TOK * 1024];
__device__ __nv_bfloat16 g_Al [M_TOK * 1024];
__device__ __nv_bfloat16 g_Mh [M_TOK * 4096];
__device__ __nv_bfloat16 g_Ml [M_TOK * 4096];
__device__ __nv_bfloat16 g_W1h[2048 * 1024], g_W1l[2048 * 1024];   // permuted (a/gate interleaved)
__device__ __nv_bfloat16 g_W2h[1024 * 1024], g_W2l[1024 * 1024];
__device__ __nv_bfloat16 g_Wf1h[4096 * 1024], g_Wf1l[4096 * 1024];
__device__ __nv_bfloat16 g_Wf2h[1024 * 4096], g_Wf2l[1024 * 4096];
__device__ float g_glu [M_TOK * 1024];
__device__ float g_S   [M_TOK * 1024];
__device__ float g_y   [M_TOK * 1024];
__device__ float g_alpha[T_DIM * BH_DIM];
__device__ float g_part[8 * CHAN];

__device__ __forceinline__ float sigmoidf_(float v) { return 1.f / (1.f + __expf(-v)); }

__device__ __forceinline__ uint32_t smem_addr_of(const void* p) {
    uint32_t a;
    asm("{ .reg .u64 t; cvta.to.shared.u64 t, %1; cvt.u32.u64 %0, t; }" : "=r"(a) : "l"(p));
    return a;
}
__device__ __forceinline__ void ldsm4(uint32_t* r, uint32_t addr) {
    asm volatile("ldmatrix.sync.aligned.m8n8.x4.shared.b16 {%0,%1,%2,%3}, [%4];"
                 : "=r"(r[0]), "=r"(r[1]), "=r"(r[2]), "=r"(r[3]) : "r"(addr));
}
__device__ __forceinline__ void mma16816(float* d, const uint32_t* a, const uint32_t* b) {
    asm volatile("mma.sync.aligned.m16n8k16.row.col.f32.bf16.bf16.f32 "
                 "{%0,%1,%2,%3}, {%4,%5,%6,%7}, {%8,%9}, {%0,%1,%2,%3};"
                 : "+f"(d[0]), "+f"(d[1]), "+f"(d[2]), "+f"(d[3])
                 : "r"(a[0]), "r"(a[1]), "r"(a[2]), "r"(a[3]), "r"(b[0]), "r"(b[1]));
}
__device__ __forceinline__ void cpa16(uint32_t s, const void* g) {
    asm volatile("cp.async.cg.shared.global [%0], [%1], 16;" :: "r"(s), "l"(g));
}
__device__ __forceinline__ void cpa_commit() {
    asm volatile("cp.async.commit_group;" ::: "memory");
}
__device__ __forceinline__ void cpa_wait1() {
    asm volatile("cp.async.wait_group 1;" ::: "memory");
}

// ---------------------------------------------------------------------------
// bf16 hi/lo emulated fp32 GEMM on mma.sync.
// CTA 128x128, 8 warps (64x32), BK=32, 3-stage cp.async ring, swizzled 64B
// rows -> 96KB smem -> 2 CTAs/SM. K is compile-time.
// EPI: 1 = +bias, swish -> bf16 hi/lo ; 2 = +bias + residual -> fp32 ;
//      3 = GLU (paired cols a/gate) +bias -> fp32 glu [M, N/2]
// ---------------------------------------------------------------------------
#define TILE_B  8192
#define STAGE_B 32768
#define GEMM_SMEM (3 * STAGE_B)

template<int EPI, int K>
__global__ __launch_bounds__(256, 2) void gemm_mma(
    const __nv_bfloat16* __restrict__ Ah, const __nv_bfloat16* __restrict__ Al,
    const __nv_bfloat16* __restrict__ Bh, const __nv_bfloat16* __restrict__ Bl,
    const float* __restrict__ bias, const float* __restrict__ res,
    float* __restrict__ C, __nv_bfloat16* __restrict__ Ch, __nv_bfloat16* __restrict__ Cl,
    int M, int N)
{
    extern __shared__ __align__(1024) char smem[];
    const uint32_t sb = smem_addr_of(smem);
    const int tid = threadIdx.x, wid = tid >> 5, lane = tid & 31;
    const int wm = wid & 1, wn = wid >> 1;
    const int m0 = blockIdx.y << 7, n0 = blockIdx.x << 7;

    const __nv_bfloat16* gt[4] = {
        Ah + (size_t)m0 * K, Al + (size_t)m0 * K,
        Bh + (size_t)n0 * K, Bl + (size_t)n0 * K };

    const int ldr = tid >> 2;
    const int ldc = tid & 3;
    const uint32_t dstoff = (uint32_t)ldr * 64 + ((ldc ^ ((ldr >> 1) & 3)) << 4);
    const uint32_t dstoff2 = dstoff + 64 * 64;   // row +64 keeps same swizzle phase

    auto load_stage = [&](uint32_t sbase, int chunk) {
        const int k0 = chunk << 5;
        #pragma unroll
        for (int t = 0; t < 4; t++) {
            const __nv_bfloat16* g = gt[t] + (size_t)ldr * K + k0 + (ldc << 3);
            cpa16(sbase + t * TILE_B + dstoff,  g);
            cpa16(sbase + t * TILE_B + dstoff2, g + (size_t)64 * K);
        }
    };

    float acc[4][4][4];
    #pragma unroll
    for (int a = 0; a < 4; a++)
        #pragma unroll
        for (int b = 0; b < 4; b++)
            #pragma unroll
            for (int k = 0; k < 4; k++) acc[a][b][k] = 0.f;

    constexpr int NC = K >> 5;
    uint32_t st0 = sb, st1 = sb + STAGE_B, st2 = sb + 2 * STAGE_B;
    load_stage(st0, 0); cpa_commit();
    load_stage(st1, 1); cpa_commit();

    const int ar = (wm << 6) + (lane & 15);
    const uint32_t aRow = (uint32_t)ar * 64;
    const int ax = (ar >> 1) & 3;
    const int ahalf = lane >> 4;
    const int br = (wn << 5) + ((lane & 7) | ((lane & 16) >> 1));
    const uint32_t bRow = (uint32_t)br * 64;
    const int bx = (br >> 1) & 3;
    const int bhalf = (lane >> 3) & 1;

    #pragma unroll 1
    for (int c = 0; c < NC; c++) {
        cpa_wait1();
        __syncthreads();
        if (c + 2 < NC) load_stage(st2, c + 2);
        cpa_commit();

        const uint32_t aH = st0 + aRow;
        const uint32_t bH = st0 + 2 * TILE_B + bRow;

        #pragma unroll
        for (int kk = 0; kk < 2; kk++) {
            const uint32_t acol = (uint32_t)(((kk << 1) + ahalf) ^ ax) << 4;
            const uint32_t bcol = (uint32_t)(((kk << 1) + bhalf) ^ bx) << 4;
            uint32_t bh[2][4], bl[2][4];
            #pragma unroll
            for (int f2 = 0; f2 < 2; f2++) {
                ldsm4(bh[f2], bH + f2 * 1024 + bcol);
                ldsm4(bl[f2], bH + TILE_B + f2 * 1024 + bcol);
            }
            #pragma unroll
            for (int fm = 0; fm < 4; fm++) {
                uint32_t a_h[4], a_l[4];
                ldsm4(a_h, aH + fm * 1024 + acol);
                ldsm4(a_l, aH + TILE_B + fm * 1024 + acol);
                // term-grouped: breaks same-acc RAW chains into 4-wide groups
                #pragma unroll
                for (int fn = 0; fn < 4; fn++)
                    mma16816(acc[fm][fn], a_h, &bh[fn >> 1][(fn & 1) << 1]);
                #pragma unroll
                for (int fn = 0; fn < 4; fn++)
                    mma16816(acc[fm][fn], a_h, &bl[fn >> 1][(fn & 1) << 1]);
                #pragma unroll
                for (int fn = 0; fn < 4; fn++)
                    mma16816(acc[fm][fn], a_l, &bh[fn >> 1][(fn & 1) << 1]);
            }
        }
        // rotate stages: compute st0 -> becomes far stage
        const uint32_t t = st0; st0 = st1; st1 = st2; st2 = t;
    }

    // ---- epilogue ----
    const int mB = m0 + (wm << 6) + (lane >> 2);
    const int nB = n0 + (wn << 5) + ((lane & 3) << 1);
    #pragma unroll
    for (int fm = 0; fm < 4; fm++) {
        const int r0 = mB + (fm << 4);
        #pragma unroll
        for (int fn = 0; fn < 4; fn++) {
            const int cc = nB + (fn << 3);
            if (EPI == 3) {
                const int j = cc >> 1;
                const float ba = __ldg(bias + j);
                const float bg = __ldg(bias + 1024 + j);
                const float a0 = acc[fm][fn][0] + ba, gg0 = acc[fm][fn][1] + bg;
                const float a1 = acc[fm][fn][2] + ba, gg1 = acc[fm][fn][3] + bg;
                C[(size_t)r0 * (N >> 1) + j]       = a0 * sigmoidf_(gg0);
                C[(size_t)(r0 + 8) * (N >> 1) + j] = a1 * sigmoidf_(gg1);
            } else {
                const float2 bv = __ldg((const float2*)(bias + cc));
                float v0 = acc[fm][fn][0] + bv.x;
                float v1 = acc[fm][fn][1] + bv.y;
                float v2 = acc[fm][fn][2] + bv.x;
                float v3 = acc[fm][fn][3] + bv.y;
                const size_t o0 = (size_t)r0 * N + cc;
                const size_t o1 = (size_t)(r0 + 8) * N + cc;
                if (EPI == 1) {
                    v0 = v0 * sigmoidf_(v0); v1 = v1 * sigmoidf_(v1);
                    v2 = v2 * sigmoidf_(v2); v3 = v3 * sigmoidf_(v3);
                    __nv_bfloat16 h0 = __float2bfloat16(v0), h1 = __float2bfloat16(v1);
                    __nv_bfloat16 h2 = __float2bfloat16(v2), h3 = __float2bfloat16(v3);
                    __nv_bfloat162 p;
                    p.x = h0; p.y = h1; *(__nv_bfloat162*)(Ch + o0) = p;
                    p.x = h2; p.y = h3; *(__nv_bfloat162*)(Ch + o1) = p;
                    p.x = __float2bfloat16(v0 - __bfloat162float(h0));
                    p.y = __float2bfloat16(v1 - __bfloat162float(h1));
                    *(__nv_bfloat162*)(Cl + o0) = p;
                    p.x = __float2bfloat16(v2 - __bfloat162float(h2));
                    p.y = __float2bfloat16(v3 - __bfloat162float(h3));
                    *(__nv_bfloat162*)(Cl + o1) = p;
                } else {
                    const float2 ra = __ldg((const float2*)(res + o0));
                    const float2 rb = __ldg((const float2*)(res + o1));
                    v0 += ra.x; v1 += ra.y; v2 += rb.x; v3 += rb.y;
                    float2 q;
                    q.x = v0; q.y = v1; *(float2*)(C + o0) = q;
                    q.x = v2; q.y = v3; *(float2*)(C + o1) = q;
                }
            }
        }
    }
}

// ---------------------------------------------------------------------------
// Weight split + transpose: W[K,N] fp32 -> Wh,Wl [N,K] bf16
// ---------------------------------------------------------------------------
__global__ __launch_bounds__(256) void wsplit_kernel(
    const float* __restrict__ W, __nv_bfloat16* __restrict__ Wh,
    __nv_bfloat16* __restrict__ Wl, int K, int N)
{
    __shared__ float tile[32][33];
    const int n0 = blockIdx.x << 5;
    const int k0 = blockIdx.y << 5;
    for (int i = threadIdx.y; i < 32; i += 8)
        tile[i][threadIdx.x] = W[(size_t)(k0 + i) * N + n0 + threadIdx.x];
    __syncthreads();
    for (int i = threadIdx.y; i < 32; i += 8) {
        const float v = tile[threadIdx.x][i];
        const __nv_bfloat16 h = __float2bfloat16(v);
        const size_t o = (size_t)(n0 + i) * K + k0 + threadIdx.x;
        Wh[o] = h;
        Wl[o] = __float2bfloat16(v - __bfloat162float(h));
    }
}

// W1 permuted: out row 2j = src col j (a), out row 2j+1 = src col 1024+j (gate)
__global__ __launch_bounds__(256) void wsplit_perm_kernel(
    const float* __restrict__ W, __nv_bfloat16* __restrict__ Wh,
    __nv_bfloat16* __restrict__ Wl)
{
    __shared__ float tile[32][33];
    const int n0 = blockIdx.x << 5;
    const int k0 = blockIdx.y << 5;
    const int tx = threadIdx.x;
    const int orow = n0 + tx;
    const int scol = (orow & 1) ? (1024 + (orow >> 1)) : (orow >> 1);
    for (int i = threadIdx.y; i < 32; i += 8)
        tile[i][tx] = W[(size_t)(k0 + i) * 2048 + scol];
    __syncthreads();
    for (int i = threadIdx.y; i < 32; i += 8) {
        const float v = tile[tx][i];
        const __nv_bfloat16 h = __float2bfloat16(v);
        const size_t o = (size_t)(n0 + i) * 1024 + k0 + tx;
        Wh[o] = h;
        Wl[o] = __float2bfloat16(v - __bfloat162float(h));
    }
}

// ---------------------------------------------------------------------------
// LayerNorm -> bf16 hi/lo split
// ---------------------------------------------------------------------------
__device__ __forceinline__ float block_sum256(float v, float* sh) {
    #pragma unroll
    for (int o = 16; o > 0; o >>= 1) v += __shfl_xor_sync(0xffffffffu, v, o);
    if ((threadIdx.x & 31) == 0) sh[threadIdx.x >> 5] = v;
    __syncthreads();
    float tot = 0.f;
    #pragma unroll
    for (int i = 0; i < 8; i++) tot += sh[i];
    __syncthreads();
    return tot;
}

__global__ __launch_bounds__(256) void ln_split_kernel(
    const float* __restrict__ in, __nv_bfloat16* __restrict__ oh,
    __nv_bfloat16* __restrict__ ol,
    const float* __restrict__ gw, const float* __restrict__ bw)
{
    __shared__ float sh[8];
    const size_t row = blockIdx.x;
    const float4 v = ((const float4*)(in + row * 1024))[threadIdx.x];

    float s = v.x + v.y + v.z + v.w;
    s = block_sum256(s, sh);
    const float mean = s * (1.f / 1024.f);
    const float dx = v.x - mean, dy = v.y - mean, dz = v.z - mean, dw = v.w - mean;
    float q = dx * dx + dy * dy + dz * dz + dw * dw;
    q = block_sum256(q, sh);
    const float rstd = rsqrtf(q * (1.f / 1024.f) + 1e-5f);

    const float4 g4 = ((const float4*)gw)[threadIdx.x];
    const float4 b4 = ((const float4*)bw)[threadIdx.x];
    float o[4];
    o[0] = dx * rstd * g4.x + b4.x;
    o[1] = dy * rstd * g4.y + b4.y;
    o[2] = dz * rstd * g4.z + b4.z;
    o[3] = dw * rstd * g4.w + b4.w;

    const size_t base = row * 1024 + (size_t)threadIdx.x * 4;
    __nv_bfloat16 h0 = __float2bfloat16(o[0]), h1 = __float2bfloat16(o[1]);
    __nv_bfloat16 h2 = __float2bfloat16(o[2]), h3 = __float2bfloat16(o[3]);
    __nv_bfloat162 p;
    p.x = h0; p.y = h1; *(__nv_bfloat162*)(oh + base) = p;
    p.x = h2; p.y = h3; *(__nv_bfloat162*)(oh + base + 2) = p;
    p.x = __float2bfloat16(o[0] - __bfloat162float(h0));
    p.y = __float2bfloat16(o[1] - __bfloat162float(h1));
    *(__nv_bfloat162*)(ol + base) = p;
    p.x = __float2bfloat16(o[2] - __bfloat162float(h2));
    p.y = __float2bfloat16(o[3] - __bfloat162float(h3));
    *(__nv_bfloat162*)(ol + base + 2) = p;
}

// ---------------------------------------------------------------------------
// alpha = sigmoid(glu @ W_off + b_off). Warp per row, W_off transposed in
// smem Ws[n][k]. 8 rows per block.
// ---------------------------------------------------------------------------
__global__ __launch_bounds__(256) void alpha_kernel(
    const float* __restrict__ g, const float* __restrict__ Woff,
    const float* __restrict__ boff, float* __restrict__ alpha)
{
    extern __shared__ float Ws[];   // [16][1024]
    for (int k = threadIdx.x; k < 1024; k += 256) {
        const float4 w0 = __ldg((const float4*)(Woff + (size_t)k * 16));
        const float4 w1 = __ldg((const float4*)(Woff + (size_t)k * 16 + 4));
        const float4 w2 = __ldg((const float4*)(Woff + (size_t)k * 16 + 8));
        const float4 w3 = __ldg((const float4*)(Woff + (size_t)k * 16 + 12));
        Ws[0 * 1024 + k] = w0.x; Ws[1 * 1024 + k] = w0.y;
        Ws[2 * 1024 + k] = w0.z; Ws[3 * 1024 + k] = w0.w;
        Ws[4 * 1024 + k] = w1.x; Ws[5 * 1024 + k] = w1.y;
        Ws[6 * 1024 + k] = w1.z; Ws[7 * 1024 + k] = w1.w;
        Ws[8 * 1024 + k] = w2.x; Ws[9 * 1024 + k] = w2.y;
        Ws[10 * 1024 + k] = w2.z; Ws[11 * 1024 + k] = w2.w;
        Ws[12 * 1024 + k] = w3.x; Ws[13 * 1024 + k] = w3.y;
        Ws[14 * 1024 + k] = w3.z; Ws[15 * 1024 + k] = w3.w;
    }
    __syncthreads();

    const int wid = threadIdx.x >> 5, lane = threadIdx.x & 31;
    const int row = blockIdx.x * 8 + wid;
    const float* gr = g + (size_t)row * 1024;

    float acc[16];
    #pragma unroll
    for (int n = 0; n < 16; n++) acc[n] = 0.f;

    #pragma unroll
    for (int j = 0; j < 8; j++) {
        const int k = (lane << 2) + (j << 7);
        const float4 v = *(const float4*)(gr + k);
        #pragma unroll
        for (int n = 0; n < 16; n++) {
            const float4 w = *(const float4*)(Ws + n * 1024 + k);
            acc[n] += v.x * w.x + v.y * w.y + v.z * w.z + v.w * w.w;
        }
    }
    #pragma unroll
    for (int o = 16; o > 0; o >>= 1)
        #pragma unroll
        for (int n = 0; n < 16; n++)
            acc[n] += __shfl_xor_sync(0xffffffffu, acc[n], o);

    if (lane < 16) {
        const int t = row >> 3, b = row & 7;
        alpha[(size_t)t * BH_DIM + b * 16 + lane] =
            sigmoidf_(acc[lane] + __ldg(boff + lane));
    }
}

// ---------------------------------------------------------------------------
// Segmented cumsum over time (scale 1/32)
// ---------------------------------------------------------------------------
__global__ __launch_bounds__(256) void cumsum_part(
    const float* __restrict__ in, float* __restrict__ part)
{
    const int c = blockIdx.x * 256 + threadIdx.x;
    const int s = blockIdx.y;
    float acc = 0.f;
    for (int t0 = s * 512; t0 < (s + 1) * 512; t0 += 8) {
        float v[8];
        #pragma unroll
        for (int i = 0; i < 8; i++) v[i] = in[(size_t)(t0 + i) * CHAN + c];
        #pragma unroll
        for (int i = 0; i < 8; i++) acc += v[i];
    }
    part[s * CHAN + c] = acc;
}

__global__ __launch_bounds__(256) void cumsum_scan(
    const float* __restrict__ in, const float* __restrict__ part,
    float* __restrict__ out)
{
    const int c = blockIdx.x * 256 + threadIdx.x;
    const int s = blockIdx.y;
    const float scale = 1.f / 32.f;
    float acc = 0.f;
    for (int p = 0; p < s; p++) acc += part[p * CHAN + c];
    acc *= scale;
    for (int t0 = s * 512; t0 < (s + 1) * 512; t0 += 8) {
        float v[8];
        #pragma unroll
        for (int i = 0; i < 8; i++) v[i] = in[(size_t)(t0 + i) * CHAN + c];
        #pragma unroll
        for (int i = 0; i < 8; i++) {
            acc = fmaf(v[i], scale, acc);
            out[(size_t)(t0 + i) * CHAN + c] = acc;
        }
    }
}

// ---------------------------------------------------------------------------
// TaLK gather/lerp -> bf16 hi/lo split
// ---------------------------------------------------------------------------
__global__ __launch_bounds__(256) void talk_split_kernel(
    const float* __restrict__ S, const float* __restrict__ alpha,
    __nv_bfloat16* __restrict__ oh, __nv_bfloat16* __restrict__ ol)
{
    const size_t e = ((size_t)blockIdx.x * blockDim.x + threadIdx.x) << 2;
    const int t = (int)(e >> 13);
    const int col = (int)(e & 8191);
    const int bh = col >> 6;

    const float al = alpha[(size_t)t * BH_DIM + bh];
    const float eff = fminf(31.f, (float)t);
    const float pos = (float)t - 1.f - al * eff;
    const float i0f = floorf(pos);
    const float frac = pos - i0f;
    const int i0 = (int)i0f;
    const int c0 = max(i0, 0);
    const int c1 = i0 + 1;

    const float4 s  = *(const float4*)(S + (size_t)t  * CHAN + col);
    float4 v0       = *(const float4*)(S + (size_t)c0 * CHAN + col);
    const float4 v1 = *(const float4*)(S + (size_t)c1 * CHAN + col);
    if (i0 < 0) { v0.x = 0.f; v0.y = 0.f; v0.z = 0.f; v0.w = 0.f; }

    float o[4];
    o[0] = s.x - (v0.x + frac * (v1.x - v0.x));
    o[1] = s.y - (v0.y + frac * (v1.y - v0.y));
    o[2] = s.z - (v0.z + frac * (v1.z - v0.z));
    o[3] = s.w - (v0.w + frac * (v1.w - v0.w));

    __nv_bfloat16 h0 = __float2bfloat16(o[0]), h1 = __float2bfloat16(o[1]);
    __nv_bfloat16 h2 = __float2bfloat16(o[2]), h3 = __float2bfloat16(o[3]);
    __nv_bfloat162 p;
    p.x = h0; p.y = h1; *(__nv_bfloat162*)(oh + e) = p;
    p.x = h2; p.y = h3; *(__nv_bfloat162*)(oh + e + 2) = p;
    p.x = __float2bfloat16(o[0] - __bfloat162float(h0));
    p.y = __float2bfloat16(o[1] - __bfloat162float(h1));
    *(__nv_bfloat162*)(ol + e) = p;
    p.x = __float2bfloat16(o[2] - __bfloat162float(h2));
    p.y = __float2bfloat16(o[3] - __bfloat162float(h3));
    *(__nv_bfloat162*)(ol + e + 2) = p;
}

// ---------------------------------------------------------------------------
// Launch
// ---------------------------------------------------------------------------
extern "C" void kernel_launch(void* const* d_in, const int* in_sizes, int n_in,
                              void* d_out, int out_size)
{
    const float* x    = (const float*)d_in[0];
    const float* W1   = (const float*)d_in[4];
    const float* b1   = (const float*)d_in[5];
    const float* Woff = (const float*)d_in[6];
    const float* boff = (const float*)d_in[7];
    const float* W2   = (const float*)d_in[8];
    const float* b2   = (const float*)d_in[9];
    const float* Wf1  = (const float*)d_in[10];
    const float* bf1  = (const float*)d_in[11];
    const float* Wf2  = (const float*)d_in[12];
    const float* bf2  = (const float*)d_in[13];
    const float* gcv  = (const float*)d_in[14];
    const float* bcv  = (const float*)d_in[15];
    const float* gfn  = (const float*)d_in[16];
    const float* bfn  = (const float*)d_in[17];

    __nv_bfloat16 *Ahp, *Alp, *Mhp, *Mlp;
    __nv_bfloat16 *W1h, *W1l, *W2h, *W2l, *Wf1h, *Wf1l, *Wf2h, *Wf2l;
    float *glu, *S, *y, *alpha, *part;
    cudaGetSymbolAddress((void**)&Ahp, g_Ah);   cudaGetSymbolAddress((void**)&Alp, g_Al);
    cudaGetSymbolAddress((void**)&Mhp, g_Mh);   cudaGetSymbolAddress((void**)&Mlp, g_Ml);
    cudaGetSymbolAddress((void**)&W1h, g_W1h);  cudaGetSymbolAddress((void**)&W1l, g_W1l);
    cudaGetSymbolAddress((void**)&W2h, g_W2h);  cudaGetSymbolAddress((void**)&W2l, g_W2l);
    cudaGetSymbolAddress((void**)&Wf1h, g_Wf1h); cudaGetSymbolAddress((void**)&Wf1l, g_Wf1l);
    cudaGetSymbolAddress((void**)&Wf2h, g_Wf2h); cudaGetSymbolAddress((void**)&Wf2l, g_Wf2l);
    cudaGetSymbolAddress((void**)&glu, g_glu);
    cudaGetSymbolAddress((void**)&S, g_S);      cudaGetSymbolAddress((void**)&y, g_y);
    cudaGetSymbolAddress((void**)&alpha, g_alpha);
    cudaGetSymbolAddress((void**)&part, g_part);

    cudaFuncSetAttribute((const void*)gemm_mma<1, 1024>, cudaFuncAttributeMaxDynamicSharedMemorySize, GEMM_SMEM);
    cudaFuncSetAttribute((const void*)gemm_mma<2, 1024>, cudaFuncAttributeMaxDynamicSharedMemorySize, GEMM_SMEM);
    cudaFuncSetAttribute((const void*)gemm_mma<3, 1024>, cudaFuncAttributeMaxDynamicSharedMemorySize, GEMM_SMEM);
    cudaFuncSetAttribute((const void*)gemm_mma<2, 4096>, cudaFuncAttributeMaxDynamicSharedMemorySize, GEMM_SMEM);
    cudaFuncSetAttribute(alpha_kernel, cudaFuncAttributeMaxDynamicSharedMemorySize, 65536);

    const dim3 tb(32, 8);
    wsplit_perm_kernel<<<dim3(2048 / 32, 1024 / 32), tb>>>(W1, W1h, W1l);
    wsplit_kernel<<<dim3(1024 / 32, 1024 / 32), tb>>>(W2,  W2h,  W2l,  1024, 1024);
    wsplit_kernel<<<dim3(4096 / 32, 1024 / 32), tb>>>(Wf1, Wf1h, Wf1l, 1024, 4096);
    wsplit_kernel<<<dim3(1024 / 32, 4096 / 32), tb>>>(Wf2, Wf2h, Wf2l, 4096, 1024);

    const int ew_blocks = (M_TOK * 1024 / 4) / 256;

    // conv block
    ln_split_kernel<<<M_TOK, 256>>>(x, Ahp, Alp, gcv, bcv);
    gemm_mma<3, 1024><<<dim3(16, 256), 256, GEMM_SMEM>>>(
        Ahp, Alp, W1h, W1l, b1, nullptr, glu, nullptr, nullptr, M_TOK, 2048);
    alpha_kernel<<<M_TOK / 8, 256, 65536>>>(glu, Woff, boff, alpha);
    cumsum_part<<<dim3(CHAN / 256, 8), 256>>>(glu, part);
    cumsum_scan<<<dim3(CHAN / 256, 8), 256>>>(glu, part, S);
    talk_split_kernel<<<ew_blocks, 256>>>(S, alpha, Ahp, Alp);
    gemm_mma<2, 1024><<<dim3(8, 256), 256, GEMM_SMEM>>>(
        Ahp, Alp, W2h, W2l, b2, x, y, nullptr, nullptr, M_TOK, 1024);

    // FFN block
    ln_split_kernel<<<M_TOK, 256>>>(y, Ahp, Alp, gfn, bfn);
    gemm_mma<1, 1024><<<dim3(32, 256), 256, GEMM_SMEM>>>(
        Ahp, Alp, Wf1h, Wf1l, bf1, nullptr, nullptr, Mhp, Mlp, M_TOK, 4096);
    gemm_mma<2, 4096><<<dim3(8, 256), 256, GEMM_SMEM>>>(
        Mhp, Mlp, Wf2h, Wf2l, bf2, y, (float*)d_out, nullptr, nullptr, M_TOK, 1024);
}

// round 7
// speedup vs baseline: 4.5842x; 1.4627x over previous
#include <cuda_runtime.h>
#include <cuda_fp16.h>
#include <stdint.h>
#include <math.h>

#define T_DIM   4096
#define B_DIM   8
#define M_TOK   32768
#define CHAN    8192
#define BH_DIM  128

// ---------------------------------------------------------------------------
// Device-global scratch
// ---------------------------------------------------------------------------
__device__ __half g_A  [M_TOK * 1024];                     // fp16 activations
__device__ __half g_M  [M_TOK * 4096];                     // fp16 FFN mid
__device__ __half g_W1h[2048 * 1024], g_W1l[2048 * 1024];  // permuted (a/gate interleaved)
__device__ __half g_W2h[1024 * 1024], g_W2l[1024 * 1024];
__device__ __half g_Wf1h[4096 * 1024], g_Wf1l[4096 * 1024];
__device__ __half g_Wf2h[1024 * 4096], g_Wf2l[1024 * 4096];
__device__ float g_glu [M_TOK * 1024];
__device__ float g_S   [M_TOK * 1024];
__device__ float g_y   [M_TOK * 1024];
__device__ float g_alpha[T_DIM * BH_DIM];
__device__ float g_part[8 * CHAN];

__device__ __forceinline__ float sigmoidf_(float v) { return 1.f / (1.f + __expf(-v)); }

__device__ __forceinline__ uint32_t smem_addr_of(const void* p) {
    uint32_t a;
    asm("{ .reg .u64 t; cvta.to.shared.u64 t, %1; cvt.u32.u64 %0, t; }" : "=r"(a) : "l"(p));
    return a;
}
__device__ __forceinline__ void ldsm4(uint32_t* r, uint32_t addr) {
    asm volatile("ldmatrix.sync.aligned.m8n8.x4.shared.b16 {%0,%1,%2,%3}, [%4];"
                 : "=r"(r[0]), "=r"(r[1]), "=r"(r[2]), "=r"(r[3]) : "r"(addr));
}
__device__ __forceinline__ void mma16816h(float* d, const uint32_t* a, const uint32_t* b) {
    asm volatile("mma.sync.aligned.m16n8k16.row.col.f32.f16.f16.f32 "
                 "{%0,%1,%2,%3}, {%4,%5,%6,%7}, {%8,%9}, {%0,%1,%2,%3};"
                 : "+f"(d[0]), "+f"(d[1]), "+f"(d[2]), "+f"(d[3])
                 : "r"(a[0]), "r"(a[1]), "r"(a[2]), "r"(a[3]), "r"(b[0]), "r"(b[1]));
}
__device__ __forceinline__ void cpa16(uint32_t s, const void* g) {
    asm volatile("cp.async.cg.shared.global [%0], [%1], 16;" :: "r"(s), "l"(g));
}
__device__ __forceinline__ void cpa_commit() {
    asm volatile("cp.async.commit_group;" ::: "memory");
}
__device__ __forceinline__ void cpa_wait1() {
    asm volatile("cp.async.wait_group 1;" ::: "memory");
}

// ---------------------------------------------------------------------------
// Emulated-fp32 GEMM on fp16 mma.sync, asymmetric 2-term:
//   C = A_fp16 @ (Bh + Bl)^T     (A quantized rna; B split hi/lo -> exact)
// CTA 128x128, 8 warps (64x32), BK=32, 3-stage cp.async ring, swizzled 64B
// rows -> 72KB smem -> 2 CTAs/SM. K compile-time.
// EPI: 1 = +bias, swish -> fp16 ; 2 = +bias + residual -> fp32 ;
//      3 = GLU (paired cols a/gate) +bias -> fp32 glu [M, N/2]
// ---------------------------------------------------------------------------
#define TILE_B  8192
#define STAGE_B 24576
#define GEMM_SMEM (3 * STAGE_B)

template<int EPI, int K>
__global__ __launch_bounds__(256, 2) void gemm_mma(
    const __half* __restrict__ A,
    const __half* __restrict__ Bh, const __half* __restrict__ Bl,
    const float* __restrict__ bias, const float* __restrict__ res,
    float* __restrict__ C, __half* __restrict__ Ch,
    int M, int N)
{
    extern __shared__ __align__(1024) char smem[];
    const uint32_t sb = smem_addr_of(smem);
    const int tid = threadIdx.x, wid = tid >> 5, lane = tid & 31;
    const int wm = wid & 1, wn = wid >> 1;
    const int m0 = blockIdx.y << 7, n0 = blockIdx.x << 7;

    const __half* gt[3] = {
        A + (size_t)m0 * K, Bh + (size_t)n0 * K, Bl + (size_t)n0 * K };

    const int ldr = tid >> 2;
    const int ldc = tid & 3;
    const uint32_t dstoff = (uint32_t)ldr * 64 + ((ldc ^ ((ldr >> 1) & 3)) << 4);
    const uint32_t dstoff2 = dstoff + 64 * 64;

    auto load_stage = [&](uint32_t sbase, int chunk) {
        const int k0 = chunk << 5;
        #pragma unroll
        for (int t = 0; t < 3; t++) {
            const __half* g = gt[t] + (size_t)ldr * K + k0 + (ldc << 3);
            cpa16(sbase + t * TILE_B + dstoff,  g);
            cpa16(sbase + t * TILE_B + dstoff2, g + (size_t)64 * K);
        }
    };

    float acc[4][4][4];
    #pragma unroll
    for (int a = 0; a < 4; a++)
        #pragma unroll
        for (int b = 0; b < 4; b++)
            #pragma unroll
            for (int k = 0; k < 4; k++) acc[a][b][k] = 0.f;

    constexpr int NC = K >> 5;
    uint32_t st0 = sb, st1 = sb + STAGE_B, st2 = sb + 2 * STAGE_B;
    load_stage(st0, 0); cpa_commit();
    load_stage(st1, 1); cpa_commit();

    const int ar = (wm << 6) + (lane & 15);
    const uint32_t aRow = (uint32_t)ar * 64;
    const int ax = (ar >> 1) & 3;
    const int ahalf = lane >> 4;
    const int br = (wn << 5) + ((lane & 7) | ((lane & 16) >> 1));
    const uint32_t bRow = (uint32_t)br * 64;
    const int bx = (br >> 1) & 3;
    const int bhalf = (lane >> 3) & 1;

    #pragma unroll 1
    for (int c = 0; c < NC; c++) {
        cpa_wait1();
        __syncthreads();
        if (c + 2 < NC) load_stage(st2, c + 2);
        cpa_commit();

        const uint32_t aH = st0 + aRow;
        const uint32_t bH = st0 + TILE_B + bRow;

        #pragma unroll
        for (int kk = 0; kk < 2; kk++) {
            const uint32_t acol = (uint32_t)(((kk << 1) + ahalf) ^ ax) << 4;
            const uint32_t bcol = (uint32_t)(((kk << 1) + bhalf) ^ bx) << 4;
            uint32_t bh[2][4], bl[2][4];
            #pragma unroll
            for (int f2 = 0; f2 < 2; f2++) {
                ldsm4(bh[f2], bH + f2 * 1024 + bcol);
                ldsm4(bl[f2], bH + TILE_B + f2 * 1024 + bcol);
            }
            #pragma unroll
            for (int fm = 0; fm < 4; fm++) {
                uint32_t a_f[4];
                ldsm4(a_f, aH + fm * 1024 + acol);
                #pragma unroll
                for (int fn = 0; fn < 4; fn++)
                    mma16816h(acc[fm][fn], a_f, &bh[fn >> 1][(fn & 1) << 1]);
                #pragma unroll
                for (int fn = 0; fn < 4; fn++)
                    mma16816h(acc[fm][fn], a_f, &bl[fn >> 1][(fn & 1) << 1]);
            }
        }
        const uint32_t t = st0; st0 = st1; st1 = st2; st2 = t;
    }

    // ---- epilogue ----
    const int mB = m0 + (wm << 6) + (lane >> 2);
    const int nB = n0 + (wn << 5) + ((lane & 3) << 1);
    #pragma unroll
    for (int fm = 0; fm < 4; fm++) {
        const int r0 = mB + (fm << 4);
        #pragma unroll
        for (int fn = 0; fn < 4; fn++) {
            const int cc = nB + (fn << 3);
            if (EPI == 3) {
                const int j = cc >> 1;
                const float ba = __ldg(bias + j);
                const float bg = __ldg(bias + 1024 + j);
                const float a0 = acc[fm][fn][0] + ba, gg0 = acc[fm][fn][1] + bg;
                const float a1 = acc[fm][fn][2] + ba, gg1 = acc[fm][fn][3] + bg;
                C[(size_t)r0 * (N >> 1) + j]       = a0 * sigmoidf_(gg0);
                C[(size_t)(r0 + 8) * (N >> 1) + j] = a1 * sigmoidf_(gg1);
            } else {
                const float2 bv = __ldg((const float2*)(bias + cc));
                float v0 = acc[fm][fn][0] + bv.x;
                float v1 = acc[fm][fn][1] + bv.y;
                float v2 = acc[fm][fn][2] + bv.x;
                float v3 = acc[fm][fn][3] + bv.y;
                const size_t o0 = (size_t)r0 * N + cc;
                const size_t o1 = (size_t)(r0 + 8) * N + cc;
                if (EPI == 1) {
                    v0 = v0 * sigmoidf_(v0); v1 = v1 * sigmoidf_(v1);
                    v2 = v2 * sigmoidf_(v2); v3 = v3 * sigmoidf_(v3);
                    __half2 p;
                    p.x = __float2half_rn(v0); p.y = __float2half_rn(v1);
                    *(__half2*)(Ch + o0) = p;
                    p.x = __float2half_rn(v2); p.y = __float2half_rn(v3);
                    *(__half2*)(Ch + o1) = p;
                } else {
                    const float2 ra = __ldg((const float2*)(res + o0));
                    const float2 rb = __ldg((const float2*)(res + o1));
                    v0 += ra.x; v1 += ra.y; v2 += rb.x; v3 += rb.y;
                    float2 q;
                    q.x = v0; q.y = v1; *(float2*)(C + o0) = q;
                    q.x = v2; q.y = v3; *(float2*)(C + o1) = q;
                }
            }
        }
    }
}

// ---------------------------------------------------------------------------
// Weight split + transpose: W[K,N] fp32 -> Wh,Wl [N,K] fp16 (hi + exact lo)
// ---------------------------------------------------------------------------
__global__ __launch_bounds__(256) void wsplit_kernel(
    const float* __restrict__ W, __half* __restrict__ Wh,
    __half* __restrict__ Wl, int K, int N)
{
    __shared__ float tile[32][33];
    const int n0 = blockIdx.x << 5;
    const int k0 = blockIdx.y << 5;
    for (int i = threadIdx.y; i < 32; i += 8)
        tile[i][threadIdx.x] = W[(size_t)(k0 + i) * N + n0 + threadIdx.x];
    __syncthreads();
    for (int i = threadIdx.y; i < 32; i += 8) {
        const float v = tile[threadIdx.x][i];
        const __half h = __float2half_rn(v);
        const size_t o = (size_t)(n0 + i) * K + k0 + threadIdx.x;
        Wh[o] = h;
        Wl[o] = __float2half_rn(v - __half2float(h));
    }
}

// W1 permuted: out row 2j = src col j (a), out row 2j+1 = src col 1024+j (gate)
__global__ __launch_bounds__(256) void wsplit_perm_kernel(
    const float* __restrict__ W, __half* __restrict__ Wh,
    __half* __restrict__ Wl)
{
    __shared__ float tile[32][33];
    const int n0 = blockIdx.x << 5;
    const int k0 = blockIdx.y << 5;
    const int tx = threadIdx.x;
    const int orow = n0 + tx;
    const int scol = (orow & 1) ? (1024 + (orow >> 1)) : (orow >> 1);
    for (int i = threadIdx.y; i < 32; i += 8)
        tile[i][tx] = W[(size_t)(k0 + i) * 2048 + scol];
    __syncthreads();
    for (int i = threadIdx.y; i < 32; i += 8) {
        const float v = tile[tx][i];
        const __half h = __float2half_rn(v);
        const size_t o = (size_t)(n0 + i) * 1024 + k0 + tx;
        Wh[o] = h;
        Wl[o] = __float2half_rn(v - __half2float(h));
    }
}

// ---------------------------------------------------------------------------
// LayerNorm -> fp16
// ---------------------------------------------------------------------------
__device__ __forceinline__ float block_sum256(float v, float* sh) {
    #pragma unroll
    for (int o = 16; o > 0; o >>= 1) v += __shfl_xor_sync(0xffffffffu, v, o);
    if ((threadIdx.x & 31) == 0) sh[threadIdx.x >> 5] = v;
    __syncthreads();
    float tot = 0.f;
    #pragma unroll
    for (int i = 0; i < 8; i++) tot += sh[i];
    __syncthreads();
    return tot;
}

__global__ __launch_bounds__(256) void ln_h_kernel(
    const float* __restrict__ in, __half* __restrict__ oh,
    const float* __restrict__ gw, const float* __restrict__ bw)
{
    __shared__ float sh[8];
    const size_t row = blockIdx.x;
    const float4 v = ((const float4*)(in + row * 1024))[threadIdx.x];

    float s = v.x + v.y + v.z + v.w;
    s = block_sum256(s, sh);
    const float mean = s * (1.f / 1024.f);
    const float dx = v.x - mean, dy = v.y - mean, dz = v.z - mean, dw = v.w - mean;
    float q = dx * dx + dy * dy + dz * dz + dw * dw;
    q = block_sum256(q, sh);
    const float rstd = rsqrtf(q * (1.f / 1024.f) + 1e-5f);

    const float4 g4 = ((const float4*)gw)[threadIdx.x];
    const float4 b4 = ((const float4*)bw)[threadIdx.x];
    const size_t base = row * 1024 + (size_t)threadIdx.x * 4;
    __half2 p;
    p.x = __float2half_rn(dx * rstd * g4.x + b4.x);
    p.y = __float2half_rn(dy * rstd * g4.y + b4.y);
    *(__half2*)(oh + base) = p;
    p.x = __float2half_rn(dz * rstd * g4.z + b4.z);
    p.y = __float2half_rn(dw * rstd * g4.w + b4.w);
    *(__half2*)(oh + base + 2) = p;
}

// ---------------------------------------------------------------------------
// alpha = sigmoid(glu @ W_off + b_off). Warp per row, W_off transposed in smem.
// ---------------------------------------------------------------------------
__global__ __launch_bounds__(256) void alpha_kernel(
    const float* __restrict__ g, const float* __restrict__ Woff,
    const float* __restrict__ boff, float* __restrict__ alpha)
{
    extern __shared__ float Ws[];   // [16][1024]
    for (int k = threadIdx.x; k < 1024; k += 256) {
        const float4 w0 = __ldg((const float4*)(Woff + (size_t)k * 16));
        const float4 w1 = __ldg((const float4*)(Woff + (size_t)k * 16 + 4));
        const float4 w2 = __ldg((const float4*)(Woff + (size_t)k * 16 + 8));
        const float4 w3 = __ldg((const float4*)(Woff + (size_t)k * 16 + 12));
        Ws[0 * 1024 + k] = w0.x; Ws[1 * 1024 + k] = w0.y;
        Ws[2 * 1024 + k] = w0.z; Ws[3 * 1024 + k] = w0.w;
        Ws[4 * 1024 + k] = w1.x; Ws[5 * 1024 + k] = w1.y;
        Ws[6 * 1024 + k] = w1.z; Ws[7 * 1024 + k] = w1.w;
        Ws[8 * 1024 + k] = w2.x; Ws[9 * 1024 + k] = w2.y;
        Ws[10 * 1024 + k] = w2.z; Ws[11 * 1024 + k] = w2.w;
        Ws[12 * 1024 + k] = w3.x; Ws[13 * 1024 + k] = w3.y;
        Ws[14 * 1024 + k] = w3.z; Ws[15 * 1024 + k] = w3.w;
    }
    __syncthreads();

    const int wid = threadIdx.x >> 5, lane = threadIdx.x & 31;
    const int row = blockIdx.x * 8 + wid;
    const float* gr = g + (size_t)row * 1024;

    float acc[16];
    #pragma unroll
    for (int n = 0; n < 16; n++) acc[n] = 0.f;

    #pragma unroll
    for (int j = 0; j < 8; j++) {
        const int k = (lane << 2) + (j << 7);
        const float4 v = *(const float4*)(gr + k);
        #pragma unroll
        for (int n = 0; n < 16; n++) {
            const float4 w = *(const float4*)(Ws + n * 1024 + k);
            acc[n] += v.x * w.x + v.y * w.y + v.z * w.z + v.w * w.w;
        }
    }
    #pragma unroll
    for (int o = 16; o > 0; o >>= 1)
        #pragma unroll
        for (int n = 0; n < 16; n++)
            acc[n] += __shfl_xor_sync(0xffffffffu, acc[n], o);

    if (lane < 16) {
        const int t = row >> 3, b = row & 7;
        alpha[(size_t)t * BH_DIM + b * 16 + lane] =
            sigmoidf_(acc[lane] + __ldg(boff + lane));
    }
}

// ---------------------------------------------------------------------------
// Segmented cumsum over time (scale 1/32)
// ---------------------------------------------------------------------------
__global__ __launch_bounds__(256) void cumsum_part(
    const float* __restrict__ in, float* __restrict__ part)
{
    const int c = blockIdx.x * 256 + threadIdx.x;
    const int s = blockIdx.y;
    float acc = 0.f;
    for (int t0 = s * 512; t0 < (s + 1) * 512; t0 += 8) {
        float v[8];
        #pragma unroll
        for (int i = 0; i < 8; i++) v[i] = in[(size_t)(t0 + i) * CHAN + c];
        #pragma unroll
        for (int i = 0; i < 8; i++) acc += v[i];
    }
    part[s * CHAN + c] = acc;
}

__global__ __launch_bounds__(256) void cumsum_scan(
    const float* __restrict__ in, const float* __restrict__ part,
    float* __restrict__ out)
{
    const int c = blockIdx.x * 256 + threadIdx.x;
    const int s = blockIdx.y;
    const float scale = 1.f / 32.f;
    float acc = 0.f;
    for (int p = 0; p < s; p++) acc += part[p * CHAN + c];
    acc *= scale;
    for (int t0 = s * 512; t0 < (s + 1) * 512; t0 += 8) {
        float v[8];
        #pragma unroll
        for (int i = 0; i < 8; i++) v[i] = in[(size_t)(t0 + i) * CHAN + c];
        #pragma unroll
        for (int i = 0; i < 8; i++) {
            acc = fmaf(v[i], scale, acc);
            out[(size_t)(t0 + i) * CHAN + c] = acc;
        }
    }
}

// ---------------------------------------------------------------------------
// TaLK gather/lerp -> fp16
// ---------------------------------------------------------------------------
__global__ __launch_bounds__(256) void talk_h_kernel(
    const float* __restrict__ S, const float* __restrict__ alpha,
    __half* __restrict__ oh)
{
    const size_t e = ((size_t)blockIdx.x * blockDim.x + threadIdx.x) << 2;
    const int t = (int)(e >> 13);
    const int col = (int)(e & 8191);
    const int bh = col >> 6;

    const float al = alpha[(size_t)t * BH_DIM + bh];
    const float eff = fminf(31.f, (float)t);
    const float pos = (float)t - 1.f - al * eff;
    const float i0f = floorf(pos);
    const float frac = pos - i0f;
    const int i0 = (int)i0f;
    const int c0 = max(i0, 0);
    const int c1 = i0 + 1;

    const float4 s  = *(const float4*)(S + (size_t)t  * CHAN + col);
    float4 v0       = *(const float4*)(S + (size_t)c0 * CHAN + col);
    const float4 v1 = *(const float4*)(S + (size_t)c1 * CHAN + col);
    if (i0 < 0) { v0.x = 0.f; v0.y = 0.f; v0.z = 0.f; v0.w = 0.f; }

    __half2 p;
    p.x = __float2half_rn(s.x - (v0.x + frac * (v1.x - v0.x)));
    p.y = __float2half_rn(s.y - (v0.y + frac * (v1.y - v0.y)));
    *(__half2*)(oh + e) = p;
    p.x = __float2half_rn(s.z - (v0.z + frac * (v1.z - v0.z)));
    p.y = __float2half_rn(s.w - (v0.w + frac * (v1.w - v0.w)));
    *(__half2*)(oh + e + 2) = p;
}

// ---------------------------------------------------------------------------
// Launch
// ---------------------------------------------------------------------------
extern "C" void kernel_launch(void* const* d_in, const int* in_sizes, int n_in,
                              void* d_out, int out_size)
{
    const float* x    = (const float*)d_in[0];
    const float* W1   = (const float*)d_in[4];
    const float* b1   = (const float*)d_in[5];
    const float* Woff = (const float*)d_in[6];
    const float* boff = (const float*)d_in[7];
    const float* W2   = (const float*)d_in[8];
    const float* b2   = (const float*)d_in[9];
    const float* Wf1  = (const float*)d_in[10];
    const float* bf1  = (const float*)d_in[11];
    const float* Wf2  = (const float*)d_in[12];
    const float* bf2  = (const float*)d_in[13];
    const float* gcv  = (const float*)d_in[14];
    const float* bcv  = (const float*)d_in[15];
    const float* gfn  = (const float*)d_in[16];
    const float* bfn  = (const float*)d_in[17];

    __half *Ap, *Mp;
    __half *W1h, *W1l, *W2h, *W2l, *Wf1h, *Wf1l, *Wf2h, *Wf2l;
    float *glu, *S, *y, *alpha, *part;
    cudaGetSymbolAddress((void**)&Ap, g_A);
    cudaGetSymbolAddress((void**)&Mp, g_M);
    cudaGetSymbolAddress((void**)&W1h, g_W1h);  cudaGetSymbolAddress((void**)&W1l, g_W1l);
    cudaGetSymbolAddress((void**)&W2h, g_W2h);  cudaGetSymbolAddress((void**)&W2l, g_W2l);
    cudaGetSymbolAddress((void**)&Wf1h, g_Wf1h); cudaGetSymbolAddress((void**)&Wf1l, g_Wf1l);
    cudaGetSymbolAddress((void**)&Wf2h, g_Wf2h); cudaGetSymbolAddress((void**)&Wf2l, g_Wf2l);
    cudaGetSymbolAddress((void**)&glu, g_glu);
    cudaGetSymbolAddress((void**)&S, g_S);      cudaGetSymbolAddress((void**)&y, g_y);
    cudaGetSymbolAddress((void**)&alpha, g_alpha);
    cudaGetSymbolAddress((void**)&part, g_part);

    cudaFuncSetAttribute((const void*)gemm_mma<1, 1024>, cudaFuncAttributeMaxDynamicSharedMemorySize, GEMM_SMEM);
    cudaFuncSetAttribute((const void*)gemm_mma<2, 1024>, cudaFuncAttributeMaxDynamicSharedMemorySize, GEMM_SMEM);
    cudaFuncSetAttribute((const void*)gemm_mma<3, 1024>, cudaFuncAttributeMaxDynamicSharedMemorySize, GEMM_SMEM);
    cudaFuncSetAttribute((const void*)gemm_mma<2, 4096>, cudaFuncAttributeMaxDynamicSharedMemorySize, GEMM_SMEM);
    cudaFuncSetAttribute(alpha_kernel, cudaFuncAttributeMaxDynamicSharedMemorySize, 65536);

    const dim3 tb(32, 8);
    wsplit_perm_kernel<<<dim3(2048 / 32, 1024 / 32), tb>>>(W1, W1h, W1l);
    wsplit_kernel<<<dim3(1024 / 32, 1024 / 32), tb>>>(W2,  W2h,  W2l,  1024, 1024);
    wsplit_kernel<<<dim3(4096 / 32, 1024 / 32), tb>>>(Wf1, Wf1h, Wf1l, 1024, 4096);
    wsplit_kernel<<<dim3(1024 / 32, 4096 / 32), tb>>>(Wf2, Wf2h, Wf2l, 4096, 1024);

    const int ew_blocks = (M_TOK * 1024 / 4) / 256;

    // conv block
    ln_h_kernel<<<M_TOK, 256>>>(x, Ap, gcv, bcv);
    gemm_mma<3, 1024><<<dim3(16, 256), 256, GEMM_SMEM>>>(
        Ap, W1h, W1l, b1, nullptr, glu, nullptr, M_TOK, 2048);
    alpha_kernel<<<M_TOK / 8, 256, 65536>>>(glu, Woff, boff, alpha);
    cumsum_part<<<dim3(CHAN / 256, 8), 256>>>(glu, part);
    cumsum_scan<<<dim3(CHAN / 256, 8), 256>>>(glu, part, S);
    talk_h_kernel<<<ew_blocks, 256>>>(S, alpha, Ap);
    gemm_mma<2, 1024><<<dim3(8, 256), 256, GEMM_SMEM>>>(
        Ap, W2h, W2l, b2, x, y, nullptr, M_TOK, 1024);

    // FFN block
    ln_h_kernel<<<M_TOK, 256>>>(y, Ap, gfn, bfn);
    gemm_mma<1, 1024><<<dim3(32, 256), 256, GEMM_SMEM>>>(
        Ap, Wf1h, Wf1l, bf1, nullptr, nullptr, Mp, M_TOK, 4096);
    gemm_mma<2, 4096><<<dim3(8, 256), 256, GEMM_SMEM>>>(
        Mp, Wf2h, Wf2l, bf2, y, (float*)d_out, nullptr, M_TOK, 1024);
}

// round 8
// speedup vs baseline: 6.8070x; 1.4849x over previous
#include <cuda_runtime.h>
#include <cuda_fp16.h>
#include <stdint.h>
#include <math.h>

#define T_DIM   4096
#define B_DIM   8
#define M_TOK   32768
#define CHAN    8192
#define BH_DIM  128

// ---------------------------------------------------------------------------
// Device-global scratch
// ---------------------------------------------------------------------------
__device__ __half g_A  [M_TOK * 1024];                     // fp16 activations
__device__ __half g_M  [M_TOK * 4096];                     // fp16 FFN mid
__device__ __half g_W1 [2048 * 1024];                      // permuted (a/gate interleaved)
__device__ __half g_W2 [1024 * 1024];
__device__ __half g_Wf1[4096 * 1024];
__device__ __half g_Wf2[1024 * 4096];
__device__ float g_glu [M_TOK * 1024];
__device__ float g_S   [M_TOK * 1024];
__device__ float g_y   [M_TOK * 1024];
__device__ float g_alpha[T_DIM * BH_DIM];
__device__ float g_part[8 * CHAN];

__device__ __forceinline__ float sigmoidf_(float v) { return 1.f / (1.f + __expf(-v)); }

__device__ __forceinline__ uint32_t smem_addr_of(const void* p) {
    uint32_t a;
    asm("{ .reg .u64 t; cvta.to.shared.u64 t, %1; cvt.u32.u64 %0, t; }" : "=r"(a) : "l"(p));
    return a;
}
__device__ __forceinline__ void ldsm4(uint32_t* r, uint32_t addr) {
    asm volatile("ldmatrix.sync.aligned.m8n8.x4.shared.b16 {%0,%1,%2,%3}, [%4];"
                 : "=r"(r[0]), "=r"(r[1]), "=r"(r[2]), "=r"(r[3]) : "r"(addr));
}
__device__ __forceinline__ void mma16816h(float* d, const uint32_t* a, const uint32_t* b) {
    asm volatile("mma.sync.aligned.m16n8k16.row.col.f32.f16.f16.f32 "
                 "{%0,%1,%2,%3}, {%4,%5,%6,%7}, {%8,%9}, {%0,%1,%2,%3};"
                 : "+f"(d[0]), "+f"(d[1]), "+f"(d[2]), "+f"(d[3])
                 : "r"(a[0]), "r"(a[1]), "r"(a[2]), "r"(a[3]), "r"(b[0]), "r"(b[1]));
}
__device__ __forceinline__ void cpa16(uint32_t s, const void* g) {
    asm volatile("cp.async.cg.shared.global [%0], [%1], 16;" :: "r"(s), "l"(g));
}
__device__ __forceinline__ void cpa_commit() {
    asm volatile("cp.async.commit_group;" ::: "memory");
}
__device__ __forceinline__ void cpa_wait2() {
    asm volatile("cp.async.wait_group 2;" ::: "memory");
}

// ---------------------------------------------------------------------------
// fp16 GEMM on mma.sync: C = A_fp16 @ B_fp16^T, fp32 accumulate.
// CTA 128x128, 8 warps (64x32), BK=32, 4-stage cp.async ring, swizzled 64B
// rows -> 64KB smem -> 2 CTAs/SM. K compile-time.
// EPI: 1 = +bias, swish -> fp16 ; 2 = +bias + residual -> fp32 ;
//      3 = GLU (paired cols a/gate) +bias -> fp32 glu [M, N/2]
// ---------------------------------------------------------------------------
#define TILE_B  8192
#define STAGE_B 16384
#define GEMM_SMEM (4 * STAGE_B)

template<int EPI, int K>
__global__ __launch_bounds__(256, 2) void gemm_mma(
    const __half* __restrict__ A, const __half* __restrict__ B,
    const float* __restrict__ bias, const float* __restrict__ res,
    float* __restrict__ C, __half* __restrict__ Ch,
    int M, int N)
{
    extern __shared__ __align__(1024) char smem[];
    const uint32_t sb = smem_addr_of(smem);
    const int tid = threadIdx.x, wid = tid >> 5, lane = tid & 31;
    const int wm = wid & 1, wn = wid >> 1;
    const int m0 = blockIdx.y << 7, n0 = blockIdx.x << 7;

    const __half* gA = A + (size_t)m0 * K;
    const __half* gB = B + (size_t)n0 * K;

    const int ldr = tid >> 2;
    const int ldc = tid & 3;
    const uint32_t dstoff = (uint32_t)ldr * 64 + ((ldc ^ ((ldr >> 1) & 3)) << 4);
    const uint32_t dstoff2 = dstoff + 64 * 64;

    auto load_stage = [&](uint32_t sbase, int chunk) {
        const int k0 = chunk << 5;
        const __half* a = gA + (size_t)ldr * K + k0 + (ldc << 3);
        const __half* b = gB + (size_t)ldr * K + k0 + (ldc << 3);
        cpa16(sbase + dstoff,  a);
        cpa16(sbase + dstoff2, a + (size_t)64 * K);
        cpa16(sbase + TILE_B + dstoff,  b);
        cpa16(sbase + TILE_B + dstoff2, b + (size_t)64 * K);
    };

    float acc[4][4][4];
    #pragma unroll
    for (int a = 0; a < 4; a++)
        #pragma unroll
        for (int b = 0; b < 4; b++)
            #pragma unroll
            for (int k = 0; k < 4; k++) acc[a][b][k] = 0.f;

    constexpr int NC = K >> 5;
    uint32_t st0 = sb, st1 = sb + STAGE_B, st2 = sb + 2 * STAGE_B, st3 = sb + 3 * STAGE_B;
    load_stage(st0, 0); cpa_commit();
    load_stage(st1, 1); cpa_commit();
    load_stage(st2, 2); cpa_commit();

    const int ar = (wm << 6) + (lane & 15);
    const uint32_t aRow = (uint32_t)ar * 64;
    const int ax = (ar >> 1) & 3;
    const int ahalf = lane >> 4;
    const int br = (wn << 5) + ((lane & 7) | ((lane & 16) >> 1));
    const uint32_t bRow = (uint32_t)br * 64;
    const int bx = (br >> 1) & 3;
    const int bhalf = (lane >> 3) & 1;

    #pragma unroll 1
    for (int c = 0; c < NC; c++) {
        cpa_wait2();
        __syncthreads();
        if (c + 3 < NC) load_stage(st3, c + 3);
        cpa_commit();

        const uint32_t aH = st0 + aRow;
        const uint32_t bH = st0 + TILE_B + bRow;

        #pragma unroll
        for (int kk = 0; kk < 2; kk++) {
            const uint32_t acol = (uint32_t)(((kk << 1) + ahalf) ^ ax) << 4;
            const uint32_t bcol = (uint32_t)(((kk << 1) + bhalf) ^ bx) << 4;
            uint32_t bh[2][4];
            ldsm4(bh[0], bH + bcol);
            ldsm4(bh[1], bH + 1024 + bcol);
            #pragma unroll
            for (int fm = 0; fm < 4; fm++) {
                uint32_t a_f[4];
                ldsm4(a_f, aH + fm * 1024 + acol);
                #pragma unroll
                for (int fn = 0; fn < 4; fn++)
                    mma16816h(acc[fm][fn], a_f, &bh[fn >> 1][(fn & 1) << 1]);
            }
        }
        const uint32_t t = st0; st0 = st1; st1 = st2; st2 = st3; st3 = t;
    }

    // ---- epilogue ----
    const int mB = m0 + (wm << 6) + (lane >> 2);
    const int nB = n0 + (wn << 5) + ((lane & 3) << 1);
    #pragma unroll
    for (int fm = 0; fm < 4; fm++) {
        const int r0 = mB + (fm << 4);
        #pragma unroll
        for (int fn = 0; fn < 4; fn++) {
            const int cc = nB + (fn << 3);
            if (EPI == 3) {
                const int j = cc >> 1;
                const float ba = __ldg(bias + j);
                const float bg = __ldg(bias + 1024 + j);
                const float a0 = acc[fm][fn][0] + ba, gg0 = acc[fm][fn][1] + bg;
                const float a1 = acc[fm][fn][2] + ba, gg1 = acc[fm][fn][3] + bg;
                C[(size_t)r0 * (N >> 1) + j]       = a0 * sigmoidf_(gg0);
                C[(size_t)(r0 + 8) * (N >> 1) + j] = a1 * sigmoidf_(gg1);
            } else {
                const float2 bv = __ldg((const float2*)(bias + cc));
                float v0 = acc[fm][fn][0] + bv.x;
                float v1 = acc[fm][fn][1] + bv.y;
                float v2 = acc[fm][fn][2] + bv.x;
                float v3 = acc[fm][fn][3] + bv.y;
                const size_t o0 = (size_t)r0 * N + cc;
                const size_t o1 = (size_t)(r0 + 8) * N + cc;
                if (EPI == 1) {
                    v0 = v0 * sigmoidf_(v0); v1 = v1 * sigmoidf_(v1);
                    v2 = v2 * sigmoidf_(v2); v3 = v3 * sigmoidf_(v3);
                    __half2 p;
                    p.x = __float2half_rn(v0); p.y = __float2half_rn(v1);
                    *(__half2*)(Ch + o0) = p;
                    p.x = __float2half_rn(v2); p.y = __float2half_rn(v3);
                    *(__half2*)(Ch + o1) = p;
                } else {
                    const float2 ra = __ldg((const float2*)(res + o0));
                    const float2 rb = __ldg((const float2*)(res + o1));
                    v0 += ra.x; v1 += ra.y; v2 += rb.x; v3 += rb.y;
                    float2 q;
                    q.x = v0; q.y = v1; *(float2*)(C + o0) = q;
                    q.x = v2; q.y = v3; *(float2*)(C + o1) = q;
                }
            }
        }
    }
}

// ---------------------------------------------------------------------------
// Weight convert + transpose: W[K,N] fp32 -> Wh [N,K] fp16
// ---------------------------------------------------------------------------
__global__ __launch_bounds__(256) void wconv_kernel(
    const float* __restrict__ W, __half* __restrict__ Wh, int K, int N)
{
    __shared__ float tile[32][33];
    const int n0 = blockIdx.x << 5;
    const int k0 = blockIdx.y << 5;
    for (int i = threadIdx.y; i < 32; i += 8)
        tile[i][threadIdx.x] = W[(size_t)(k0 + i) * N + n0 + threadIdx.x];
    __syncthreads();
    for (int i = threadIdx.y; i < 32; i += 8)
        Wh[(size_t)(n0 + i) * K + k0 + threadIdx.x] = __float2half_rn(tile[threadIdx.x][i]);
}

// W1 permuted: out row 2j = src col j (a), out row 2j+1 = src col 1024+j (gate)
__global__ __launch_bounds__(256) void wconv_perm_kernel(
    const float* __restrict__ W, __half* __restrict__ Wh)
{
    __shared__ float tile[32][33];
    const int n0 = blockIdx.x << 5;
    const int k0 = blockIdx.y << 5;
    const int tx = threadIdx.x;
    const int orow = n0 + tx;
    const int scol = (orow & 1) ? (1024 + (orow >> 1)) : (orow >> 1);
    for (int i = threadIdx.y; i < 32; i += 8)
        tile[i][tx] = W[(size_t)(k0 + i) * 2048 + scol];
    __syncthreads();
    for (int i = threadIdx.y; i < 32; i += 8)
        Wh[(size_t)(n0 + i) * 1024 + k0 + tx] = __float2half_rn(tile[tx][i]);
}

// ---------------------------------------------------------------------------
// LayerNorm -> fp16
// ---------------------------------------------------------------------------
__device__ __forceinline__ float block_sum256(float v, float* sh) {
    #pragma unroll
    for (int o = 16; o > 0; o >>= 1) v += __shfl_xor_sync(0xffffffffu, v, o);
    if ((threadIdx.x & 31) == 0) sh[threadIdx.x >> 5] = v;
    __syncthreads();
    float tot = 0.f;
    #pragma unroll
    for (int i = 0; i < 8; i++) tot += sh[i];
    __syncthreads();
    return tot;
}

__global__ __launch_bounds__(256) void ln_h_kernel(
    const float* __restrict__ in, __half* __restrict__ oh,
    const float* __restrict__ gw, const float* __restrict__ bw)
{
    __shared__ float sh[8];
    const size_t row = blockIdx.x;
    const float4 v = ((const float4*)(in + row * 1024))[threadIdx.x];

    float s = v.x + v.y + v.z + v.w;
    s = block_sum256(s, sh);
    const float mean = s * (1.f / 1024.f);
    const float dx = v.x - mean, dy = v.y - mean, dz = v.z - mean, dw = v.w - mean;
    float q = dx * dx + dy * dy + dz * dz + dw * dw;
    q = block_sum256(q, sh);
    const float rstd = rsqrtf(q * (1.f / 1024.f) + 1e-5f);

    const float4 g4 = ((const float4*)gw)[threadIdx.x];
    const float4 b4 = ((const float4*)bw)[threadIdx.x];
    const size_t base = row * 1024 + (size_t)threadIdx.x * 4;
    __half2 p;
    p.x = __float2half_rn(dx * rstd * g4.x + b4.x);
    p.y = __float2half_rn(dy * rstd * g4.y + b4.y);
    *(__half2*)(oh + base) = p;
    p.x = __float2half_rn(dz * rstd * g4.z + b4.z);
    p.y = __float2half_rn(dw * rstd * g4.w + b4.w);
    *(__half2*)(oh + base + 2) = p;
}

// ---------------------------------------------------------------------------
// alpha = sigmoid(glu @ W_off + b_off). Warp per row, W_off transposed in smem.
// ---------------------------------------------------------------------------
__global__ __launch_bounds__(256) void alpha_kernel(
    const float* __restrict__ g, const float* __restrict__ Woff,
    const float* __restrict__ boff, float* __restrict__ alpha)
{
    extern __shared__ float Ws[];   // [16][1024]
    for (int k = threadIdx.x; k < 1024; k += 256) {
        const float4 w0 = __ldg((const float4*)(Woff + (size_t)k * 16));
        const float4 w1 = __ldg((const float4*)(Woff + (size_t)k * 16 + 4));
        const float4 w2 = __ldg((const float4*)(Woff + (size_t)k * 16 + 8));
        const float4 w3 = __ldg((const float4*)(Woff + (size_t)k * 16 + 12));
        Ws[0 * 1024 + k] = w0.x; Ws[1 * 1024 + k] = w0.y;
        Ws[2 * 1024 + k] = w0.z; Ws[3 * 1024 + k] = w0.w;
        Ws[4 * 1024 + k] = w1.x; Ws[5 * 1024 + k] = w1.y;
        Ws[6 * 1024 + k] = w1.z; Ws[7 * 1024 + k] = w1.w;
        Ws[8 * 1024 + k] = w2.x; Ws[9 * 1024 + k] = w2.y;
        Ws[10 * 1024 + k] = w2.z; Ws[11 * 1024 + k] = w2.w;
        Ws[12 * 1024 + k] = w3.x; Ws[13 * 1024 + k] = w3.y;
        Ws[14 * 1024 + k] = w3.z; Ws[15 * 1024 + k] = w3.w;
    }
    __syncthreads();

    const int wid = threadIdx.x >> 5, lane = threadIdx.x & 31;
    const int row = blockIdx.x * 8 + wid;
    const float* gr = g + (size_t)row * 1024;

    float acc[16];
    #pragma unroll
    for (int n = 0; n < 16; n++) acc[n] = 0.f;

    #pragma unroll
    for (int j = 0; j < 8; j++) {
        const int k = (lane << 2) + (j << 7);
        const float4 v = *(const float4*)(gr + k);
        #pragma unroll
        for (int n = 0; n < 16; n++) {
            const float4 w = *(const float4*)(Ws + n * 1024 + k);
            acc[n] += v.x * w.x + v.y * w.y + v.z * w.z + v.w * w.w;
        }
    }
    #pragma unroll
    for (int o = 16; o > 0; o >>= 1)
        #pragma unroll
        for (int n = 0; n < 16; n++)
            acc[n] += __shfl_xor_sync(0xffffffffu, acc[n], o);

    if (lane < 16) {
        const int t = row >> 3, b = row & 7;
        alpha[(size_t)t * BH_DIM + b * 16 + lane] =
            sigmoidf_(acc[lane] + __ldg(boff + lane));
    }
}

// ---------------------------------------------------------------------------
// Segmented cumsum over time (scale 1/32)
// ---------------------------------------------------------------------------
__global__ __launch_bounds__(256) void cumsum_part(
    const float* __restrict__ in, float* __restrict__ part)
{
    const int c = blockIdx.x * 256 + threadIdx.x;
    const int s = blockIdx.y;
    float acc = 0.f;
    for (int t0 = s * 512; t0 < (s + 1) * 512; t0 += 8) {
        float v[8];
        #pragma unroll
        for (int i = 0; i < 8; i++) v[i] = in[(size_t)(t0 + i) * CHAN + c];
        #pragma unroll
        for (int i = 0; i < 8; i++) acc += v[i];
    }
    part[s * CHAN + c] = acc;
}

__global__ __launch_bounds__(256) void cumsum_scan(
    const float* __restrict__ in, const float* __restrict__ part,
    float* __restrict__ out)
{
    const int c = blockIdx.x * 256 + threadIdx.x;
    const int s = blockIdx.y;
    const float scale = 1.f / 32.f;
    float acc = 0.f;
    for (int p = 0; p < s; p++) acc += part[p * CHAN + c];
    acc *= scale;
    for (int t0 = s * 512; t0 < (s + 1) * 512; t0 += 8) {
        float v[8];
        #pragma unroll
        for (int i = 0; i < 8; i++) v[i] = in[(size_t)(t0 + i) * CHAN + c];
        #pragma unroll
        for (int i = 0; i < 8; i++) {
            acc = fmaf(v[i], scale, acc);
            out[(size_t)(t0 + i) * CHAN + c] = acc;
        }
    }
}

// ---------------------------------------------------------------------------
// TaLK gather/lerp -> fp16
// ---------------------------------------------------------------------------
__global__ __launch_bounds__(256) void talk_h_kernel(
    const float* __restrict__ S, const float* __restrict__ alpha,
    __half* __restrict__ oh)
{
    const size_t e = ((size_t)blockIdx.x * blockDim.x + threadIdx.x) << 2;
    const int t = (int)(e >> 13);
    const int col = (int)(e & 8191);
    const int bh = col >> 6;

    const float al = alpha[(size_t)t * BH_DIM + bh];
    const float eff = fminf(31.f, (float)t);
    const float pos = (float)t - 1.f - al * eff;
    const float i0f = floorf(pos);
    const float frac = pos - i0f;
    const int i0 = (int)i0f;
    const int c0 = max(i0, 0);
    const int c1 = i0 + 1;

    const float4 s  = *(const float4*)(S + (size_t)t  * CHAN + col);
    float4 v0       = *(const float4*)(S + (size_t)c0 * CHAN + col);
    const float4 v1 = *(const float4*)(S + (size_t)c1 * CHAN + col);
    if (i0 < 0) { v0.x = 0.f; v0.y = 0.f; v0.z = 0.f; v0.w = 0.f; }

    __half2 p;
    p.x = __float2half_rn(s.x - (v0.x + frac * (v1.x - v0.x)));
    p.y = __float2half_rn(s.y - (v0.y + frac * (v1.y - v0.y)));
    *(__half2*)(oh + e) = p;
    p.x = __float2half_rn(s.z - (v0.z + frac * (v1.z - v0.z)));
    p.y = __float2half_rn(s.w - (v0.w + frac * (v1.w - v0.w)));
    *(__half2*)(oh + e + 2) = p;
}

// ---------------------------------------------------------------------------
// Launch
// ---------------------------------------------------------------------------
extern "C" void kernel_launch(void* const* d_in, const int* in_sizes, int n_in,
                              void* d_out, int out_size)
{
    const float* x    = (const float*)d_in[0];
    const float* W1   = (const float*)d_in[4];
    const float* b1   = (const float*)d_in[5];
    const float* Woff = (const float*)d_in[6];
    const float* boff = (const float*)d_in[7];
    const float* W2   = (const float*)d_in[8];
    const float* b2   = (const float*)d_in[9];
    const float* Wf1  = (const float*)d_in[10];
    const float* bf1  = (const float*)d_in[11];
    const float* Wf2  = (const float*)d_in[12];
    const float* bf2  = (const float*)d_in[13];
    const float* gcv  = (const float*)d_in[14];
    const float* bcv  = (const float*)d_in[15];
    const float* gfn  = (const float*)d_in[16];
    const float* bfn  = (const float*)d_in[17];

    __half *Ap, *Mp, *W1p, *W2p, *Wf1p, *Wf2p;
    float *glu, *S, *y, *alpha, *part;
    cudaGetSymbolAddress((void**)&Ap, g_A);
    cudaGetSymbolAddress((void**)&Mp, g_M);
    cudaGetSymbolAddress((void**)&W1p, g_W1);
    cudaGetSymbolAddress((void**)&W2p, g_W2);
    cudaGetSymbolAddress((void**)&Wf1p, g_Wf1);
    cudaGetSymbolAddress((void**)&Wf2p, g_Wf2);
    cudaGetSymbolAddress((void**)&glu, g_glu);
    cudaGetSymbolAddress((void**)&S, g_S);      cudaGetSymbolAddress((void**)&y, g_y);
    cudaGetSymbolAddress((void**)&alpha, g_alpha);
    cudaGetSymbolAddress((void**)&part, g_part);

    cudaFuncSetAttribute((const void*)gemm_mma<1, 1024>, cudaFuncAttributeMaxDynamicSharedMemorySize, GEMM_SMEM);
    cudaFuncSetAttribute((const void*)gemm_mma<2, 1024>, cudaFuncAttributeMaxDynamicSharedMemorySize, GEMM_SMEM);
    cudaFuncSetAttribute((const void*)gemm_mma<3, 1024>, cudaFuncAttributeMaxDynamicSharedMemorySize, GEMM_SMEM);
    cudaFuncSetAttribute((const void*)gemm_mma<2, 4096>, cudaFuncAttributeMaxDynamicSharedMemorySize, GEMM_SMEM);
    cudaFuncSetAttribute(alpha_kernel, cudaFuncAttributeMaxDynamicSharedMemorySize, 65536);

    const dim3 tb(32, 8);
    wconv_perm_kernel<<<dim3(2048 / 32, 1024 / 32), tb>>>(W1, W1p);
    wconv_kernel<<<dim3(1024 / 32, 1024 / 32), tb>>>(W2,  W2p,  1024, 1024);
    wconv_kernel<<<dim3(4096 / 32, 1024 / 32), tb>>>(Wf1, Wf1p, 1024, 4096);
    wconv_kernel<<<dim3(1024 / 32, 4096 / 32), tb>>>(Wf2, Wf2p, 4096, 1024);

    const int ew_blocks = (M_TOK * 1024 / 4) / 256;

    // conv block
    ln_h_kernel<<<M_TOK, 256>>>(x, Ap, gcv, bcv);
    gemm_mma<3, 1024><<<dim3(16, 256), 256, GEMM_SMEM>>>(
        Ap, W1p, b1, nullptr, glu, nullptr, M_TOK, 2048);
    alpha_kernel<<<M_TOK / 8, 256, 65536>>>(glu, Woff, boff, alpha);
    cumsum_part<<<dim3(CHAN / 256, 8), 256>>>(glu, part);
    cumsum_scan<<<dim3(CHAN / 256, 8), 256>>>(glu, part, S);
    talk_h_kernel<<<ew_blocks, 256>>>(S, alpha, Ap);
    gemm_mma<2, 1024><<<dim3(8, 256), 256, GEMM_SMEM>>>(
        Ap, W2p, b2, x, y, nullptr, M_TOK, 1024);

    // FFN block
    ln_h_kernel<<<M_TOK, 256>>>(y, Ap, gfn, bfn);
    gemm_mma<1, 1024><<<dim3(32, 256), 256, GEMM_SMEM>>>(
        Ap, Wf1p, bf1, nullptr, nullptr, Mp, M_TOK, 4096);
    gemm_mma<2, 4096><<<dim3(8, 256), 256, GEMM_SMEM>>>(
        Mp, Wf2p, bf2, y, (float*)d_out, nullptr, M_TOK, 1024);
}

// round 9
// speedup vs baseline: 7.8561x; 1.1541x over previous
#include <cuda_runtime.h>
#include <cuda_fp16.h>
#include <stdint.h>
#include <math.h>

#define T_DIM   4096
#define B_DIM   8
#define M_TOK   32768
#define CHAN    8192
#define BH_DIM  128

// ---------------------------------------------------------------------------
// Device-global scratch
// ---------------------------------------------------------------------------
__device__ __half g_A  [M_TOK * 1024];                     // fp16 activations
__device__ __half g_M  [M_TOK * 4096];                     // fp16 FFN mid
__device__ __half g_W1 [2048 * 1024];                      // permuted (a/gate interleaved)
__device__ __half g_W2 [1024 * 1024];
__device__ __half g_Wf1[4096 * 1024];
__device__ __half g_Wf2[1024 * 4096];
__device__ float g_glu [M_TOK * 1024];
__device__ float g_S   [M_TOK * 1024];
__device__ float g_y   [M_TOK * 1024];
__device__ float g_alpha[T_DIM * BH_DIM];
__device__ float g_part[8 * CHAN];

__device__ __forceinline__ float sigmoidf_(float v) { return 1.f / (1.f + __expf(-v)); }

__device__ __forceinline__ uint32_t smem_addr_of(const void* p) {
    uint32_t a;
    asm("{ .reg .u64 t; cvta.to.shared.u64 t, %1; cvt.u32.u64 %0, t; }" : "=r"(a) : "l"(p));
    return a;
}
__device__ __forceinline__ void ldsm4(uint32_t* r, uint32_t addr) {
    asm volatile("ldmatrix.sync.aligned.m8n8.x4.shared.b16 {%0,%1,%2,%3}, [%4];"
                 : "=r"(r[0]), "=r"(r[1]), "=r"(r[2]), "=r"(r[3]) : "r"(addr));
}
__device__ __forceinline__ void mma16816h(float* d, const uint32_t* a, const uint32_t* b) {
    asm volatile("mma.sync.aligned.m16n8k16.row.col.f32.f16.f16.f32 "
                 "{%0,%1,%2,%3}, {%4,%5,%6,%7}, {%8,%9}, {%0,%1,%2,%3};"
                 : "+f"(d[0]), "+f"(d[1]), "+f"(d[2]), "+f"(d[3])
                 : "r"(a[0]), "r"(a[1]), "r"(a[2]), "r"(a[3]), "r"(b[0]), "r"(b[1]));
}
__device__ __forceinline__ void cpa16(uint32_t s, const void* g) {
    asm volatile("cp.async.cg.shared.global [%0], [%1], 16;" :: "r"(s), "l"(g));
}
__device__ __forceinline__ void cpa_commit() {
    asm volatile("cp.async.commit_group;" ::: "memory");
}
__device__ __forceinline__ void cpa_wait1() {
    asm volatile("cp.async.wait_group 1;" ::: "memory");
}

// ---------------------------------------------------------------------------
// fp16 GEMM on mma.sync: C = A_fp16 @ B_fp16^T, fp32 accumulate.
// CTA 128x128, 8 warps (64x32), BK=64 (128B rows, XOR-8 swizzle),
// 3-stage cp.async ring -> 96KB smem -> 2 CTAs/SM. K compile-time.
// EPI: 1 = +bias, swish -> fp16 ; 2 = +bias + residual -> fp32 ;
//      3 = GLU (paired cols a/gate) +bias -> fp32 glu [M, N/2]
// ---------------------------------------------------------------------------
#define TILE_B  16384               // 128 rows * 128B
#define STAGE_B 32768               // A + B tiles
#define GEMM_SMEM (3 * STAGE_B)     // 98304

template<int EPI, int K>
__global__ __launch_bounds__(256, 2) void gemm_mma(
    const __half* __restrict__ A, const __half* __restrict__ B,
    const float* __restrict__ bias, const float* __restrict__ res,
    float* __restrict__ C, __half* __restrict__ Ch,
    int M, int N)
{
    extern __shared__ __align__(1024) char smem[];
    const uint32_t sb = smem_addr_of(smem);
    const int tid = threadIdx.x, wid = tid >> 5, lane = tid & 31;
    const int wm = wid & 1, wn = wid >> 1;
    const int m0 = blockIdx.y << 7, n0 = blockIdx.x << 7;

    const __half* gA = A + (size_t)m0 * K;
    const __half* gB = B + (size_t)n0 * K;

    const int ldr = tid >> 3;          // 0..31 (row within 32-row pass)
    const int ldc = tid & 7;           // 16B chunk in 128B row
    const uint32_t dst = (uint32_t)ldr * 128 + (((uint32_t)ldc ^ (ldr & 7)) << 4);

    auto load_stage = [&](uint32_t sbase, int chunk) {
        const int k0 = chunk << 6;
        const __half* a = gA + (size_t)ldr * K + k0 + (ldc << 3);
        const __half* b = gB + (size_t)ldr * K + k0 + (ldc << 3);
        #pragma unroll
        for (int i = 0; i < 4; i++) {
            cpa16(sbase + dst + i * (32 * 128), a + (size_t)(i * 32) * K);
            cpa16(sbase + TILE_B + dst + i * (32 * 128), b + (size_t)(i * 32) * K);
        }
    };

    float acc[4][4][4];
    #pragma unroll
    for (int a = 0; a < 4; a++)
        #pragma unroll
        for (int b = 0; b < 4; b++)
            #pragma unroll
            for (int k = 0; k < 4; k++) acc[a][b][k] = 0.f;

    constexpr int NC = K >> 6;
    uint32_t st0 = sb, st1 = sb + STAGE_B, st2 = sb + 2 * STAGE_B;
    load_stage(st0, 0); cpa_commit();
    load_stage(st1, 1); cpa_commit();

    const int ar = (wm << 6) + (lane & 15);
    const uint32_t aRow = (uint32_t)ar * 128;
    const int axor = ar & 7;
    const int ahalf = lane >> 4;
    const int br = (wn << 5) + ((lane & 7) | ((lane & 16) >> 1));
    const uint32_t bRow = (uint32_t)br * 128;
    const int bxor = br & 7;
    const int bhalf = (lane >> 3) & 1;

    #pragma unroll 1
    for (int c = 0; c < NC; c++) {
        cpa_wait1();
        __syncthreads();
        if (c + 2 < NC) load_stage(st2, c + 2);
        cpa_commit();

        const uint32_t aH = st0 + aRow;
        const uint32_t bH = st0 + TILE_B + bRow;

        #pragma unroll
        for (int kk = 0; kk < 4; kk++) {
            const uint32_t acol = (uint32_t)((((kk << 1) + ahalf) ^ axor)) << 4;
            const uint32_t bcol = (uint32_t)((((kk << 1) + bhalf) ^ bxor)) << 4;
            uint32_t bh[2][4];
            ldsm4(bh[0], bH + bcol);
            ldsm4(bh[1], bH + (16 * 128) + bcol);
            #pragma unroll
            for (int fm = 0; fm < 4; fm++) {
                uint32_t a_f[4];
                ldsm4(a_f, aH + fm * (16 * 128) + acol);
                #pragma unroll
                for (int fn = 0; fn < 4; fn++)
                    mma16816h(acc[fm][fn], a_f, &bh[fn >> 1][(fn & 1) << 1]);
            }
        }
        const uint32_t t = st0; st0 = st1; st1 = st2; st2 = t;
    }

    // ---- epilogue ----
    const int mB = m0 + (wm << 6) + (lane >> 2);
    const int nB = n0 + (wn << 5) + ((lane & 3) << 1);
    #pragma unroll
    for (int fm = 0; fm < 4; fm++) {
        const int r0 = mB + (fm << 4);
        #pragma unroll
        for (int fn = 0; fn < 4; fn++) {
            const int cc = nB + (fn << 3);
            if (EPI == 3) {
                const int j = cc >> 1;
                const float ba = __ldg(bias + j);
                const float bg = __ldg(bias + 1024 + j);
                const float a0 = acc[fm][fn][0] + ba, gg0 = acc[fm][fn][1] + bg;
                const float a1 = acc[fm][fn][2] + ba, gg1 = acc[fm][fn][3] + bg;
                C[(size_t)r0 * (N >> 1) + j]       = a0 * sigmoidf_(gg0);
                C[(size_t)(r0 + 8) * (N >> 1) + j] = a1 * sigmoidf_(gg1);
            } else {
                const float2 bv = __ldg((const float2*)(bias + cc));
                float v0 = acc[fm][fn][0] + bv.x;
                float v1 = acc[fm][fn][1] + bv.y;
                float v2 = acc[fm][fn][2] + bv.x;
                float v3 = acc[fm][fn][3] + bv.y;
                const size_t o0 = (size_t)r0 * N + cc;
                const size_t o1 = (size_t)(r0 + 8) * N + cc;
                if (EPI == 1) {
                    v0 = v0 * sigmoidf_(v0); v1 = v1 * sigmoidf_(v1);
                    v2 = v2 * sigmoidf_(v2); v3 = v3 * sigmoidf_(v3);
                    __half2 p;
                    p.x = __float2half_rn(v0); p.y = __float2half_rn(v1);
                    *(__half2*)(Ch + o0) = p;
                    p.x = __float2half_rn(v2); p.y = __float2half_rn(v3);
                    *(__half2*)(Ch + o1) = p;
                } else {
                    const float2 ra = __ldg((const float2*)(res + o0));
                    const float2 rb = __ldg((const float2*)(res + o1));
                    v0 += ra.x; v1 += ra.y; v2 += rb.x; v3 += rb.y;
                    float2 q;
                    q.x = v0; q.y = v1; *(float2*)(C + o0) = q;
                    q.x = v2; q.y = v3; *(float2*)(C + o1) = q;
                }
            }
        }
    }
}

// ---------------------------------------------------------------------------
// Weight convert + transpose: W[K,N] fp32 -> Wh [N,K] fp16
// ---------------------------------------------------------------------------
__global__ __launch_bounds__(256) void wconv_kernel(
    const float* __restrict__ W, __half* __restrict__ Wh, int K, int N)
{
    __shared__ float tile[32][33];
    const int n0 = blockIdx.x << 5;
    const int k0 = blockIdx.y << 5;
    for (int i = threadIdx.y; i < 32; i += 8)
        tile[i][threadIdx.x] = W[(size_t)(k0 + i) * N + n0 + threadIdx.x];
    __syncthreads();
    for (int i = threadIdx.y; i < 32; i += 8)
        Wh[(size_t)(n0 + i) * K + k0 + threadIdx.x] = __float2half_rn(tile[threadIdx.x][i]);
}

// W1 permuted: out row 2j = src col j (a), out row 2j+1 = src col 1024+j (gate)
__global__ __launch_bounds__(256) void wconv_perm_kernel(
    const float* __restrict__ W, __half* __restrict__ Wh)
{
    __shared__ float tile[32][33];
    const int n0 = blockIdx.x << 5;
    const int k0 = blockIdx.y << 5;
    const int tx = threadIdx.x;
    const int orow = n0 + tx;
    const int scol = (orow & 1) ? (1024 + (orow >> 1)) : (orow >> 1);
    for (int i = threadIdx.y; i < 32; i += 8)
        tile[i][tx] = W[(size_t)(k0 + i) * 2048 + scol];
    __syncthreads();
    for (int i = threadIdx.y; i < 32; i += 8)
        Wh[(size_t)(n0 + i) * 1024 + k0 + tx] = __float2half_rn(tile[tx][i]);
}

// ---------------------------------------------------------------------------
// LayerNorm -> fp16
// ---------------------------------------------------------------------------
__device__ __forceinline__ float block_sum256(float v, float* sh) {
    #pragma unroll
    for (int o = 16; o > 0; o >>= 1) v += __shfl_xor_sync(0xffffffffu, v, o);
    if ((threadIdx.x & 31) == 0) sh[threadIdx.x >> 5] = v;
    __syncthreads();
    float tot = 0.f;
    #pragma unroll
    for (int i = 0; i < 8; i++) tot += sh[i];
    __syncthreads();
    return tot;
}

__global__ __launch_bounds__(256) void ln_h_kernel(
    const float* __restrict__ in, __half* __restrict__ oh,
    const float* __restrict__ gw, const float* __restrict__ bw)
{
    __shared__ float sh[8];
    const size_t row = blockIdx.x;
    const float4 v = ((const float4*)(in + row * 1024))[threadIdx.x];

    float s = v.x + v.y + v.z + v.w;
    s = block_sum256(s, sh);
    const float mean = s * (1.f / 1024.f);
    const float dx = v.x - mean, dy = v.y - mean, dz = v.z - mean, dw = v.w - mean;
    float q = dx * dx + dy * dy + dz * dz + dw * dw;
    q = block_sum256(q, sh);
    const float rstd = rsqrtf(q * (1.f / 1024.f) + 1e-5f);

    const float4 g4 = ((const float4*)gw)[threadIdx.x];
    const float4 b4 = ((const float4*)bw)[threadIdx.x];
    const size_t base = row * 1024 + (size_t)threadIdx.x * 4;
    __half2 p;
    p.x = __float2half_rn(dx * rstd * g4.x + b4.x);
    p.y = __float2half_rn(dy * rstd * g4.y + b4.y);
    *(__half2*)(oh + base) = p;
    p.x = __float2half_rn(dz * rstd * g4.z + b4.z);
    p.y = __float2half_rn(dw * rstd * g4.w + b4.w);
    *(__half2*)(oh + base + 2) = p;
}

// ---------------------------------------------------------------------------
// alpha = sigmoid(glu @ W_off + b_off). Warp per row, W_off transposed in smem.
// ---------------------------------------------------------------------------
__global__ __launch_bounds__(256) void alpha_kernel(
    const float* __restrict__ g, const float* __restrict__ Woff,
    const float* __restrict__ boff, float* __restrict__ alpha)
{
    extern __shared__ float Ws[];   // [16][1024]
    for (int k = threadIdx.x; k < 1024; k += 256) {
        const float4 w0 = __ldg((const float4*)(Woff + (size_t)k * 16));
        const float4 w1 = __ldg((const float4*)(Woff + (size_t)k * 16 + 4));
        const float4 w2 = __ldg((const float4*)(Woff + (size_t)k * 16 + 8));
        const float4 w3 = __ldg((const float4*)(Woff + (size_t)k * 16 + 12));
        Ws[0 * 1024 + k] = w0.x; Ws[1 * 1024 + k] = w0.y;
        Ws[2 * 1024 + k] = w0.z; Ws[3 * 1024 + k] = w0.w;
        Ws[4 * 1024 + k] = w1.x; Ws[5 * 1024 + k] = w1.y;
        Ws[6 * 1024 + k] = w1.z; Ws[7 * 1024 + k] = w1.w;
        Ws[8 * 1024 + k] = w2.x; Ws[9 * 1024 + k] = w2.y;
        Ws[10 * 1024 + k] = w2.z; Ws[11 * 1024 + k] = w2.w;
        Ws[12 * 1024 + k] = w3.x; Ws[13 * 1024 + k] = w3.y;
        Ws[14 * 1024 + k] = w3.z; Ws[15 * 1024 + k] = w3.w;
    }
    __syncthreads();

    const int wid = threadIdx.x >> 5, lane = threadIdx.x & 31;
    const int row = blockIdx.x * 8 + wid;
    const float* gr = g + (size_t)row * 1024;

    float acc[16];
    #pragma unroll
    for (int n = 0; n < 16; n++) acc[n] = 0.f;

    #pragma unroll
    for (int j = 0; j < 8; j++) {
        const int k = (lane << 2) + (j << 7);
        const float4 v = *(const float4*)(gr + k);
        #pragma unroll
        for (int n = 0; n < 16; n++) {
            const float4 w = *(const float4*)(Ws + n * 1024 + k);
            acc[n] += v.x * w.x + v.y * w.y + v.z * w.z + v.w * w.w;
        }
    }
    #pragma unroll
    for (int o = 16; o > 0; o >>= 1)
        #pragma unroll
        for (int n = 0; n < 16; n++)
            acc[n] += __shfl_xor_sync(0xffffffffu, acc[n], o);

    if (lane < 16) {
        const int t = row >> 3, b = row & 7;
        alpha[(size_t)t * BH_DIM + b * 16 + lane] =
            sigmoidf_(acc[lane] + __ldg(boff + lane));
    }
}

// ---------------------------------------------------------------------------
// Segmented cumsum over time (scale 1/32)
// ---------------------------------------------------------------------------
__global__ __launch_bounds__(256) void cumsum_part(
    const float* __restrict__ in, float* __restrict__ part)
{
    const int c = blockIdx.x * 256 + threadIdx.x;
    const int s = blockIdx.y;
    float acc = 0.f;
    for (int t0 = s * 512; t0 < (s + 1) * 512; t0 += 8) {
        float v[8];
        #pragma unroll
        for (int i = 0; i < 8; i++) v[i] = in[(size_t)(t0 + i) * CHAN + c];
        #pragma unroll
        for (int i = 0; i < 8; i++) acc += v[i];
    }
    part[s * CHAN + c] = acc;
}

__global__ __launch_bounds__(256) void cumsum_scan(
    const float* __restrict__ in, const float* __restrict__ part,
    float* __restrict__ out)
{
    const int c = blockIdx.x * 256 + threadIdx.x;
    const int s = blockIdx.y;
    const float scale = 1.f / 32.f;
    float acc = 0.f;
    for (int p = 0; p < s; p++) acc += part[p * CHAN + c];
    acc *= scale;
    for (int t0 = s * 512; t0 < (s + 1) * 512; t0 += 8) {
        float v[8];
        #pragma unroll
        for (int i = 0; i < 8; i++) v[i] = in[(size_t)(t0 + i) * CHAN + c];
        #pragma unroll
        for (int i = 0; i < 8; i++) {
            acc = fmaf(v[i], scale, acc);
            out[(size_t)(t0 + i) * CHAN + c] = acc;
        }
    }
}

// ---------------------------------------------------------------------------
// TaLK gather/lerp -> fp16
// ---------------------------------------------------------------------------
__global__ __launch_bounds__(256) void talk_h_kernel(
    const float* __restrict__ S, const float* __restrict__ alpha,
    __half* __restrict__ oh)
{
    const size_t e = ((size_t)blockIdx.x * blockDim.x + threadIdx.x) << 2;
    const int t = (int)(e >> 13);
    const int col = (int)(e & 8191);
    const int bh = col >> 6;

    const float al = alpha[(size_t)t * BH_DIM + bh];
    const float eff = fminf(31.f, (float)t);
    const float pos = (float)t - 1.f - al * eff;
    const float i0f = floorf(pos);
    const float frac = pos - i0f;
    const int i0 = (int)i0f;
    const int c0 = max(i0, 0);
    const int c1 = i0 + 1;

    const float4 s  = *(const float4*)(S + (size_t)t  * CHAN + col);
    float4 v0       = *(const float4*)(S + (size_t)c0 * CHAN + col);
    const float4 v1 = *(const float4*)(S + (size_t)c1 * CHAN + col);
    if (i0 < 0) { v0.x = 0.f; v0.y = 0.f; v0.z = 0.f; v0.w = 0.f; }

    __half2 p;
    p.x = __float2half_rn(s.x - (v0.x + frac * (v1.x - v0.x)));
    p.y = __float2half_rn(s.y - (v0.y + frac * (v1.y - v0.y)));
    *(__half2*)(oh + e) = p;
    p.x = __float2half_rn(s.z - (v0.z + frac * (v1.z - v0.z)));
    p.y = __float2half_rn(s.w - (v0.w + frac * (v1.w - v0.w)));
    *(__half2*)(oh + e + 2) = p;
}

// ---------------------------------------------------------------------------
// Launch
// ---------------------------------------------------------------------------
extern "C" void kernel_launch(void* const* d_in, const int* in_sizes, int n_in,
                              void* d_out, int out_size)
{
    const float* x    = (const float*)d_in[0];
    const float* W1   = (const float*)d_in[4];
    const float* b1   = (const float*)d_in[5];
    const float* Woff = (const float*)d_in[6];
    const float* boff = (const float*)d_in[7];
    const float* W2   = (const float*)d_in[8];
    const float* b2   = (const float*)d_in[9];
    const float* Wf1  = (const float*)d_in[10];
    const float* bf1  = (const float*)d_in[11];
    const float* Wf2  = (const float*)d_in[12];
    const float* bf2  = (const float*)d_in[13];
    const float* gcv  = (const float*)d_in[14];
    const float* bcv  = (const float*)d_in[15];
    const float* gfn  = (const float*)d_in[16];
    const float* bfn  = (const float*)d_in[17];

    __half *Ap, *Mp, *W1p, *W2p, *Wf1p, *Wf2p;
    float *glu, *S, *y, *alpha, *part;
    cudaGetSymbolAddress((void**)&Ap, g_A);
    cudaGetSymbolAddress((void**)&Mp, g_M);
    cudaGetSymbolAddress((void**)&W1p, g_W1);
    cudaGetSymbolAddress((void**)&W2p, g_W2);
    cudaGetSymbolAddress((void**)&Wf1p, g_Wf1);
    cudaGetSymbolAddress((void**)&Wf2p, g_Wf2);
    cudaGetSymbolAddress((void**)&glu, g_glu);
    cudaGetSymbolAddress((void**)&S, g_S);      cudaGetSymbolAddress((void**)&y, g_y);
    cudaGetSymbolAddress((void**)&alpha, g_alpha);
    cudaGetSymbolAddress((void**)&part, g_part);

    cudaFuncSetAttribute((const void*)gemm_mma<1, 1024>, cudaFuncAttributeMaxDynamicSharedMemorySize, GEMM_SMEM);
    cudaFuncSetAttribute((const void*)gemm_mma<2, 1024>, cudaFuncAttributeMaxDynamicSharedMemorySize, GEMM_SMEM);
    cudaFuncSetAttribute((const void*)gemm_mma<3, 1024>, cudaFuncAttributeMaxDynamicSharedMemorySize, GEMM_SMEM);
    cudaFuncSetAttribute((const void*)gemm_mma<2, 4096>, cudaFuncAttributeMaxDynamicSharedMemorySize, GEMM_SMEM);
    cudaFuncSetAttribute(alpha_kernel, cudaFuncAttributeMaxDynamicSharedMemorySize, 65536);

    const dim3 tb(32, 8);
    wconv_perm_kernel<<<dim3(2048 / 32, 1024 / 32), tb>>>(W1, W1p);
    wconv_kernel<<<dim3(1024 / 32, 1024 / 32), tb>>>(W2,  W2p,  1024, 1024);
    wconv_kernel<<<dim3(4096 / 32, 1024 / 32), tb>>>(Wf1, Wf1p, 1024, 4096);
    wconv_kernel<<<dim3(1024 / 32, 4096 / 32), tb>>>(Wf2, Wf2p, 4096, 1024);

    const int ew_blocks = (M_TOK * 1024 / 4) / 256;

    // conv block
    ln_h_kernel<<<M_TOK, 256>>>(x, Ap, gcv, bcv);
    gemm_mma<3, 1024><<<dim3(16, 256), 256, GEMM_SMEM>>>(
        Ap, W1p, b1, nullptr, glu, nullptr, M_TOK, 2048);
    alpha_kernel<<<M_TOK / 8, 256, 65536>>>(glu, Woff, boff, alpha);
    cumsum_part<<<dim3(CHAN / 256, 8), 256>>>(glu, part);
    cumsum_scan<<<dim3(CHAN / 256, 8), 256>>>(glu, part, S);
    talk_h_kernel<<<ew_blocks, 256>>>(S, alpha, Ap);
    gemm_mma<2, 1024><<<dim3(8, 256), 256, GEMM_SMEM>>>(
        Ap, W2p, b2, x, y, nullptr, M_TOK, 1024);

    // FFN block
    ln_h_kernel<<<M_TOK, 256>>>(y, Ap, gfn, bfn);
    gemm_mma<1, 1024><<<dim3(32, 256), 256, GEMM_SMEM>>>(
        Ap, Wf1p, bf1, nullptr, nullptr, Mp, M_TOK, 4096);
    gemm_mma<2, 4096><<<dim3(8, 256), 256, GEMM_SMEM>>>(
        Mp, Wf2p, bf2, y, (float*)d_out, nullptr, M_TOK, 1024);
}

// round 10
// speedup vs baseline: 7.9811x; 1.0159x over previous
#include <cuda_runtime.h>
#include <cuda_fp16.h>
#include <stdint.h>
#include <math.h>

#define T_DIM   4096
#define B_DIM   8
#define M_TOK   32768
#define CHAN    8192
#define BH_DIM  128

// ---------------------------------------------------------------------------
// Device-global scratch
// ---------------------------------------------------------------------------
__device__ __half g_A  [M_TOK * 1024];                     // fp16 activations
__device__ __half g_M  [M_TOK * 4096];                     // fp16 FFN mid
__device__ __half g_W1 [2048 * 1024];                      // permuted (a/gate interleaved)
__device__ __half g_W2 [1024 * 1024];
__device__ __half g_Wf1[4096 * 1024];
__device__ __half g_Wf2[1024 * 4096];
__device__ __half g_glu[M_TOK * 1024];                     // fp16 GLU output
__device__ float g_y   [M_TOK * 1024];
__device__ float g_alpha[T_DIM * BH_DIM];
__device__ float g_part[8 * CHAN];

__device__ __forceinline__ float sigmoidf_(float v) { return 1.f / (1.f + __expf(-v)); }

__device__ __forceinline__ uint32_t smem_addr_of(const void* p) {
    uint32_t a;
    asm("{ .reg .u64 t; cvta.to.shared.u64 t, %1; cvt.u32.u64 %0, t; }" : "=r"(a) : "l"(p));
    return a;
}
__device__ __forceinline__ void ldsm4(uint32_t* r, uint32_t addr) {
    asm volatile("ldmatrix.sync.aligned.m8n8.x4.shared.b16 {%0,%1,%2,%3}, [%4];"
                 : "=r"(r[0]), "=r"(r[1]), "=r"(r[2]), "=r"(r[3]) : "r"(addr));
}
__device__ __forceinline__ void mma16816h(float* d, const uint32_t* a, const uint32_t* b) {
    asm volatile("mma.sync.aligned.m16n8k16.row.col.f32.f16.f16.f32 "
                 "{%0,%1,%2,%3}, {%4,%5,%6,%7}, {%8,%9}, {%0,%1,%2,%3};"
                 : "+f"(d[0]), "+f"(d[1]), "+f"(d[2]), "+f"(d[3])
                 : "r"(a[0]), "r"(a[1]), "r"(a[2]), "r"(a[3]), "r"(b[0]), "r"(b[1]));
}
__device__ __forceinline__ void cpa16(uint32_t s, const void* g) {
    asm volatile("cp.async.cg.shared.global [%0], [%1], 16;" :: "r"(s), "l"(g));
}
__device__ __forceinline__ void cpa_commit() {
    asm volatile("cp.async.commit_group;" ::: "memory");
}
__device__ __forceinline__ void cpa_wait1() {
    asm volatile("cp.async.wait_group 1;" ::: "memory");
}

// ---------------------------------------------------------------------------
// fp16 GEMM on mma.sync: C = A_fp16 @ B_fp16^T, fp32 accumulate.
// CTA 128x128, 8 warps (64x32), BK=64 (128B rows, XOR-8 swizzle),
// 3-stage cp.async ring -> 96KB smem -> 2 CTAs/SM. K compile-time.
// EPI: 1 = +bias, swish -> fp16 ; 2 = +bias + residual -> fp32 ;
//      3 = GLU (paired cols a/gate) +bias -> fp16 glu [M, N/2]
// ---------------------------------------------------------------------------
#define TILE_B  16384               // 128 rows * 128B
#define STAGE_B 32768               // A + B tiles
#define GEMM_SMEM (3 * STAGE_B)     // 98304

template<int EPI, int K>
__global__ __launch_bounds__(256, 2) void gemm_mma(
    const __half* __restrict__ A, const __half* __restrict__ B,
    const float* __restrict__ bias, const float* __restrict__ res,
    float* __restrict__ C, __half* __restrict__ Ch,
    int M, int N)
{
    extern __shared__ __align__(1024) char smem[];
    const uint32_t sb = smem_addr_of(smem);
    const int tid = threadIdx.x, wid = tid >> 5, lane = tid & 31;
    const int wm = wid & 1, wn = wid >> 1;
    const int m0 = blockIdx.y << 7, n0 = blockIdx.x << 7;

    const __half* gA = A + (size_t)m0 * K;
    const __half* gB = B + (size_t)n0 * K;

    const int ldr = tid >> 3;
    const int ldc = tid & 7;
    const uint32_t dst = (uint32_t)ldr * 128 + (((uint32_t)ldc ^ (ldr & 7)) << 4);

    auto load_stage = [&](uint32_t sbase, int chunk) {
        const int k0 = chunk << 6;
        const __half* a = gA + (size_t)ldr * K + k0 + (ldc << 3);
        const __half* b = gB + (size_t)ldr * K + k0 + (ldc << 3);
        #pragma unroll
        for (int i = 0; i < 4; i++) {
            cpa16(sbase + dst + i * (32 * 128), a + (size_t)(i * 32) * K);
            cpa16(sbase + TILE_B + dst + i * (32 * 128), b + (size_t)(i * 32) * K);
        }
    };

    float acc[4][4][4];
    #pragma unroll
    for (int a = 0; a < 4; a++)
        #pragma unroll
        for (int b = 0; b < 4; b++)
            #pragma unroll
            for (int k = 0; k < 4; k++) acc[a][b][k] = 0.f;

    constexpr int NC = K >> 6;
    uint32_t st0 = sb, st1 = sb + STAGE_B, st2 = sb + 2 * STAGE_B;
    load_stage(st0, 0); cpa_commit();
    load_stage(st1, 1); cpa_commit();

    const int ar = (wm << 6) + (lane & 15);
    const uint32_t aRow = (uint32_t)ar * 128;
    const int axor = ar & 7;
    const int ahalf = lane >> 4;
    const int br = (wn << 5) + ((lane & 7) | ((lane & 16) >> 1));
    const uint32_t bRow = (uint32_t)br * 128;
    const int bxor = br & 7;
    const int bhalf = (lane >> 3) & 1;

    #pragma unroll 1
    for (int c = 0; c < NC; c++) {
        cpa_wait1();
        __syncthreads();
        if (c + 2 < NC) load_stage(st2, c + 2);
        cpa_commit();

        const uint32_t aH = st0 + aRow;
        const uint32_t bH = st0 + TILE_B + bRow;

        #pragma unroll
        for (int kk = 0; kk < 4; kk++) {
            const uint32_t acol = (uint32_t)((((kk << 1) + ahalf) ^ axor)) << 4;
            const uint32_t bcol = (uint32_t)((((kk << 1) + bhalf) ^ bxor)) << 4;
            uint32_t bh[2][4];
            ldsm4(bh[0], bH + bcol);
            ldsm4(bh[1], bH + (16 * 128) + bcol);
            #pragma unroll
            for (int fm = 0; fm < 4; fm++) {
                uint32_t a_f[4];
                ldsm4(a_f, aH + fm * (16 * 128) + acol);
                #pragma unroll
                for (int fn = 0; fn < 4; fn++)
                    mma16816h(acc[fm][fn], a_f, &bh[fn >> 1][(fn & 1) << 1]);
            }
        }
        const uint32_t t = st0; st0 = st1; st1 = st2; st2 = t;
    }

    // ---- epilogue ----
    const int mB = m0 + (wm << 6) + (lane >> 2);
    const int nB = n0 + (wn << 5) + ((lane & 3) << 1);
    #pragma unroll
    for (int fm = 0; fm < 4; fm++) {
        const int r0 = mB + (fm << 4);
        #pragma unroll
        for (int fn = 0; fn < 4; fn++) {
            const int cc = nB + (fn << 3);
            if (EPI == 3) {
                const int j = cc >> 1;
                const float ba = __ldg(bias + j);
                const float bg = __ldg(bias + 1024 + j);
                const float a0 = acc[fm][fn][0] + ba, gg0 = acc[fm][fn][1] + bg;
                const float a1 = acc[fm][fn][2] + ba, gg1 = acc[fm][fn][3] + bg;
                Ch[(size_t)r0 * (N >> 1) + j]       = __float2half_rn(a0 * sigmoidf_(gg0));
                Ch[(size_t)(r0 + 8) * (N >> 1) + j] = __float2half_rn(a1 * sigmoidf_(gg1));
            } else {
                const float2 bv = __ldg((const float2*)(bias + cc));
                float v0 = acc[fm][fn][0] + bv.x;
                float v1 = acc[fm][fn][1] + bv.y;
                float v2 = acc[fm][fn][2] + bv.x;
                float v3 = acc[fm][fn][3] + bv.y;
                const size_t o0 = (size_t)r0 * N + cc;
                const size_t o1 = (size_t)(r0 + 8) * N + cc;
                if (EPI == 1) {
                    v0 = v0 * sigmoidf_(v0); v1 = v1 * sigmoidf_(v1);
                    v2 = v2 * sigmoidf_(v2); v3 = v3 * sigmoidf_(v3);
                    __half2 p;
                    p.x = __float2half_rn(v0); p.y = __float2half_rn(v1);
                    *(__half2*)(Ch + o0) = p;
                    p.x = __float2half_rn(v2); p.y = __float2half_rn(v3);
                    *(__half2*)(Ch + o1) = p;
                } else {
                    const float2 ra = __ldg((const float2*)(res + o0));
                    const float2 rb = __ldg((const float2*)(res + o1));
                    v0 += ra.x; v1 += ra.y; v2 += rb.x; v3 += rb.y;
                    float2 q;
                    q.x = v0; q.y = v1; *(float2*)(C + o0) = q;
                    q.x = v2; q.y = v3; *(float2*)(C + o1) = q;
                }
            }
        }
    }
}

// ---------------------------------------------------------------------------
// Weight convert + transpose: W[K,N] fp32 -> Wh [N,K] fp16
// ---------------------------------------------------------------------------
__global__ __launch_bounds__(256) void wconv_kernel(
    const float* __restrict__ W, __half* __restrict__ Wh, int K, int N)
{
    __shared__ float tile[32][33];
    const int n0 = blockIdx.x << 5;
    const int k0 = blockIdx.y << 5;
    for (int i = threadIdx.y; i < 32; i += 8)
        tile[i][threadIdx.x] = W[(size_t)(k0 + i) * N + n0 + threadIdx.x];
    __syncthreads();
    for (int i = threadIdx.y; i < 32; i += 8)
        Wh[(size_t)(n0 + i) * K + k0 + threadIdx.x] = __float2half_rn(tile[threadIdx.x][i]);
}

// W1 permuted: out row 2j = src col j (a), out row 2j+1 = src col 1024+j (gate)
__global__ __launch_bounds__(256) void wconv_perm_kernel(
    const float* __restrict__ W, __half* __restrict__ Wh)
{
    __shared__ float tile[32][33];
    const int n0 = blockIdx.x << 5;
    const int k0 = blockIdx.y << 5;
    const int tx = threadIdx.x;
    const int orow = n0 + tx;
    const int scol = (orow & 1) ? (1024 + (orow >> 1)) : (orow >> 1);
    for (int i = threadIdx.y; i < 32; i += 8)
        tile[i][tx] = W[(size_t)(k0 + i) * 2048 + scol];
    __syncthreads();
    for (int i = threadIdx.y; i < 32; i += 8)
        Wh[(size_t)(n0 + i) * 1024 + k0 + tx] = __float2half_rn(tile[tx][i]);
}

// ---------------------------------------------------------------------------
// LayerNorm -> fp16
// ---------------------------------------------------------------------------
__device__ __forceinline__ float block_sum256(float v, float* sh) {
    #pragma unroll
    for (int o = 16; o > 0; o >>= 1) v += __shfl_xor_sync(0xffffffffu, v, o);
    if ((threadIdx.x & 31) == 0) sh[threadIdx.x >> 5] = v;
    __syncthreads();
    float tot = 0.f;
    #pragma unroll
    for (int i = 0; i < 8; i++) tot += sh[i];
    __syncthreads();
    return tot;
}

__global__ __launch_bounds__(256) void ln_h_kernel(
    const float* __restrict__ in, __half* __restrict__ oh,
    const float* __restrict__ gw, const float* __restrict__ bw)
{
    __shared__ float sh[8];
    const size_t row = blockIdx.x;
    const float4 v = ((const float4*)(in + row * 1024))[threadIdx.x];

    float s = v.x + v.y + v.z + v.w;
    s = block_sum256(s, sh);
    const float mean = s * (1.f / 1024.f);
    const float dx = v.x - mean, dy = v.y - mean, dz = v.z - mean, dw = v.w - mean;
    float q = dx * dx + dy * dy + dz * dz + dw * dw;
    q = block_sum256(q, sh);
    const float rstd = rsqrtf(q * (1.f / 1024.f) + 1e-5f);

    const float4 g4 = ((const float4*)gw)[threadIdx.x];
    const float4 b4 = ((const float4*)bw)[threadIdx.x];
    const size_t base = row * 1024 + (size_t)threadIdx.x * 4;
    __half2 p;
    p.x = __float2half_rn(dx * rstd * g4.x + b4.x);
    p.y = __float2half_rn(dy * rstd * g4.y + b4.y);
    *(__half2*)(oh + base) = p;
    p.x = __float2half_rn(dz * rstd * g4.z + b4.z);
    p.y = __float2half_rn(dw * rstd * g4.w + b4.w);
    *(__half2*)(oh + base + 2) = p;
}

// ---------------------------------------------------------------------------
// alpha = sigmoid(glu @ W_off + b_off). Warp per row, W_off transposed in smem.
// glu is fp16.
// ---------------------------------------------------------------------------
__global__ __launch_bounds__(256) void alpha_kernel(
    const __half* __restrict__ g, const float* __restrict__ Woff,
    const float* __restrict__ boff, float* __restrict__ alpha)
{
    extern __shared__ float Ws[];   // [16][1024]
    for (int k = threadIdx.x; k < 1024; k += 256) {
        const float4 w0 = __ldg((const float4*)(Woff + (size_t)k * 16));
        const float4 w1 = __ldg((const float4*)(Woff + (size_t)k * 16 + 4));
        const float4 w2 = __ldg((const float4*)(Woff + (size_t)k * 16 + 8));
        const float4 w3 = __ldg((const float4*)(Woff + (size_t)k * 16 + 12));
        Ws[0 * 1024 + k] = w0.x; Ws[1 * 1024 + k] = w0.y;
        Ws[2 * 1024 + k] = w0.z; Ws[3 * 1024 + k] = w0.w;
        Ws[4 * 1024 + k] = w1.x; Ws[5 * 1024 + k] = w1.y;
        Ws[6 * 1024 + k] = w1.z; Ws[7 * 1024 + k] = w1.w;
        Ws[8 * 1024 + k] = w2.x; Ws[9 * 1024 + k] = w2.y;
        Ws[10 * 1024 + k] = w2.z; Ws[11 * 1024 + k] = w2.w;
        Ws[12 * 1024 + k] = w3.x; Ws[13 * 1024 + k] = w3.y;
        Ws[14 * 1024 + k] = w3.z; Ws[15 * 1024 + k] = w3.w;
    }
    __syncthreads();

    const int wid = threadIdx.x >> 5, lane = threadIdx.x & 31;
    const int row = blockIdx.x * 8 + wid;
    const __half* gr = g + (size_t)row * 1024;

    float acc[16];
    #pragma unroll
    for (int n = 0; n < 16; n++) acc[n] = 0.f;

    #pragma unroll
    for (int j = 0; j < 8; j++) {
        const int k = (lane << 2) + (j << 7);
        const __half2 h0 = *(const __half2*)(gr + k);
        const __half2 h1 = *(const __half2*)(gr + k + 2);
        const float2 f0 = __half22float2(h0);
        const float2 f1 = __half22float2(h1);
        #pragma unroll
        for (int n = 0; n < 16; n++) {
            const float4 w = *(const float4*)(Ws + n * 1024 + k);
            acc[n] += f0.x * w.x + f0.y * w.y + f1.x * w.z + f1.y * w.w;
        }
    }
    #pragma unroll
    for (int o = 16; o > 0; o >>= 1)
        #pragma unroll
        for (int n = 0; n < 16; n++)
            acc[n] += __shfl_xor_sync(0xffffffffu, acc[n], o);

    if (lane < 16) {
        const int t = row >> 3, b = row & 7;
        alpha[(size_t)t * BH_DIM + b * 16 + lane] =
            sigmoidf_(acc[lane] + __ldg(boff + lane));
    }
}

// ---------------------------------------------------------------------------
// Segment partial sums (fp16 input)
// ---------------------------------------------------------------------------
__global__ __launch_bounds__(256) void cumsum_part(
    const __half* __restrict__ in, float* __restrict__ part)
{
    const int c = blockIdx.x * 256 + threadIdx.x;
    const int s = blockIdx.y;
    float acc = 0.f;
    for (int t0 = s * 512; t0 < (s + 1) * 512; t0 += 8) {
        float v[8];
        #pragma unroll
        for (int i = 0; i < 8; i++)
            v[i] = __half2float(in[(size_t)(t0 + i) * CHAN + c]);
        #pragma unroll
        for (int i = 0; i < 8; i++) acc += v[i];
    }
    part[s * CHAN + c] = acc;
}

// ---------------------------------------------------------------------------
// Fused cumsum-scan + TaLK: computes S on the fly into a per-thread smem
// ring (window of 34 needed; ring of 64), emits TaLK output directly as fp16.
// Grid (32, 8), block 256, dynamic smem 64KB (ring[64][256]).
// ---------------------------------------------------------------------------
__global__ __launch_bounds__(256) void scan_talk_kernel(
    const __half* __restrict__ in, const float* __restrict__ part,
    const float* __restrict__ alpha, __half* __restrict__ oh)
{
    extern __shared__ float ring[];   // [64][256]
    const int tidx = threadIdx.x;
    const int c = blockIdx.x * 256 + tidx;
    const int s = blockIdx.y;
    const int bh = c >> 6;
    const float scale = 1.f / 32.f;

    float acc = 0.f;
    for (int p = 0; p < s; p++) acc += part[p * CHAN + c];
    acc *= scale;

    const int tbase = s * 512;
    if (s > 0) {
        // warm-up: recompute previous segment's last 34 S values into the ring
        float w[34];
        #pragma unroll
        for (int i = 0; i < 34; i++)
            w[i] = __half2float(in[(size_t)(tbase - 34 + i) * CHAN + c]);
        float sub = 0.f;
        #pragma unroll
        for (int i = 0; i < 34; i++) sub += w[i];
        acc = fmaf(-sub, scale, acc * 32.f * scale);   // acc*(32*scale)=acc; keep exact: acc - sub*scale
        // note: acc*32*scale == acc exactly (scale = 1/32), so acc = acc - sub*scale
        #pragma unroll
        for (int i = 0; i < 34; i++) {
            acc = fmaf(w[i], scale, acc);
            ring[((tbase - 34 + i) & 63) * 256 + tidx] = acc;
        }
    }

    for (int t0 = tbase; t0 < tbase + 512; t0 += 8) {
        float v[8];
        #pragma unroll
        for (int i = 0; i < 8; i++)
            v[i] = __half2float(in[(size_t)(t0 + i) * CHAN + c]);
        float sreg[8];
        #pragma unroll
        for (int i = 0; i < 8; i++) {
            acc = fmaf(v[i], scale, acc);
            sreg[i] = acc;
            ring[((t0 + i) & 63) * 256 + tidx] = acc;
        }
        float al[8];
        #pragma unroll
        for (int i = 0; i < 8; i++)
            al[i] = __ldg(alpha + (size_t)(t0 + i) * BH_DIM + bh);
        #pragma unroll
        for (int i = 0; i < 8; i++) {
            const int t = t0 + i;
            const float eff = fminf(31.f, (float)t);
            const float pos = (float)t - 1.f - al[i] * eff;
            const float i0f = floorf(pos);
            const float frac = pos - i0f;
            const int i0 = (int)i0f;
            const int c0 = max(i0, 0);
            const int c1 = i0 + 1;
            const float v0 = (i0 < 0) ? 0.f : ring[(c0 & 63) * 256 + tidx];
            const float v1 = ring[(c1 & 63) * 256 + tidx];
            const float out = sreg[i] - (v0 + frac * (v1 - v0));
            oh[(size_t)t * CHAN + c] = __float2half_rn(out);
        }
    }
}

// ---------------------------------------------------------------------------
// Launch
// ---------------------------------------------------------------------------
extern "C" void kernel_launch(void* const* d_in, const int* in_sizes, int n_in,
                              void* d_out, int out_size)
{
    const float* x    = (const float*)d_in[0];
    const float* W1   = (const float*)d_in[4];
    const float* b1   = (const float*)d_in[5];
    const float* Woff = (const float*)d_in[6];
    const float* boff = (const float*)d_in[7];
    const float* W2   = (const float*)d_in[8];
    const float* b2   = (const float*)d_in[9];
    const float* Wf1  = (const float*)d_in[10];
    const float* bf1  = (const float*)d_in[11];
    const float* Wf2  = (const float*)d_in[12];
    const float* bf2  = (const float*)d_in[13];
    const float* gcv  = (const float*)d_in[14];
    const float* bcv  = (const float*)d_in[15];
    const float* gfn  = (const float*)d_in[16];
    const float* bfn  = (const float*)d_in[17];

    __half *Ap, *Mp, *W1p, *W2p, *Wf1p, *Wf2p, *glu;
    float *y, *alpha, *part;
    cudaGetSymbolAddress((void**)&Ap, g_A);
    cudaGetSymbolAddress((void**)&Mp, g_M);
    cudaGetSymbolAddress((void**)&W1p, g_W1);
    cudaGetSymbolAddress((void**)&W2p, g_W2);
    cudaGetSymbolAddress((void**)&Wf1p, g_Wf1);
    cudaGetSymbolAddress((void**)&Wf2p, g_Wf2);
    cudaGetSymbolAddress((void**)&glu, g_glu);
    cudaGetSymbolAddress((void**)&y, g_y);
    cudaGetSymbolAddress((void**)&alpha, g_alpha);
    cudaGetSymbolAddress((void**)&part, g_part);

    cudaFuncSetAttribute((const void*)gemm_mma<1, 1024>, cudaFuncAttributeMaxDynamicSharedMemorySize, GEMM_SMEM);
    cudaFuncSetAttribute((const void*)gemm_mma<2, 1024>, cudaFuncAttributeMaxDynamicSharedMemorySize, GEMM_SMEM);
    cudaFuncSetAttribute((const void*)gemm_mma<3, 1024>, cudaFuncAttributeMaxDynamicSharedMemorySize, GEMM_SMEM);
    cudaFuncSetAttribute((const void*)gemm_mma<2, 4096>, cudaFuncAttributeMaxDynamicSharedMemorySize, GEMM_SMEM);
    cudaFuncSetAttribute(alpha_kernel, cudaFuncAttributeMaxDynamicSharedMemorySize, 65536);
    cudaFuncSetAttribute(scan_talk_kernel, cudaFuncAttributeMaxDynamicSharedMemorySize, 65536);

    const dim3 tb(32, 8);
    wconv_perm_kernel<<<dim3(2048 / 32, 1024 / 32), tb>>>(W1, W1p);
    wconv_kernel<<<dim3(1024 / 32, 1024 / 32), tb>>>(W2,  W2p,  1024, 1024);
    wconv_kernel<<<dim3(4096 / 32, 1024 / 32), tb>>>(Wf1, Wf1p, 1024, 4096);
    wconv_kernel<<<dim3(1024 / 32, 4096 / 32), tb>>>(Wf2, Wf2p, 4096, 1024);

    // conv block
    ln_h_kernel<<<M_TOK, 256>>>(x, Ap, gcv, bcv);
    gemm_mma<3, 1024><<<dim3(16, 256), 256, GEMM_SMEM>>>(
        Ap, W1p, b1, nullptr, nullptr, glu, M_TOK, 2048);
    alpha_kernel<<<M_TOK / 8, 256, 65536>>>(glu, Woff, boff, alpha);
    cumsum_part<<<dim3(CHAN / 256, 8), 256>>>(glu, part);
    scan_talk_kernel<<<dim3(CHAN / 256, 8), 256, 65536>>>(glu, part, alpha, Ap);
    gemm_mma<2, 1024><<<dim3(8, 256), 256, GEMM_SMEM>>>(
        Ap, W2p, b2, x, y, nullptr, M_TOK, 1024);

    // FFN block
    ln_h_kernel<<<M_TOK, 256>>>(y, Ap, gfn, bfn);
    gemm_mma<1, 1024><<<dim3(32, 256), 256, GEMM_SMEM>>>(
        Ap, Wf1p, bf1, nullptr, nullptr, Mp, M_TOK, 4096);
    gemm_mma<2, 4096><<<dim3(8, 256), 256, GEMM_SMEM>>>(
        Mp, Wf2p, bf2, y, (float*)d_out, nullptr, M_TOK, 1024);
}